// round 1
// baseline (speedup 1.0000x reference)
#include <cuda_runtime.h>
#include <math.h>

#define BB 4
#define TT 2048
#define HH 8
#define DD 64
#define FF 512
#define MM (BB*TT)   // 8192

// Scratch (device globals: no allocation allowed)
__device__ float g_q[(size_t)BB*HH*TT*128];  // q_cat: [b,h,t, 0:64]=q+bias_u, [64:128]=q+bias_v
__device__ float g_k[(size_t)BB*HH*TT*64];   // [b,h,t,d]
__device__ float g_p[(size_t)HH*TT*64];      // [h,t,d]
__device__ float g_v[(size_t)BB*HH*TT*64];   // [b,h,t,d]
__device__ float g_ao[(size_t)MM*FF];        // attention out, (b,t, h*64+c) row-major

__device__ __forceinline__ void fma16(float acc[4][4], float4 a, float4 b) {
    acc[0][0] += a.x*b.x; acc[0][1] += a.x*b.y; acc[0][2] += a.x*b.z; acc[0][3] += a.x*b.w;
    acc[1][0] += a.y*b.x; acc[1][1] += a.y*b.y; acc[1][2] += a.y*b.z; acc[1][3] += a.y*b.w;
    acc[2][0] += a.z*b.x; acc[2][1] += a.z*b.y; acc[2][2] += a.z*b.z; acc[2][3] += a.z*b.w;
    acc[3][0] += a.w*b.x; acc[3][1] += a.w*b.y; acc[3][2] += a.w*b.z; acc[3][3] += a.w*b.w;
}

__device__ __forceinline__ float redmax16(float v) {
    v = fmaxf(v, __shfl_xor_sync(0xffffffffu, v, 1, 16));
    v = fmaxf(v, __shfl_xor_sync(0xffffffffu, v, 2, 16));
    v = fmaxf(v, __shfl_xor_sync(0xffffffffu, v, 4, 16));
    v = fmaxf(v, __shfl_xor_sync(0xffffffffu, v, 8, 16));
    return v;
}
__device__ __forceinline__ float redsum16(float v) {
    v += __shfl_xor_sync(0xffffffffu, v, 1, 16);
    v += __shfl_xor_sync(0xffffffffu, v, 2, 16);
    v += __shfl_xor_sync(0xffffffffu, v, 4, 16);
    v += __shfl_xor_sync(0xffffffffu, v, 8, 16);
    return v;
}

// ---------------------------------------------------------------------------
// NT SGEMM: C[m,n] = sum_k A[m,k]*W[n,k] (+ bias[n]); epilogue scatter by mode.
// mode 0: Q  -> g_q (both halves, + pos_bias_u / pos_bias_v)
// mode 1: K  -> g_k     mode 2: V -> g_v     mode 3: P -> g_p (M=2048, no bias)
// mode 4: OUT: A taken from g_ao, write C = d_out
// ---------------------------------------------------------------------------
__global__ __launch_bounds__(256) void gemm_kernel(
    const float* __restrict__ A, const float* __restrict__ W,
    const float* __restrict__ bias, int mode,
    const float* __restrict__ pbu, const float* __restrict__ pbv,
    float* __restrict__ C)
{
    __shared__ float As[16][64];
    __shared__ float Ws[16][64];
    int tid = threadIdx.x;
    int ty = tid >> 4, tx = tid & 15;
    int m0 = blockIdx.y << 6, n0 = blockIdx.x << 6;
    int lr = tid >> 2, lc = (tid & 3) << 2;

    const float* Abase = (mode == 4) ? g_ao : A;
    const float* Ap = Abase + (size_t)(m0 + lr) * FF + lc;
    const float* Wp = W     + (size_t)(n0 + lr) * FF + lc;

    float acc[4][4] = {};

    for (int k0 = 0; k0 < FF; k0 += 16) {
        float4 av = *(const float4*)(Ap + k0);
        float4 wv = *(const float4*)(Wp + k0);
        __syncthreads();
        As[lc+0][lr] = av.x; As[lc+1][lr] = av.y; As[lc+2][lr] = av.z; As[lc+3][lr] = av.w;
        Ws[lc+0][lr] = wv.x; Ws[lc+1][lr] = wv.y; Ws[lc+2][lr] = wv.z; Ws[lc+3][lr] = wv.w;
        __syncthreads();
#pragma unroll
        for (int k = 0; k < 16; k++) {
            float4 a = *(const float4*)&As[k][ty << 2];
            float4 b = *(const float4*)&Ws[k][tx << 2];
            fma16(acc, a, b);
        }
    }

#pragma unroll
    for (int i = 0; i < 4; i++) {
        int m = m0 + (ty << 2) + i;
#pragma unroll
        for (int j = 0; j < 4; j++) {
            int n = n0 + (tx << 2) + j;
            float v = acc[i][j];
            if (bias) v += bias[n];
            int h = n >> 6, dd = n & 63;
            if (mode == 0) {
                int b = m >> 11, t = m & (TT - 1);
                size_t base = ((size_t)(b * HH + h) * TT + t) * 128;
                g_q[base + dd]      = v + pbu[n];
                g_q[base + 64 + dd] = v + pbv[n];
            } else if (mode == 1) {
                int b = m >> 11, t = m & (TT - 1);
                g_k[((size_t)(b * HH + h) * TT + t) * 64 + dd] = v;
            } else if (mode == 2) {
                int b = m >> 11, t = m & (TT - 1);
                g_v[((size_t)(b * HH + h) * TT + t) * 64 + dd] = v;
            } else if (mode == 3) {
                g_p[((size_t)h * TT + m) * 64 + dd] = v;
            } else {
                C[(size_t)m * FF + n] = v;
            }
        }
    }
}

// ---------------------------------------------------------------------------
// Flash attention: d_qk = 128 (concat trick), d_v = 64, full softmax over T.
// Grid: (T/64, B*H). Block 256. Per-thread 4x4 microtiles (16x16 thread grid).
// Qt/Kt: transposed [k][i] smem with XOR swizzle (col4 = ib ^ ((k>>2)&15)).
// ---------------------------------------------------------------------------
#define FLASH_SMEM ((2*128*64 + 2*64*68) * 4)

__global__ __launch_bounds__(256) void flash_kernel()
{
    extern __shared__ float sm[];
    float* Qt = sm;                   // [128][64] swizzled
    float* Kt = sm + 128 * 64;        // [128][64] swizzled
    float* Vs = sm + 2 * 128 * 64;    // [64][68]
    float* Pt = Vs + 64 * 68;         // [64][68]  (Pt[j][i])

    int tid = threadIdx.x;
    int ty = tid >> 4, tx = tid & 15;
    int bh = blockIdx.y;
    int b = bh >> 3, h = bh & 7;
    int t0 = blockIdx.x << 6;

    // Load Q tile (64 rows x 128 k), transposed + swizzled
    for (int idx = tid; idx < 2048; idx += 256) {
        int r  = idx >> 5;        // 0..63
        int c4 = idx & 31;        // float4 index over k
        float4 v = *(const float4*)&g_q[((size_t)bh * TT + t0 + r) * 128 + (c4 << 2)];
        int col = (((r >> 2) ^ (c4 & 15)) << 2) + (r & 3);
        int kb = c4 << 2;
        Qt[(kb + 0) * 64 + col] = v.x;
        Qt[(kb + 1) * 64 + col] = v.y;
        Qt[(kb + 2) * 64 + col] = v.z;
        Qt[(kb + 3) * 64 + col] = v.w;
    }

    float m_i[4], l_i[4], acc[4][4];
#pragma unroll
    for (int i = 0; i < 4; i++) {
        m_i[i] = -1e30f; l_i[i] = 0.f;
#pragma unroll
        for (int j = 0; j < 4; j++) acc[i][j] = 0.f;
    }

    for (int s0 = 0; s0 < TT; s0 += 64) {
        // K/P tile -> Kt (transposed + swizzled): k[0:64] from g_k, k[64:128] from g_p
        for (int idx = tid; idx < 2048; idx += 256) {
            int r  = idx >> 5;
            int c4 = idx & 31;
            float4 v;
            if (c4 < 16)
                v = *(const float4*)&g_k[((size_t)bh * TT + s0 + r) * 64 + (c4 << 2)];
            else
                v = *(const float4*)&g_p[((size_t)h * TT + s0 + r) * 64 + ((c4 - 16) << 2)];
            int col = (((r >> 2) ^ (c4 & 15)) << 2) + (r & 3);
            int kb = c4 << 2;
            Kt[(kb + 0) * 64 + col] = v.x;
            Kt[(kb + 1) * 64 + col] = v.y;
            Kt[(kb + 2) * 64 + col] = v.z;
            Kt[(kb + 3) * 64 + col] = v.w;
        }
        // V tile -> Vs[64][68] row-major
        for (int idx = tid; idx < 1024; idx += 256) {
            int r = idx >> 4, c4 = idx & 15;
            float4 v = *(const float4*)&g_v[((size_t)bh * TT + s0 + r) * 64 + (c4 << 2)];
            *(float4*)&Vs[r * 68 + (c4 << 2)] = v;
        }
        __syncthreads();

        // S = Q @ K^T over 128 dims
        float s[4][4] = {};
#pragma unroll 8
        for (int k = 0; k < 128; k++) {
            int sw = (k >> 2) & 15;
            float4 a  = *(const float4*)&Qt[k * 64 + ((ty ^ sw) << 2)];
            float4 bb = *(const float4*)&Kt[k * 64 + ((tx ^ sw) << 2)];
            fma16(s, a, bb);
        }

        // online softmax (scale 1/sqrt(64) = 0.125)
#pragma unroll
        for (int i = 0; i < 4; i++) {
            float rmax = -1e30f;
#pragma unroll
            for (int j = 0; j < 4; j++) { s[i][j] *= 0.125f; rmax = fmaxf(rmax, s[i][j]); }
            rmax = redmax16(rmax);
            float mnew = fmaxf(m_i[i], rmax);
            float corr = __expf(m_i[i] - mnew);
            m_i[i] = mnew;
            float rsum = 0.f;
#pragma unroll
            for (int j = 0; j < 4; j++) { s[i][j] = __expf(s[i][j] - mnew); rsum += s[i][j]; }
            rsum = redsum16(rsum);
            l_i[i] = l_i[i] * corr + rsum;
#pragma unroll
            for (int j = 0; j < 4; j++) acc[i][j] *= corr;
        }

        // Stage P transposed: Pt[j][i]
#pragma unroll
        for (int j = 0; j < 4; j++) {
            float4 p = make_float4(s[0][j], s[1][j], s[2][j], s[3][j]);
            *(float4*)&Pt[((tx << 2) + j) * 68 + (ty << 2)] = p;
        }
        __syncthreads();

        // acc += P @ V
#pragma unroll 8
        for (int j = 0; j < 64; j++) {
            float4 p  = *(const float4*)&Pt[j * 68 + (ty << 2)];
            float4 vv = *(const float4*)&Vs[j * 68 + (tx << 2)];
            fma16(acc, p, vv);
        }
        __syncthreads();
    }

    // epilogue: normalize and write (b, t, h*64 + c)
#pragma unroll
    for (int i = 0; i < 4; i++) {
        float inv = 1.f / l_i[i];
        int t = t0 + (ty << 2) + i;
#pragma unroll
        for (int j = 0; j < 4; j++) {
            int c = (tx << 2) + j;
            g_ao[((size_t)(b * TT + t)) * FF + (h << 6) + c] = acc[i][j] * inv;
        }
    }
}

extern "C" void kernel_launch(void* const* d_in, const int* in_sizes, int n_in,
                              void* d_out, int out_size)
{
    const float* x    = (const float*)d_in[0];
    const float* pe   = (const float*)d_in[1];
    const float* Wq   = (const float*)d_in[2];
    const float* bq   = (const float*)d_in[3];
    const float* Wk   = (const float*)d_in[4];
    const float* bk   = (const float*)d_in[5];
    const float* Wv   = (const float*)d_in[6];
    const float* bv   = (const float*)d_in[7];
    const float* Wpos = (const float*)d_in[8];
    const float* Wout = (const float*)d_in[9];
    const float* bout = (const float*)d_in[10];
    const float* pbu  = (const float*)d_in[11];
    const float* pbv  = (const float*)d_in[12];
    float* out = (float*)d_out;

    cudaFuncSetAttribute(flash_kernel, cudaFuncAttributeMaxDynamicSharedMemorySize, FLASH_SMEM);

    dim3 blk(256);
    // Projections (M=8192 rows, N=512): grid (N/64=8, M/64=128)
    gemm_kernel<<<dim3(8, 128), blk>>>(x,  Wq, bq, 0, pbu, pbv, nullptr);
    gemm_kernel<<<dim3(8, 128), blk>>>(x,  Wk, bk, 1, nullptr, nullptr, nullptr);
    gemm_kernel<<<dim3(8, 128), blk>>>(x,  Wv, bv, 2, nullptr, nullptr, nullptr);
    // Positional projection (M=2048)
    gemm_kernel<<<dim3(8, 32),  blk>>>(pe, Wpos, nullptr, 3, nullptr, nullptr, nullptr);
    // Attention
    flash_kernel<<<dim3(TT / 64, BB * HH), blk, FLASH_SMEM>>>();
    // Output projection -> d_out
    gemm_kernel<<<dim3(8, 128), blk>>>(nullptr, Wout, bout, 4, nullptr, nullptr, out);
}

// round 3
// speedup vs baseline: 1.8262x; 1.8262x over previous
#include <cuda_runtime.h>
#include <cuda_bf16.h>
#include <cstdint>

#define BB 4
#define TT 2048
#define HH 8
#define FF 512
#define MM (BB*TT)   // 8192

// ---------------------------------------------------------------------------
// Global scratch (device globals; uint4 for 16B alignment)
// ---------------------------------------------------------------------------
__device__ uint4 g_qh_[1048576];   // q_cat hi: [bh=32][t=2048][128] bf16 (scaled 0.125, biases fused)
__device__ uint4 g_ql_[1048576];   // q_cat lo
__device__ uint4 g_kh_[1048576];   // k_cat hi: [bh][t][0:64]=k, [64:128]=p
__device__ uint4 g_kl_[1048576];
__device__ uint4 g_vh_[524288];    // V hi: [bh][t][64] bf16
__device__ uint4 g_vl_[524288];
__device__ float g_ao[(size_t)MM*FF];

#define G_QH ((__nv_bfloat16*)g_qh_)
#define G_QL ((__nv_bfloat16*)g_ql_)
#define G_KH ((__nv_bfloat16*)g_kh_)
#define G_KL ((__nv_bfloat16*)g_kl_)
#define G_VH ((__nv_bfloat16*)g_vh_)
#define G_VL ((__nv_bfloat16*)g_vl_)

// ---------------------------------------------------------------------------
__device__ __forceinline__ uint32_t cvta_s(const void* p) {
    return (uint32_t)__cvta_generic_to_shared(p);
}
__device__ __forceinline__ float ex2f(float x) {
    float r; asm("ex2.approx.ftz.f32 %0, %1;" : "=f"(r) : "f"(x)); return r;
}
// pack two f32 -> bf16x2 word: first arg -> low half, second -> high half
__device__ __forceinline__ uint32_t pack2(float lo, float hi) {
    uint32_t r; asm("cvt.rn.bf16x2.f32 %0, %1, %2;" : "=r"(r) : "f"(hi), "f"(lo)); return r;
}

__device__ __forceinline__ void ldsm4(uint32_t r[4], uint32_t a) {
    asm volatile("ldmatrix.sync.aligned.m8n8.x4.shared.b16 {%0,%1,%2,%3}, [%4];"
                 : "=r"(r[0]), "=r"(r[1]), "=r"(r[2]), "=r"(r[3]) : "r"(a));
}
__device__ __forceinline__ void ldsm4t(uint32_t r[4], uint32_t a) {
    asm volatile("ldmatrix.sync.aligned.m8n8.x4.trans.shared.b16 {%0,%1,%2,%3}, [%4];"
                 : "=r"(r[0]), "=r"(r[1]), "=r"(r[2]), "=r"(r[3]) : "r"(a));
}
__device__ __forceinline__ void mma16(float c[4], const uint32_t a[4], uint32_t b0, uint32_t b1) {
    asm volatile("mma.sync.aligned.m16n8k16.row.col.f32.bf16.bf16.f32 "
                 "{%0,%1,%2,%3}, {%4,%5,%6,%7}, {%8,%9}, {%0,%1,%2,%3};"
                 : "+f"(c[0]), "+f"(c[1]), "+f"(c[2]), "+f"(c[3])
                 : "r"(a[0]), "r"(a[1]), "r"(a[2]), "r"(a[3]), "r"(b0), "r"(b1));
}

// ---------------------------------------------------------------------------
// SIMT projection GEMM (C[m,n] = sum_k A[m,k]*W[n,k] + bias[n]) with
// mode-specific bf16 hi/lo scatter epilogues.
// mode 0: Q -> g_q{h,l} (both halves, +pos_bias_u/v, *0.125)
// mode 1: K -> g_k{h,l}[.. 0:64]
// mode 2: V -> g_v{h,l} ([bh][t][64] row-major)
// mode 3: P -> g_k{h,l}[.. 64:128] for all 4 batches (M=2048, no bias)
// mode 4: OUT: A = g_ao, C = d_out (fp32)
// ---------------------------------------------------------------------------
__device__ __forceinline__ void fma16(float acc[4][4], float4 a, float4 b) {
    acc[0][0] += a.x*b.x; acc[0][1] += a.x*b.y; acc[0][2] += a.x*b.z; acc[0][3] += a.x*b.w;
    acc[1][0] += a.y*b.x; acc[1][1] += a.y*b.y; acc[1][2] += a.y*b.z; acc[1][3] += a.y*b.w;
    acc[2][0] += a.z*b.x; acc[2][1] += a.z*b.y; acc[2][2] += a.z*b.z; acc[2][3] += a.z*b.w;
    acc[3][0] += a.w*b.x; acc[3][1] += a.w*b.y; acc[3][2] += a.w*b.z; acc[3][3] += a.w*b.w;
}

__device__ __forceinline__ void split4(const float v[4], uint2& hi, uint2& lo) {
    uint32_t h0 = pack2(v[0], v[1]);
    uint32_t h1 = pack2(v[2], v[3]);
    float r0 = v[0] - __uint_as_float(h0 << 16);
    float r1 = v[1] - __uint_as_float(h0 & 0xffff0000u);
    float r2 = v[2] - __uint_as_float(h1 << 16);
    float r3 = v[3] - __uint_as_float(h1 & 0xffff0000u);
    hi = make_uint2(h0, h1);
    lo = make_uint2(pack2(r0, r1), pack2(r2, r3));
}

__global__ __launch_bounds__(256) void gemm_kernel(
    const float* __restrict__ A, const float* __restrict__ W,
    const float* __restrict__ bias, int mode,
    const float* __restrict__ pbu, const float* __restrict__ pbv,
    float* __restrict__ C)
{
    __shared__ float As[16][64];
    __shared__ float Ws[16][64];
    int tid = threadIdx.x;
    int ty = tid >> 4, tx = tid & 15;
    int m0 = blockIdx.y << 6, n0 = blockIdx.x << 6;
    int lr = tid >> 2, lc = (tid & 3) << 2;

    const float* Abase = (mode == 4) ? g_ao : A;
    const float* Ap = Abase + (size_t)(m0 + lr) * FF + lc;
    const float* Wp = W     + (size_t)(n0 + lr) * FF + lc;

    float acc[4][4] = {};

    for (int k0 = 0; k0 < FF; k0 += 16) {
        float4 av = *(const float4*)(Ap + k0);
        float4 wv = *(const float4*)(Wp + k0);
        __syncthreads();
        As[lc+0][lr] = av.x; As[lc+1][lr] = av.y; As[lc+2][lr] = av.z; As[lc+3][lr] = av.w;
        Ws[lc+0][lr] = wv.x; Ws[lc+1][lr] = wv.y; Ws[lc+2][lr] = wv.z; Ws[lc+3][lr] = wv.w;
        __syncthreads();
#pragma unroll
        for (int k = 0; k < 16; k++) {
            float4 a = *(const float4*)&As[k][ty << 2];
            float4 b = *(const float4*)&Ws[k][tx << 2];
            fma16(acc, a, b);
        }
    }

    int ncol = n0 + (tx << 2);
    int h = ncol >> 6, dd = ncol & 63;

    if (mode == 0) {
#pragma unroll
        for (int i = 0; i < 4; i++) {
            int m = m0 + (ty << 2) + i;
            int b = m >> 11, t = m & (TT - 1);
            float vu[4], vv[4];
#pragma unroll
            for (int j = 0; j < 4; j++) {
                float v = acc[i][j] + bias[ncol + j];
                vu[j] = (v + pbu[ncol + j]) * 0.125f;
                vv[j] = (v + pbv[ncol + j]) * 0.125f;
            }
            size_t base = ((size_t)(b * HH + h) * TT + t) * 128 + dd;
            uint2 hi, lo;
            split4(vu, hi, lo);
            *(uint2*)(G_QH + base) = hi; *(uint2*)(G_QL + base) = lo;
            split4(vv, hi, lo);
            *(uint2*)(G_QH + base + 64) = hi; *(uint2*)(G_QL + base + 64) = lo;
        }
    } else if (mode == 1) {
#pragma unroll
        for (int i = 0; i < 4; i++) {
            int m = m0 + (ty << 2) + i;
            int b = m >> 11, t = m & (TT - 1);
            float vk[4];
#pragma unroll
            for (int j = 0; j < 4; j++) vk[j] = acc[i][j] + bias[ncol + j];
            size_t base = ((size_t)(b * HH + h) * TT + t) * 128 + dd;
            uint2 hi, lo;
            split4(vk, hi, lo);
            *(uint2*)(G_KH + base) = hi; *(uint2*)(G_KL + base) = lo;
        }
    } else if (mode == 2) {
#pragma unroll
        for (int i = 0; i < 4; i++) {
            int m = m0 + (ty << 2) + i;
            int b = m >> 11, t = m & (TT - 1);
            float vk[4];
#pragma unroll
            for (int j = 0; j < 4; j++) vk[j] = acc[i][j] + bias[ncol + j];
            size_t base = ((size_t)(b * HH + h) * TT + t) * 64 + dd;
            uint2 hi, lo;
            split4(vk, hi, lo);
            *(uint2*)(G_VH + base) = hi; *(uint2*)(G_VL + base) = lo;
        }
    } else if (mode == 3) {
#pragma unroll
        for (int i = 0; i < 4; i++) {
            int t = m0 + (ty << 2) + i;   // m is t (0..2047)
            float vp[4];
#pragma unroll
            for (int j = 0; j < 4; j++) vp[j] = acc[i][j];
            uint2 hi, lo;
            split4(vp, hi, lo);
#pragma unroll
            for (int bb = 0; bb < BB; bb++) {
                size_t base = ((size_t)(bb * HH + h) * TT + t) * 128 + 64 + dd;
                *(uint2*)(G_KH + base) = hi; *(uint2*)(G_KL + base) = lo;
            }
        }
    } else {
#pragma unroll
        for (int i = 0; i < 4; i++) {
            int m = m0 + (ty << 2) + i;
#pragma unroll
            for (int j = 0; j < 4; j++) {
                int n = ncol + j;
                C[(size_t)m * FF + n] = acc[i][j] + bias[n];
            }
        }
    }
}

// ---------------------------------------------------------------------------
// mma.sync flash attention.
// CTA = 128 q-rows of one (b,h), 8 warps x 16 rows. d_qk=128 (concat), d_v=64.
// Static-shift softmax p = e^(s-30); O accumulated in fp32 regs across tiles.
// ---------------------------------------------------------------------------
#define KSTR 272     // K/Q smem row stride bytes (128 bf16 + 16B pad)
#define VSTR 144     // V smem row stride bytes (64 bf16 + 16B pad)
#define SM_KH 0
#define SM_KL 34816
#define SM_VH 69632
#define SM_VL 88064
#define FLASH_SMEM 106496

#define LOG2E_F 1.4426950408889634f
#define EXPBIAS_F 43.280851226668914f   /* 30*log2(e) */

__global__ __launch_bounds__(256) void flash_kernel()
{
    extern __shared__ char sm[];
    uint32_t sb = cvta_s(sm);

    int tid = threadIdx.x;
    int w = tid >> 5, l = tid & 31;
    int bh = blockIdx.y;
    int b = bh >> 3, h = bh & 7;
    int t0 = blockIdx.x << 7;

    // ---- load Q tile (128 x 128 bf16, hi+lo) into K buffers, frag to regs ----
    {
        const uint4* qh = g_qh_ + ((size_t)bh * TT + t0) * 16;
        const uint4* ql = g_ql_ + ((size_t)bh * TT + t0) * 16;
        for (int i = tid; i < 2048; i += 256) {
            int r = i >> 4, c = i & 15;
            *(uint4*)(sm + SM_KH + r * KSTR + c * 16) = qh[r * 16 + c];
            *(uint4*)(sm + SM_KL + r * KSTR + c * 16) = ql[r * 16 + c];
        }
    }
    __syncthreads();

    uint32_t Qh[8][4], Ql[8][4];
    {
        uint32_t rowa = sb + (16 * w + (l & 15)) * KSTR + (l >> 4) * 16;
#pragma unroll
        for (int ks = 0; ks < 8; ks++) {
            ldsm4(Qh[ks], rowa + SM_KH + ks * 32);
            ldsm4(Ql[ks], rowa + SM_KL + ks * 32);
        }
    }
    __syncthreads();

    float O[8][4];
#pragma unroll
    for (int i = 0; i < 8; i++)
#pragma unroll
        for (int j = 0; j < 4; j++) O[i][j] = 0.f;
    float lsum0 = 0.f, lsum1 = 0.f;

    // precomputed ldmatrix lane address components
    uint32_t kB_lane = sb + (l & 7) * KSTR + (l >> 3) * 16;                       // QK B frags
    uint32_t vB_lane = sb + ((l & 7) + ((l >> 3) & 1) * 8) * VSTR + (l >> 4) * 16; // V frags

    for (int it = 0; it < 16; ++it) {
        int s0 = it << 7;
        // ---- copy K (128x128, hi/lo) and V (128x64, hi/lo) tiles ----
        {
            const uint4* kh = g_kh_ + ((size_t)bh * TT + s0) * 16;
            const uint4* kl = g_kl_ + ((size_t)bh * TT + s0) * 16;
            for (int i = tid; i < 2048; i += 256) {
                int r = i >> 4, c = i & 15;
                *(uint4*)(sm + SM_KH + r * KSTR + c * 16) = kh[r * 16 + c];
                *(uint4*)(sm + SM_KL + r * KSTR + c * 16) = kl[r * 16 + c];
            }
            const uint4* vh = g_vh_ + ((size_t)bh * TT + s0) * 8;
            const uint4* vl = g_vl_ + ((size_t)bh * TT + s0) * 8;
            for (int i = tid; i < 1024; i += 256) {
                int r = i >> 3, c = i & 7;
                *(uint4*)(sm + SM_VH + r * VSTR + c * 16) = vh[r * 8 + c];
                *(uint4*)(sm + SM_VL + r * VSTR + c * 16) = vl[r * 8 + c];
            }
        }
        __syncthreads();

#pragma unroll
        for (int kb = 0; kb < 8; kb++) {
            // ---- S for 16 keys (n-tiles 2kb, 2kb+1) over full d_qk=128 ----
            float S0[4] = {0.f, 0.f, 0.f, 0.f};
            float S1[4] = {0.f, 0.f, 0.f, 0.f};
            uint32_t r0a = kB_lane + (16 * kb) * KSTR;
            uint32_t r1a = kB_lane + (16 * kb + 8) * KSTR;
#pragma unroll
            for (int j = 0; j < 4; j++) {
                uint32_t Bh[4], Bl[4];
                ldsm4(Bh, r0a + SM_KH + j * 64);
                ldsm4(Bl, r0a + SM_KL + j * 64);
                mma16(S0, Qh[2*j],   Bh[0], Bh[1]);
                mma16(S0, Qh[2*j],   Bl[0], Bl[1]);
                mma16(S0, Ql[2*j],   Bh[0], Bh[1]);
                mma16(S0, Qh[2*j+1], Bh[2], Bh[3]);
                mma16(S0, Qh[2*j+1], Bl[2], Bl[3]);
                mma16(S0, Ql[2*j+1], Bh[2], Bh[3]);
                ldsm4(Bh, r1a + SM_KH + j * 64);
                ldsm4(Bl, r1a + SM_KL + j * 64);
                mma16(S1, Qh[2*j],   Bh[0], Bh[1]);
                mma16(S1, Qh[2*j],   Bl[0], Bl[1]);
                mma16(S1, Ql[2*j],   Bh[0], Bh[1]);
                mma16(S1, Qh[2*j+1], Bh[2], Bh[3]);
                mma16(S1, Qh[2*j+1], Bl[2], Bl[3]);
                mma16(S1, Ql[2*j+1], Bh[2], Bh[3]);
            }

            // ---- softmax terms + P fragments (bf16 hi/lo) ----
            float p00 = ex2f(fmaf(S0[0], LOG2E_F, -EXPBIAS_F));
            float p01 = ex2f(fmaf(S0[1], LOG2E_F, -EXPBIAS_F));
            float p02 = ex2f(fmaf(S0[2], LOG2E_F, -EXPBIAS_F));
            float p03 = ex2f(fmaf(S0[3], LOG2E_F, -EXPBIAS_F));
            float p10 = ex2f(fmaf(S1[0], LOG2E_F, -EXPBIAS_F));
            float p11 = ex2f(fmaf(S1[1], LOG2E_F, -EXPBIAS_F));
            float p12 = ex2f(fmaf(S1[2], LOG2E_F, -EXPBIAS_F));
            float p13 = ex2f(fmaf(S1[3], LOG2E_F, -EXPBIAS_F));
            lsum0 += (p00 + p01) + (p10 + p11);
            lsum1 += (p02 + p03) + (p12 + p13);

            uint32_t Ph[4], Pl[4];
            Ph[0] = pack2(p00, p01);
            Ph[1] = pack2(p02, p03);
            Ph[2] = pack2(p10, p11);
            Ph[3] = pack2(p12, p13);
            Pl[0] = pack2(p00 - __uint_as_float(Ph[0] << 16), p01 - __uint_as_float(Ph[0] & 0xffff0000u));
            Pl[1] = pack2(p02 - __uint_as_float(Ph[1] << 16), p03 - __uint_as_float(Ph[1] & 0xffff0000u));
            Pl[2] = pack2(p10 - __uint_as_float(Ph[2] << 16), p11 - __uint_as_float(Ph[2] & 0xffff0000u));
            Pl[3] = pack2(p12 - __uint_as_float(Ph[3] << 16), p13 - __uint_as_float(Ph[3] & 0xffff0000u));

            // ---- O += P @ V for this 16-key block ----
            uint32_t va = vB_lane + (16 * kb) * VSTR;
#pragma unroll
            for (int nd = 0; nd < 4; nd++) {
                uint32_t Vh[4], Vl[4];
                ldsm4t(Vh, va + SM_VH + nd * 32);
                ldsm4t(Vl, va + SM_VL + nd * 32);
                mma16(O[2*nd],   Ph, Vh[0], Vh[1]);
                mma16(O[2*nd],   Ph, Vl[0], Vl[1]);
                mma16(O[2*nd],   Pl, Vh[0], Vh[1]);
                mma16(O[2*nd+1], Ph, Vh[2], Vh[3]);
                mma16(O[2*nd+1], Ph, Vl[2], Vl[3]);
                mma16(O[2*nd+1], Pl, Vh[2], Vh[3]);
            }
        }
        __syncthreads();
    }

    // ---- reduce row sums across quads, normalize, write out ----
    lsum0 += __shfl_xor_sync(0xffffffffu, lsum0, 1);
    lsum0 += __shfl_xor_sync(0xffffffffu, lsum0, 2);
    lsum1 += __shfl_xor_sync(0xffffffffu, lsum1, 1);
    lsum1 += __shfl_xor_sync(0xffffffffu, lsum1, 2);
    float inv0 = 1.f / lsum0;
    float inv1 = 1.f / lsum1;

    int row0 = t0 + 16 * w + (l >> 2);
    float* d0 = g_ao + ((size_t)(b * TT + row0)) * FF + (h << 6) + ((l & 3) << 1);
    float* d1 = d0 + (size_t)8 * FF;
#pragma unroll
    for (int nd = 0; nd < 8; nd++) {
        *(float2*)(d0 + nd * 8) = make_float2(O[nd][0] * inv0, O[nd][1] * inv0);
        *(float2*)(d1 + nd * 8) = make_float2(O[nd][2] * inv1, O[nd][3] * inv1);
    }
}

// ---------------------------------------------------------------------------
extern "C" void kernel_launch(void* const* d_in, const int* in_sizes, int n_in,
                              void* d_out, int out_size)
{
    const float* x    = (const float*)d_in[0];
    const float* pe   = (const float*)d_in[1];
    const float* Wq   = (const float*)d_in[2];
    const float* bq   = (const float*)d_in[3];
    const float* Wk   = (const float*)d_in[4];
    const float* bk   = (const float*)d_in[5];
    const float* Wv   = (const float*)d_in[6];
    const float* bv   = (const float*)d_in[7];
    const float* Wpos = (const float*)d_in[8];
    const float* Wout = (const float*)d_in[9];
    const float* bout = (const float*)d_in[10];
    const float* pbu  = (const float*)d_in[11];
    const float* pbv  = (const float*)d_in[12];
    float* out = (float*)d_out;

    cudaFuncSetAttribute(flash_kernel, cudaFuncAttributeMaxDynamicSharedMemorySize, FLASH_SMEM);

    dim3 blk(256);
    gemm_kernel<<<dim3(8, 128), blk>>>(x,  Wq, bq, 0, pbu, pbv, nullptr);
    gemm_kernel<<<dim3(8, 128), blk>>>(x,  Wk, bk, 1, nullptr, nullptr, nullptr);
    gemm_kernel<<<dim3(8, 128), blk>>>(x,  Wv, bv, 2, nullptr, nullptr, nullptr);
    gemm_kernel<<<dim3(8, 32),  blk>>>(pe, Wpos, nullptr, 3, nullptr, nullptr, nullptr);
    flash_kernel<<<dim3(TT / 128, BB * HH), blk, FLASH_SMEM>>>();
    gemm_kernel<<<dim3(8, 128), blk>>>(nullptr, Wout, bout, 4, nullptr, nullptr, out);
}

// round 4
// speedup vs baseline: 2.0310x; 1.1122x over previous
#include <cuda_runtime.h>
#include <cuda_bf16.h>
#include <cstdint>

#define BB 4
#define TT 2048
#define HH 8
#define FF 512
#define MM (BB*TT)   // 8192

// ---------------------------------------------------------------------------
// Global scratch (device globals; uint4 for 16B alignment)
// ---------------------------------------------------------------------------
__device__ uint4 g_qh_[1048576];   // q_cat hi: [bh=32][t=2048][128] bf16 (scaled 0.125, biases fused)
__device__ uint4 g_ql_[1048576];   // q_cat lo
__device__ uint4 g_kh_[1048576];   // k_cat hi: [bh][t][0:64]=k, [64:128]=p
__device__ uint4 g_kl_[1048576];
__device__ uint4 g_vh_[524288];    // V hi: [bh][t][64] bf16
__device__ uint4 g_vl_[524288];
__device__ float g_ao[(size_t)MM*FF];

#define G_QH ((__nv_bfloat16*)g_qh_)
#define G_QL ((__nv_bfloat16*)g_ql_)
#define G_KH ((__nv_bfloat16*)g_kh_)
#define G_KL ((__nv_bfloat16*)g_kl_)
#define G_VH ((__nv_bfloat16*)g_vh_)
#define G_VL ((__nv_bfloat16*)g_vl_)

// ---------------------------------------------------------------------------
__device__ __forceinline__ uint32_t cvta_s(const void* p) {
    return (uint32_t)__cvta_generic_to_shared(p);
}
__device__ __forceinline__ float ex2f(float x) {
    float r; asm("ex2.approx.ftz.f32 %0, %1;" : "=f"(r) : "f"(x)); return r;
}
// pack two f32 -> bf16x2 word: first arg -> low half, second -> high half
__device__ __forceinline__ uint32_t pack2(float lo, float hi) {
    uint32_t r; asm("cvt.rn.bf16x2.f32 %0, %1, %2;" : "=r"(r) : "f"(hi), "f"(lo)); return r;
}

__device__ __forceinline__ void ldsm4(uint32_t r[4], uint32_t a) {
    asm volatile("ldmatrix.sync.aligned.m8n8.x4.shared.b16 {%0,%1,%2,%3}, [%4];"
                 : "=r"(r[0]), "=r"(r[1]), "=r"(r[2]), "=r"(r[3]) : "r"(a));
}
__device__ __forceinline__ void ldsm4t(uint32_t r[4], uint32_t a) {
    asm volatile("ldmatrix.sync.aligned.m8n8.x4.trans.shared.b16 {%0,%1,%2,%3}, [%4];"
                 : "=r"(r[0]), "=r"(r[1]), "=r"(r[2]), "=r"(r[3]) : "r"(a));
}
// NOTE: non-volatile, no memory clobber — pure register op, lets ptxas
// interleave independent accumulator chains freely.
__device__ __forceinline__ void mma16(float c[4], const uint32_t a[4], uint32_t b0, uint32_t b1) {
    asm("mma.sync.aligned.m16n8k16.row.col.f32.bf16.bf16.f32 "
        "{%0,%1,%2,%3}, {%4,%5,%6,%7}, {%8,%9}, {%0,%1,%2,%3};"
        : "+f"(c[0]), "+f"(c[1]), "+f"(c[2]), "+f"(c[3])
        : "r"(a[0]), "r"(a[1]), "r"(a[2]), "r"(a[3]), "r"(b0), "r"(b1));
}

__device__ __forceinline__ void cpa16(uint32_t d, const void* s) {
    asm volatile("cp.async.cg.shared.global [%0], [%1], 16;" :: "r"(d), "l"(s) : "memory");
}
#define CPA_COMMIT() asm volatile("cp.async.commit_group;" ::: "memory")
#define CPA_WAIT1()  asm volatile("cp.async.wait_group 1;" ::: "memory")
#define CPA_WAIT0()  asm volatile("cp.async.wait_group 0;" ::: "memory")

// ---------------------------------------------------------------------------
// SIMT projection GEMM (C[m,n] = sum_k A[m,k]*W[n,k] + bias[n]) with
// mode-specific bf16 hi/lo scatter epilogues. (unchanged from R3)
// ---------------------------------------------------------------------------
__device__ __forceinline__ void fma16(float acc[4][4], float4 a, float4 b) {
    acc[0][0] += a.x*b.x; acc[0][1] += a.x*b.y; acc[0][2] += a.x*b.z; acc[0][3] += a.x*b.w;
    acc[1][0] += a.y*b.x; acc[1][1] += a.y*b.y; acc[1][2] += a.y*b.z; acc[1][3] += a.y*b.w;
    acc[2][0] += a.z*b.x; acc[2][1] += a.z*b.y; acc[2][2] += a.z*b.z; acc[2][3] += a.z*b.w;
    acc[3][0] += a.w*b.x; acc[3][1] += a.w*b.y; acc[3][2] += a.w*b.z; acc[3][3] += a.w*b.w;
}

__device__ __forceinline__ void split4(const float v[4], uint2& hi, uint2& lo) {
    uint32_t h0 = pack2(v[0], v[1]);
    uint32_t h1 = pack2(v[2], v[3]);
    float r0 = v[0] - __uint_as_float(h0 << 16);
    float r1 = v[1] - __uint_as_float(h0 & 0xffff0000u);
    float r2 = v[2] - __uint_as_float(h1 << 16);
    float r3 = v[3] - __uint_as_float(h1 & 0xffff0000u);
    hi = make_uint2(h0, h1);
    lo = make_uint2(pack2(r0, r1), pack2(r2, r3));
}

__global__ __launch_bounds__(256) void gemm_kernel(
    const float* __restrict__ A, const float* __restrict__ W,
    const float* __restrict__ bias, int mode,
    const float* __restrict__ pbu, const float* __restrict__ pbv,
    float* __restrict__ C)
{
    __shared__ float As[16][64];
    __shared__ float Ws[16][64];
    int tid = threadIdx.x;
    int ty = tid >> 4, tx = tid & 15;
    int m0 = blockIdx.y << 6, n0 = blockIdx.x << 6;
    int lr = tid >> 2, lc = (tid & 3) << 2;

    const float* Abase = (mode == 4) ? g_ao : A;
    const float* Ap = Abase + (size_t)(m0 + lr) * FF + lc;
    const float* Wp = W     + (size_t)(n0 + lr) * FF + lc;

    float acc[4][4] = {};

    for (int k0 = 0; k0 < FF; k0 += 16) {
        float4 av = *(const float4*)(Ap + k0);
        float4 wv = *(const float4*)(Wp + k0);
        __syncthreads();
        As[lc+0][lr] = av.x; As[lc+1][lr] = av.y; As[lc+2][lr] = av.z; As[lc+3][lr] = av.w;
        Ws[lc+0][lr] = wv.x; Ws[lc+1][lr] = wv.y; Ws[lc+2][lr] = wv.z; Ws[lc+3][lr] = wv.w;
        __syncthreads();
#pragma unroll
        for (int k = 0; k < 16; k++) {
            float4 a = *(const float4*)&As[k][ty << 2];
            float4 b = *(const float4*)&Ws[k][tx << 2];
            fma16(acc, a, b);
        }
    }

    int ncol = n0 + (tx << 2);
    int h = ncol >> 6, dd = ncol & 63;

    if (mode == 0) {
#pragma unroll
        for (int i = 0; i < 4; i++) {
            int m = m0 + (ty << 2) + i;
            int b = m >> 11, t = m & (TT - 1);
            float vu[4], vv[4];
#pragma unroll
            for (int j = 0; j < 4; j++) {
                float v = acc[i][j] + bias[ncol + j];
                vu[j] = (v + pbu[ncol + j]) * 0.125f;
                vv[j] = (v + pbv[ncol + j]) * 0.125f;
            }
            size_t base = ((size_t)(b * HH + h) * TT + t) * 128 + dd;
            uint2 hi, lo;
            split4(vu, hi, lo);
            *(uint2*)(G_QH + base) = hi; *(uint2*)(G_QL + base) = lo;
            split4(vv, hi, lo);
            *(uint2*)(G_QH + base + 64) = hi; *(uint2*)(G_QL + base + 64) = lo;
        }
    } else if (mode == 1) {
#pragma unroll
        for (int i = 0; i < 4; i++) {
            int m = m0 + (ty << 2) + i;
            int b = m >> 11, t = m & (TT - 1);
            float vk[4];
#pragma unroll
            for (int j = 0; j < 4; j++) vk[j] = acc[i][j] + bias[ncol + j];
            size_t base = ((size_t)(b * HH + h) * TT + t) * 128 + dd;
            uint2 hi, lo;
            split4(vk, hi, lo);
            *(uint2*)(G_KH + base) = hi; *(uint2*)(G_KL + base) = lo;
        }
    } else if (mode == 2) {
#pragma unroll
        for (int i = 0; i < 4; i++) {
            int m = m0 + (ty << 2) + i;
            int b = m >> 11, t = m & (TT - 1);
            float vk[4];
#pragma unroll
            for (int j = 0; j < 4; j++) vk[j] = acc[i][j] + bias[ncol + j];
            size_t base = ((size_t)(b * HH + h) * TT + t) * 64 + dd;
            uint2 hi, lo;
            split4(vk, hi, lo);
            *(uint2*)(G_VH + base) = hi; *(uint2*)(G_VL + base) = lo;
        }
    } else if (mode == 3) {
#pragma unroll
        for (int i = 0; i < 4; i++) {
            int t = m0 + (ty << 2) + i;   // m is t (0..2047)
            float vp[4];
#pragma unroll
            for (int j = 0; j < 4; j++) vp[j] = acc[i][j];
            uint2 hi, lo;
            split4(vp, hi, lo);
#pragma unroll
            for (int bb = 0; bb < BB; bb++) {
                size_t base = ((size_t)(bb * HH + h) * TT + t) * 128 + 64 + dd;
                *(uint2*)(G_KH + base) = hi; *(uint2*)(G_KL + base) = lo;
            }
        }
    } else {
#pragma unroll
        for (int i = 0; i < 4; i++) {
            int m = m0 + (ty << 2) + i;
#pragma unroll
            for (int j = 0; j < 4; j++) {
                int n = ncol + j;
                C[(size_t)m * FF + n] = acc[i][j] + bias[n];
            }
        }
    }
}

// ---------------------------------------------------------------------------
// mma.sync flash attention with cp.async double-buffered K/V pipeline.
// CTA = 128 q-rows of one (b,h), 8 warps x 16 rows. d_qk=128 (concat), d_v=64.
// Static-shift softmax p = e^(s-30); O accumulated in fp32 regs across tiles.
// ---------------------------------------------------------------------------
#define KSTR 272     // K/Q smem row stride bytes (128 bf16 + 16B pad)
#define VSTR 144     // V smem row stride bytes (64 bf16 + 16B pad)
#define SM_KH 0
#define SM_KL 34816
#define SM_VH 69632
#define SM_VL 88064
#define STAGE 106496
#define FLASH_SMEM (2*STAGE)   // 212992

#define LOG2E_F 1.4426950408889634f
#define EXPBIAS_F 43.280851226668914f   /* 30*log2(e) */

// issue cp.async for one K/V tile (s0) into stage base `stb`
__device__ __forceinline__ void copy_tile_async(uint32_t stb, int bh, int s0, int tid) {
    const uint4* kh = g_kh_ + ((size_t)bh * TT + s0) * 16;
    const uint4* kl = g_kl_ + ((size_t)bh * TT + s0) * 16;
#pragma unroll
    for (int i = 0; i < 8; i++) {
        int idx = tid + i * 256;
        int r = idx >> 4, c = idx & 15;
        cpa16(stb + SM_KH + r * KSTR + c * 16, kh + r * 16 + c);
        cpa16(stb + SM_KL + r * KSTR + c * 16, kl + r * 16 + c);
    }
    const uint4* vh = g_vh_ + ((size_t)bh * TT + s0) * 8;
    const uint4* vl = g_vl_ + ((size_t)bh * TT + s0) * 8;
#pragma unroll
    for (int i = 0; i < 4; i++) {
        int idx = tid + i * 256;
        int r = idx >> 3, c = idx & 7;
        cpa16(stb + SM_VH + r * VSTR + c * 16, vh + r * 8 + c);
        cpa16(stb + SM_VL + r * VSTR + c * 16, vl + r * 8 + c);
    }
}

__global__ __launch_bounds__(256) void flash_kernel()
{
    extern __shared__ char sm[];
    uint32_t sb = cvta_s(sm);

    int tid = threadIdx.x;
    int w = tid >> 5, l = tid & 31;
    int bh = blockIdx.y;
    int b = bh >> 3, h = bh & 7;
    int t0 = blockIdx.x << 7;

    // ---- prologue: Q -> stage1 (cp.async), tile0 -> stage0 (cp.async) ----
    {
        uint32_t qb = sb + STAGE;
        const uint4* qh = g_qh_ + ((size_t)bh * TT + t0) * 16;
        const uint4* ql = g_ql_ + ((size_t)bh * TT + t0) * 16;
#pragma unroll
        for (int i = 0; i < 8; i++) {
            int idx = tid + i * 256;
            int r = idx >> 4, c = idx & 15;
            cpa16(qb + SM_KH + r * KSTR + c * 16, qh + r * 16 + c);
            cpa16(qb + SM_KL + r * KSTR + c * 16, ql + r * 16 + c);
        }
        CPA_COMMIT();
        copy_tile_async(sb, bh, 0, tid);
        CPA_COMMIT();
    }
    CPA_WAIT1();           // Q landed
    __syncthreads();

    // ---- frag Q (16 rows per warp, full d=128, hi+lo) ----
    uint32_t Qh[8][4], Ql[8][4];
    {
        uint32_t rowa = sb + STAGE + (16 * w + (l & 15)) * KSTR + (l >> 4) * 16;
#pragma unroll
        for (int ks = 0; ks < 8; ks++) {
            ldsm4(Qh[ks], rowa + SM_KH + ks * 32);
            ldsm4(Ql[ks], rowa + SM_KL + ks * 32);
        }
    }

    float O[8][4];
#pragma unroll
    for (int i = 0; i < 8; i++)
#pragma unroll
        for (int j = 0; j < 4; j++) O[i][j] = 0.f;
    float lsum0 = 0.f, lsum1 = 0.f;

    uint32_t kB_rel = (l & 7) * KSTR + (l >> 3) * 16;                        // QK B frags
    uint32_t vB_rel = ((l & 7) + ((l >> 3) & 1) * 8) * VSTR + (l >> 4) * 16; // V frags

    for (int it = 0; it < 16; ++it) {
        __syncthreads();   // all warps done with previous compute (and Q frag at it=0)
        if (it < 15) {
            copy_tile_async(sb + ((it + 1) & 1) * STAGE, bh, (it + 1) << 7, tid);
            CPA_COMMIT();
            CPA_WAIT1();   // tile `it` complete (one group still in flight)
        } else {
            CPA_WAIT0();
        }
        __syncthreads();   // tile `it` visible to all warps

        uint32_t stb = sb + (it & 1) * STAGE;
        uint32_t kB_lane = stb + kB_rel;
        uint32_t vB_lane = stb + vB_rel;

#pragma unroll
        for (int kb = 0; kb < 8; kb++) {
            // ---- S for 16 keys (n-tiles 2kb, 2kb+1) over full d_qk=128 ----
            float S0A[4] = {0.f,0.f,0.f,0.f}, S0B[4] = {0.f,0.f,0.f,0.f};
            float S1A[4] = {0.f,0.f,0.f,0.f}, S1B[4] = {0.f,0.f,0.f,0.f};
            uint32_t r0a = kB_lane + (16 * kb) * KSTR;
            uint32_t r1a = kB_lane + (16 * kb + 8) * KSTR;
#pragma unroll
            for (int j = 0; j < 4; j++) {
                float* S0 = (j & 1) ? S0B : S0A;
                float* S1 = (j & 1) ? S1B : S1A;
                uint32_t Bh[4], Bl[4];
                ldsm4(Bh, r0a + SM_KH + j * 64);
                ldsm4(Bl, r0a + SM_KL + j * 64);
                mma16(S0, Qh[2*j],   Bh[0], Bh[1]);
                mma16(S0, Qh[2*j],   Bl[0], Bl[1]);
                mma16(S0, Ql[2*j],   Bh[0], Bh[1]);
                mma16(S0, Qh[2*j+1], Bh[2], Bh[3]);
                mma16(S0, Qh[2*j+1], Bl[2], Bl[3]);
                mma16(S0, Ql[2*j+1], Bh[2], Bh[3]);
                ldsm4(Bh, r1a + SM_KH + j * 64);
                ldsm4(Bl, r1a + SM_KL + j * 64);
                mma16(S1, Qh[2*j],   Bh[0], Bh[1]);
                mma16(S1, Qh[2*j],   Bl[0], Bl[1]);
                mma16(S1, Ql[2*j],   Bh[0], Bh[1]);
                mma16(S1, Qh[2*j+1], Bh[2], Bh[3]);
                mma16(S1, Qh[2*j+1], Bl[2], Bl[3]);
                mma16(S1, Ql[2*j+1], Bh[2], Bh[3]);
            }

            // ---- softmax terms + P fragments (bf16 hi/lo) ----
            float p00 = ex2f(fmaf(S0A[0]+S0B[0], LOG2E_F, -EXPBIAS_F));
            float p01 = ex2f(fmaf(S0A[1]+S0B[1], LOG2E_F, -EXPBIAS_F));
            float p02 = ex2f(fmaf(S0A[2]+S0B[2], LOG2E_F, -EXPBIAS_F));
            float p03 = ex2f(fmaf(S0A[3]+S0B[3], LOG2E_F, -EXPBIAS_F));
            float p10 = ex2f(fmaf(S1A[0]+S1B[0], LOG2E_F, -EXPBIAS_F));
            float p11 = ex2f(fmaf(S1A[1]+S1B[1], LOG2E_F, -EXPBIAS_F));
            float p12 = ex2f(fmaf(S1A[2]+S1B[2], LOG2E_F, -EXPBIAS_F));
            float p13 = ex2f(fmaf(S1A[3]+S1B[3], LOG2E_F, -EXPBIAS_F));
            lsum0 += (p00 + p01) + (p10 + p11);
            lsum1 += (p02 + p03) + (p12 + p13);

            uint32_t Ph[4], Pl[4];
            Ph[0] = pack2(p00, p01);
            Ph[1] = pack2(p02, p03);
            Ph[2] = pack2(p10, p11);
            Ph[3] = pack2(p12, p13);
            Pl[0] = pack2(p00 - __uint_as_float(Ph[0] << 16), p01 - __uint_as_float(Ph[0] & 0xffff0000u));
            Pl[1] = pack2(p02 - __uint_as_float(Ph[1] << 16), p03 - __uint_as_float(Ph[1] & 0xffff0000u));
            Pl[2] = pack2(p10 - __uint_as_float(Ph[2] << 16), p11 - __uint_as_float(Ph[2] & 0xffff0000u));
            Pl[3] = pack2(p12 - __uint_as_float(Ph[3] << 16), p13 - __uint_as_float(Ph[3] & 0xffff0000u));

            // ---- O += P @ V for this 16-key block (8 independent chains) ----
            uint32_t va = vB_lane + (16 * kb) * VSTR;
#pragma unroll
            for (int nd = 0; nd < 4; nd++) {
                uint32_t Vh[4], Vl[4];
                ldsm4t(Vh, va + SM_VH + nd * 32);
                ldsm4t(Vl, va + SM_VL + nd * 32);
                mma16(O[2*nd],   Ph, Vh[0], Vh[1]);
                mma16(O[2*nd+1], Ph, Vh[2], Vh[3]);
                mma16(O[2*nd],   Ph, Vl[0], Vl[1]);
                mma16(O[2*nd+1], Ph, Vl[2], Vl[3]);
                mma16(O[2*nd],   Pl, Vh[0], Vh[1]);
                mma16(O[2*nd+1], Pl, Vh[2], Vh[3]);
            }
        }
    }

    // ---- reduce row sums across quads, normalize, write out ----
    lsum0 += __shfl_xor_sync(0xffffffffu, lsum0, 1);
    lsum0 += __shfl_xor_sync(0xffffffffu, lsum0, 2);
    lsum1 += __shfl_xor_sync(0xffffffffu, lsum1, 1);
    lsum1 += __shfl_xor_sync(0xffffffffu, lsum1, 2);
    float inv0 = 1.f / lsum0;
    float inv1 = 1.f / lsum1;

    int row0 = t0 + 16 * w + (l >> 2);
    float* d0 = g_ao + ((size_t)(b * TT + row0)) * FF + (h << 6) + ((l & 3) << 1);
    float* d1 = d0 + (size_t)8 * FF;
#pragma unroll
    for (int nd = 0; nd < 8; nd++) {
        *(float2*)(d0 + nd * 8) = make_float2(O[nd][0] * inv0, O[nd][1] * inv0);
        *(float2*)(d1 + nd * 8) = make_float2(O[nd][2] * inv1, O[nd][3] * inv1);
    }
}

// ---------------------------------------------------------------------------
extern "C" void kernel_launch(void* const* d_in, const int* in_sizes, int n_in,
                              void* d_out, int out_size)
{
    const float* x    = (const float*)d_in[0];
    const float* pe   = (const float*)d_in[1];
    const float* Wq   = (const float*)d_in[2];
    const float* bq   = (const float*)d_in[3];
    const float* Wk   = (const float*)d_in[4];
    const float* bk   = (const float*)d_in[5];
    const float* Wv   = (const float*)d_in[6];
    const float* bv   = (const float*)d_in[7];
    const float* Wpos = (const float*)d_in[8];
    const float* Wout = (const float*)d_in[9];
    const float* bout = (const float*)d_in[10];
    const float* pbu  = (const float*)d_in[11];
    const float* pbv  = (const float*)d_in[12];
    float* out = (float*)d_out;

    cudaFuncSetAttribute(flash_kernel, cudaFuncAttributeMaxDynamicSharedMemorySize, FLASH_SMEM);

    dim3 blk(256);
    gemm_kernel<<<dim3(8, 128), blk>>>(x,  Wq, bq, 0, pbu, pbv, nullptr);
    gemm_kernel<<<dim3(8, 128), blk>>>(x,  Wk, bk, 1, nullptr, nullptr, nullptr);
    gemm_kernel<<<dim3(8, 128), blk>>>(x,  Wv, bv, 2, nullptr, nullptr, nullptr);
    gemm_kernel<<<dim3(8, 32),  blk>>>(pe, Wpos, nullptr, 3, nullptr, nullptr, nullptr);
    flash_kernel<<<dim3(TT / 128, BB * HH), blk, FLASH_SMEM>>>();
    gemm_kernel<<<dim3(8, 128), blk>>>(nullptr, Wout, bout, 4, nullptr, nullptr, out);
}

// round 5
// speedup vs baseline: 2.1465x; 1.0569x over previous
#include <cuda_runtime.h>
#include <cuda_bf16.h>
#include <cstdint>

#define BB 4
#define TT 2048
#define HH 8
#define FF 512
#define MM (BB*TT)   // 8192

// ---------------------------------------------------------------------------
// Global scratch (device globals; uint4 for 16B alignment)
// ---------------------------------------------------------------------------
__device__ uint4 g_qh_[1048576];   // q_cat hi: [bh=32][t=2048][128] bf16 (scaled 0.125, biases fused)
__device__ uint4 g_ql_[1048576];   // q_cat lo
__device__ uint4 g_kh_[1048576];   // k_cat hi: [bh][t][0:64]=k, [64:128]=p
__device__ uint4 g_kl_[1048576];
__device__ uint4 g_vh_[524288];    // V hi: [bh][t][64] bf16
__device__ uint4 g_vl_[524288];
__device__ float g_po0[(size_t)MM*FF];  // partial O (keys 0:1024), unnormalized
__device__ float g_po1[(size_t)MM*FF];  // partial O (keys 1024:2048)
__device__ float g_ls0[32*TT];          // partial row sums
__device__ float g_ls1[32*TT];
__device__ float g_ao[(size_t)MM*FF];   // combined attention out

#define G_QH ((__nv_bfloat16*)g_qh_)
#define G_QL ((__nv_bfloat16*)g_ql_)
#define G_KH ((__nv_bfloat16*)g_kh_)
#define G_KL ((__nv_bfloat16*)g_kl_)
#define G_VH ((__nv_bfloat16*)g_vh_)
#define G_VL ((__nv_bfloat16*)g_vl_)

// ---------------------------------------------------------------------------
__device__ __forceinline__ uint32_t cvta_s(const void* p) {
    return (uint32_t)__cvta_generic_to_shared(p);
}
__device__ __forceinline__ float ex2f(float x) {
    float r; asm("ex2.approx.ftz.f32 %0, %1;" : "=f"(r) : "f"(x)); return r;
}
// pack two f32 -> bf16x2 word: first arg -> low half, second -> high half
__device__ __forceinline__ uint32_t pack2(float lo, float hi) {
    uint32_t r; asm("cvt.rn.bf16x2.f32 %0, %1, %2;" : "=r"(r) : "f"(hi), "f"(lo)); return r;
}

__device__ __forceinline__ void ldsm4(uint32_t r[4], uint32_t a) {
    asm volatile("ldmatrix.sync.aligned.m8n8.x4.shared.b16 {%0,%1,%2,%3}, [%4];"
                 : "=r"(r[0]), "=r"(r[1]), "=r"(r[2]), "=r"(r[3]) : "r"(a));
}
__device__ __forceinline__ void ldsm4t(uint32_t r[4], uint32_t a) {
    asm volatile("ldmatrix.sync.aligned.m8n8.x4.trans.shared.b16 {%0,%1,%2,%3}, [%4];"
                 : "=r"(r[0]), "=r"(r[1]), "=r"(r[2]), "=r"(r[3]) : "r"(a));
}
// non-volatile, no memory clobber — pure register op, lets ptxas interleave
__device__ __forceinline__ void mma16(float c[4], const uint32_t a[4], uint32_t b0, uint32_t b1) {
    asm("mma.sync.aligned.m16n8k16.row.col.f32.bf16.bf16.f32 "
        "{%0,%1,%2,%3}, {%4,%5,%6,%7}, {%8,%9}, {%0,%1,%2,%3};"
        : "+f"(c[0]), "+f"(c[1]), "+f"(c[2]), "+f"(c[3])
        : "r"(a[0]), "r"(a[1]), "r"(a[2]), "r"(a[3]), "r"(b0), "r"(b1));
}

__device__ __forceinline__ void cpa16(uint32_t d, const void* s) {
    asm volatile("cp.async.cg.shared.global [%0], [%1], 16;" :: "r"(d), "l"(s) : "memory");
}
#define CPA_COMMIT() asm volatile("cp.async.commit_group;" ::: "memory")
#define CPA_WAIT1()  asm volatile("cp.async.wait_group 1;" ::: "memory")
#define CPA_WAIT0()  asm volatile("cp.async.wait_group 0;" ::: "memory")

// ---------------------------------------------------------------------------
// SIMT projection GEMM (near FFMA roofline; unchanged)
// ---------------------------------------------------------------------------
__device__ __forceinline__ void fma16(float acc[4][4], float4 a, float4 b) {
    acc[0][0] += a.x*b.x; acc[0][1] += a.x*b.y; acc[0][2] += a.x*b.z; acc[0][3] += a.x*b.w;
    acc[1][0] += a.y*b.x; acc[1][1] += a.y*b.y; acc[1][2] += a.y*b.z; acc[1][3] += a.y*b.w;
    acc[2][0] += a.z*b.x; acc[2][1] += a.z*b.y; acc[2][2] += a.z*b.z; acc[2][3] += a.z*b.w;
    acc[3][0] += a.w*b.x; acc[3][1] += a.w*b.y; acc[3][2] += a.w*b.z; acc[3][3] += a.w*b.w;
}

__device__ __forceinline__ void split4(const float v[4], uint2& hi, uint2& lo) {
    uint32_t h0 = pack2(v[0], v[1]);
    uint32_t h1 = pack2(v[2], v[3]);
    float r0 = v[0] - __uint_as_float(h0 << 16);
    float r1 = v[1] - __uint_as_float(h0 & 0xffff0000u);
    float r2 = v[2] - __uint_as_float(h1 << 16);
    float r3 = v[3] - __uint_as_float(h1 & 0xffff0000u);
    hi = make_uint2(h0, h1);
    lo = make_uint2(pack2(r0, r1), pack2(r2, r3));
}

__global__ __launch_bounds__(256) void gemm_kernel(
    const float* __restrict__ A, const float* __restrict__ W,
    const float* __restrict__ bias, int mode,
    const float* __restrict__ pbu, const float* __restrict__ pbv,
    float* __restrict__ C)
{
    __shared__ float As[16][64];
    __shared__ float Ws[16][64];
    int tid = threadIdx.x;
    int ty = tid >> 4, tx = tid & 15;
    int m0 = blockIdx.y << 6, n0 = blockIdx.x << 6;
    int lr = tid >> 2, lc = (tid & 3) << 2;

    const float* Abase = (mode == 4) ? g_ao : A;
    const float* Ap = Abase + (size_t)(m0 + lr) * FF + lc;
    const float* Wp = W     + (size_t)(n0 + lr) * FF + lc;

    float acc[4][4] = {};

    for (int k0 = 0; k0 < FF; k0 += 16) {
        float4 av = *(const float4*)(Ap + k0);
        float4 wv = *(const float4*)(Wp + k0);
        __syncthreads();
        As[lc+0][lr] = av.x; As[lc+1][lr] = av.y; As[lc+2][lr] = av.z; As[lc+3][lr] = av.w;
        Ws[lc+0][lr] = wv.x; Ws[lc+1][lr] = wv.y; Ws[lc+2][lr] = wv.z; Ws[lc+3][lr] = wv.w;
        __syncthreads();
#pragma unroll
        for (int k = 0; k < 16; k++) {
            float4 a = *(const float4*)&As[k][ty << 2];
            float4 b = *(const float4*)&Ws[k][tx << 2];
            fma16(acc, a, b);
        }
    }

    int ncol = n0 + (tx << 2);
    int h = ncol >> 6, dd = ncol & 63;

    if (mode == 0) {
#pragma unroll
        for (int i = 0; i < 4; i++) {
            int m = m0 + (ty << 2) + i;
            int b = m >> 11, t = m & (TT - 1);
            float vu[4], vv[4];
#pragma unroll
            for (int j = 0; j < 4; j++) {
                float v = acc[i][j] + bias[ncol + j];
                vu[j] = (v + pbu[ncol + j]) * 0.125f;
                vv[j] = (v + pbv[ncol + j]) * 0.125f;
            }
            size_t base = ((size_t)(b * HH + h) * TT + t) * 128 + dd;
            uint2 hi, lo;
            split4(vu, hi, lo);
            *(uint2*)(G_QH + base) = hi; *(uint2*)(G_QL + base) = lo;
            split4(vv, hi, lo);
            *(uint2*)(G_QH + base + 64) = hi; *(uint2*)(G_QL + base + 64) = lo;
        }
    } else if (mode == 1) {
#pragma unroll
        for (int i = 0; i < 4; i++) {
            int m = m0 + (ty << 2) + i;
            int b = m >> 11, t = m & (TT - 1);
            float vk[4];
#pragma unroll
            for (int j = 0; j < 4; j++) vk[j] = acc[i][j] + bias[ncol + j];
            size_t base = ((size_t)(b * HH + h) * TT + t) * 128 + dd;
            uint2 hi, lo;
            split4(vk, hi, lo);
            *(uint2*)(G_KH + base) = hi; *(uint2*)(G_KL + base) = lo;
        }
    } else if (mode == 2) {
#pragma unroll
        for (int i = 0; i < 4; i++) {
            int m = m0 + (ty << 2) + i;
            int b = m >> 11, t = m & (TT - 1);
            float vk[4];
#pragma unroll
            for (int j = 0; j < 4; j++) vk[j] = acc[i][j] + bias[ncol + j];
            size_t base = ((size_t)(b * HH + h) * TT + t) * 64 + dd;
            uint2 hi, lo;
            split4(vk, hi, lo);
            *(uint2*)(G_VH + base) = hi; *(uint2*)(G_VL + base) = lo;
        }
    } else if (mode == 3) {
#pragma unroll
        for (int i = 0; i < 4; i++) {
            int t = m0 + (ty << 2) + i;   // m is t (0..2047)
            float vp[4];
#pragma unroll
            for (int j = 0; j < 4; j++) vp[j] = acc[i][j];
            uint2 hi, lo;
            split4(vp, hi, lo);
#pragma unroll
            for (int bb = 0; bb < BB; bb++) {
                size_t base = ((size_t)(bb * HH + h) * TT + t) * 128 + 64 + dd;
                *(uint2*)(G_KH + base) = hi; *(uint2*)(G_KL + base) = lo;
            }
        }
    } else {
#pragma unroll
        for (int i = 0; i < 4; i++) {
            int m = m0 + (ty << 2) + i;
#pragma unroll
            for (int j = 0; j < 4; j++) {
                int n = ncol + j;
                C[(size_t)m * FF + n] = acc[i][j] + bias[n];
            }
        }
    }
}

// ---------------------------------------------------------------------------
// mma.sync flash attention, key-split (blockIdx.z halves the key range),
// cp.async double-buffered K/V pipeline, register-double-buffered fragments.
// CTA = 128 q-rows x 1024 keys of one (b,h). Writes unnormalized partial O
// + partial row sums; combine_kernel merges.
// ---------------------------------------------------------------------------
#define KSTR 272     // K/Q smem row stride bytes (128 bf16 + 16B pad)
#define VSTR 144     // V smem row stride bytes (64 bf16 + 16B pad)
#define SM_KH 0
#define SM_KL 34816
#define SM_VH 69632
#define SM_VL 88064
#define STAGE 106496
#define FLASH_SMEM (2*STAGE)   // 212992

#define LOG2E_F 1.4426950408889634f
#define EXPBIAS_F 43.280851226668914f   /* 30*log2(e) */

__device__ __forceinline__ void copy_tile_async(uint32_t stb, int bh, int s0, int tid) {
    const uint4* kh = g_kh_ + ((size_t)bh * TT + s0) * 16;
    const uint4* kl = g_kl_ + ((size_t)bh * TT + s0) * 16;
#pragma unroll
    for (int i = 0; i < 8; i++) {
        int idx = tid + i * 256;
        int r = idx >> 4, c = idx & 15;
        cpa16(stb + SM_KH + r * KSTR + c * 16, kh + r * 16 + c);
        cpa16(stb + SM_KL + r * KSTR + c * 16, kl + r * 16 + c);
    }
    const uint4* vh = g_vh_ + ((size_t)bh * TT + s0) * 8;
    const uint4* vl = g_vl_ + ((size_t)bh * TT + s0) * 8;
#pragma unroll
    for (int i = 0; i < 4; i++) {
        int idx = tid + i * 256;
        int r = idx >> 3, c = idx & 7;
        cpa16(stb + SM_VH + r * VSTR + c * 16, vh + r * 8 + c);
        cpa16(stb + SM_VL + r * VSTR + c * 16, vl + r * 8 + c);
    }
}

__global__ __launch_bounds__(256) void flash_kernel()
{
    extern __shared__ char sm[];
    uint32_t sb = cvta_s(sm);

    int tid = threadIdx.x;
    int w = tid >> 5, l = tid & 31;
    int bh = blockIdx.y;
    int b = bh >> 3, h = bh & 7;
    int t0 = blockIdx.x << 7;
    int z  = blockIdx.z;
    int kbase = z << 10;          // key range [kbase, kbase+1024)

    // ---- prologue: Q -> stage1 (cp.async), tile0 -> stage0 (cp.async) ----
    {
        uint32_t qb = sb + STAGE;
        const uint4* qh = g_qh_ + ((size_t)bh * TT + t0) * 16;
        const uint4* ql = g_ql_ + ((size_t)bh * TT + t0) * 16;
#pragma unroll
        for (int i = 0; i < 8; i++) {
            int idx = tid + i * 256;
            int r = idx >> 4, c = idx & 15;
            cpa16(qb + SM_KH + r * KSTR + c * 16, qh + r * 16 + c);
            cpa16(qb + SM_KL + r * KSTR + c * 16, ql + r * 16 + c);
        }
        CPA_COMMIT();
        copy_tile_async(sb, bh, kbase, tid);
        CPA_COMMIT();
    }
    CPA_WAIT1();           // Q landed
    __syncthreads();

    // ---- frag Q (16 rows per warp, full d=128, hi+lo) ----
    uint32_t Qh[8][4], Ql[8][4];
    {
        uint32_t rowa = sb + STAGE + (16 * w + (l & 15)) * KSTR + (l >> 4) * 16;
#pragma unroll
        for (int ks = 0; ks < 8; ks++) {
            ldsm4(Qh[ks], rowa + SM_KH + ks * 32);
            ldsm4(Ql[ks], rowa + SM_KL + ks * 32);
        }
    }

    float O[8][4];
#pragma unroll
    for (int i = 0; i < 8; i++)
#pragma unroll
        for (int j = 0; j < 4; j++) O[i][j] = 0.f;
    float lsum0 = 0.f, lsum1 = 0.f;

    uint32_t kB_rel = (l & 7) * KSTR + (l >> 3) * 16;
    uint32_t vB_rel = ((l & 7) + ((l >> 3) & 1) * 8) * VSTR + (l >> 4) * 16;

    for (int it = 0; it < 8; ++it) {
        __syncthreads();   // all warps done with stage being overwritten
        if (it < 7) {
            copy_tile_async(sb + ((it + 1) & 1) * STAGE, bh, kbase + ((it + 1) << 7), tid);
            CPA_COMMIT();
            CPA_WAIT1();   // tile `it` complete
        } else {
            CPA_WAIT0();
        }
        __syncthreads();   // tile `it` visible

        uint32_t stb = sb + (it & 1) * STAGE;
        uint32_t kB_lane = stb + kB_rel;
        uint32_t vB_lane = stb + vB_rel;

#pragma unroll
        for (int kb = 0; kb < 8; kb++) {
            // ---- S for 16 keys over full d_qk=128, B frags double-buffered ----
            float S0A[4] = {0.f,0.f,0.f,0.f}, S0B[4] = {0.f,0.f,0.f,0.f};
            float S1A[4] = {0.f,0.f,0.f,0.f}, S1B[4] = {0.f,0.f,0.f,0.f};
            uint32_t r0a = kB_lane + (16 * kb) * KSTR;
            uint32_t r1a = r0a + 8 * KSTR;

            uint32_t Bh0[2][4], Bl0[2][4], Bh1[2][4], Bl1[2][4];
            ldsm4(Bh0[0], r0a + SM_KH); ldsm4(Bl0[0], r0a + SM_KL);
            ldsm4(Bh1[0], r1a + SM_KH); ldsm4(Bl1[0], r1a + SM_KL);
#pragma unroll
            for (int j = 0; j < 4; j++) {
                int cur = j & 1, nxt = cur ^ 1;
                if (j < 3) {
                    ldsm4(Bh0[nxt], r0a + SM_KH + (j + 1) * 64);
                    ldsm4(Bl0[nxt], r0a + SM_KL + (j + 1) * 64);
                    ldsm4(Bh1[nxt], r1a + SM_KH + (j + 1) * 64);
                    ldsm4(Bl1[nxt], r1a + SM_KL + (j + 1) * 64);
                }
                float* S0 = (j & 1) ? S0B : S0A;
                float* S1 = (j & 1) ? S1B : S1A;
                mma16(S0, Qh[2*j],   Bh0[cur][0], Bh0[cur][1]);
                mma16(S1, Qh[2*j],   Bh1[cur][0], Bh1[cur][1]);
                mma16(S0, Qh[2*j],   Bl0[cur][0], Bl0[cur][1]);
                mma16(S1, Qh[2*j],   Bl1[cur][0], Bl1[cur][1]);
                mma16(S0, Ql[2*j],   Bh0[cur][0], Bh0[cur][1]);
                mma16(S1, Ql[2*j],   Bh1[cur][0], Bh1[cur][1]);
                mma16(S0, Qh[2*j+1], Bh0[cur][2], Bh0[cur][3]);
                mma16(S1, Qh[2*j+1], Bh1[cur][2], Bh1[cur][3]);
                mma16(S0, Qh[2*j+1], Bl0[cur][2], Bl0[cur][3]);
                mma16(S1, Qh[2*j+1], Bl1[cur][2], Bl1[cur][3]);
                mma16(S0, Ql[2*j+1], Bh0[cur][2], Bh0[cur][3]);
                mma16(S1, Ql[2*j+1], Bh1[cur][2], Bh1[cur][3]);
            }

            // ---- start V frag loads (latency hidden under softmax math) ----
            uint32_t va = vB_lane + (16 * kb) * VSTR;
            uint32_t Vh[2][4], Vl[2][4];
            ldsm4t(Vh[0], va + SM_VH); ldsm4t(Vl[0], va + SM_VL);

            // ---- softmax terms + P fragments (bf16 hi/lo) ----
            float p00 = ex2f(fmaf(S0A[0]+S0B[0], LOG2E_F, -EXPBIAS_F));
            float p01 = ex2f(fmaf(S0A[1]+S0B[1], LOG2E_F, -EXPBIAS_F));
            float p02 = ex2f(fmaf(S0A[2]+S0B[2], LOG2E_F, -EXPBIAS_F));
            float p03 = ex2f(fmaf(S0A[3]+S0B[3], LOG2E_F, -EXPBIAS_F));
            float p10 = ex2f(fmaf(S1A[0]+S1B[0], LOG2E_F, -EXPBIAS_F));
            float p11 = ex2f(fmaf(S1A[1]+S1B[1], LOG2E_F, -EXPBIAS_F));
            float p12 = ex2f(fmaf(S1A[2]+S1B[2], LOG2E_F, -EXPBIAS_F));
            float p13 = ex2f(fmaf(S1A[3]+S1B[3], LOG2E_F, -EXPBIAS_F));
            lsum0 += (p00 + p01) + (p10 + p11);
            lsum1 += (p02 + p03) + (p12 + p13);

            uint32_t Ph[4], Pl[4];
            Ph[0] = pack2(p00, p01);
            Ph[1] = pack2(p02, p03);
            Ph[2] = pack2(p10, p11);
            Ph[3] = pack2(p12, p13);
            Pl[0] = pack2(p00 - __uint_as_float(Ph[0] << 16), p01 - __uint_as_float(Ph[0] & 0xffff0000u));
            Pl[1] = pack2(p02 - __uint_as_float(Ph[1] << 16), p03 - __uint_as_float(Ph[1] & 0xffff0000u));
            Pl[2] = pack2(p10 - __uint_as_float(Ph[2] << 16), p11 - __uint_as_float(Ph[2] & 0xffff0000u));
            Pl[3] = pack2(p12 - __uint_as_float(Ph[3] << 16), p13 - __uint_as_float(Ph[3] & 0xffff0000u));

            // ---- O += P @ V, V frags double-buffered ----
#pragma unroll
            for (int nd = 0; nd < 4; nd++) {
                int cur = nd & 1, nxt = cur ^ 1;
                if (nd < 3) {
                    ldsm4t(Vh[nxt], va + SM_VH + (nd + 1) * 32);
                    ldsm4t(Vl[nxt], va + SM_VL + (nd + 1) * 32);
                }
                mma16(O[2*nd],   Ph, Vh[cur][0], Vh[cur][1]);
                mma16(O[2*nd+1], Ph, Vh[cur][2], Vh[cur][3]);
                mma16(O[2*nd],   Ph, Vl[cur][0], Vl[cur][1]);
                mma16(O[2*nd+1], Ph, Vl[cur][2], Vl[cur][3]);
                mma16(O[2*nd],   Pl, Vh[cur][0], Vh[cur][1]);
                mma16(O[2*nd+1], Pl, Vh[cur][2], Vh[cur][3]);
            }
        }
    }

    // ---- reduce row sums across quads, write unnormalized partials ----
    lsum0 += __shfl_xor_sync(0xffffffffu, lsum0, 1);
    lsum0 += __shfl_xor_sync(0xffffffffu, lsum0, 2);
    lsum1 += __shfl_xor_sync(0xffffffffu, lsum1, 1);
    lsum1 += __shfl_xor_sync(0xffffffffu, lsum1, 2);

    float* po = z ? g_po1 : g_po0;
    float* ls = z ? g_ls1 : g_ls0;

    int row0 = t0 + 16 * w + (l >> 2);
    if ((l & 3) == 0) {
        ls[bh * TT + row0] = lsum0;
        ls[bh * TT + row0 + 8] = lsum1;
    }
    float* d0 = po + ((size_t)(b * TT + row0)) * FF + (h << 6) + ((l & 3) << 1);
    float* d1 = d0 + (size_t)8 * FF;
#pragma unroll
    for (int nd = 0; nd < 8; nd++) {
        *(float2*)(d0 + nd * 8) = make_float2(O[nd][0], O[nd][1]);
        *(float2*)(d1 + nd * 8) = make_float2(O[nd][2], O[nd][3]);
    }
}

// ---------------------------------------------------------------------------
// combine partial O halves + row sums -> normalized g_ao
// ---------------------------------------------------------------------------
__global__ __launch_bounds__(256) void combine_kernel()
{
    int idx = blockIdx.x * 256 + threadIdx.x;   // float4 units over MM*FF
    int m = idx >> 7;
    int c = (idx & 127) << 2;
    int h = c >> 6;
    int b = m >> 11, t = m & (TT - 1);
    float lt = g_ls0[(b * HH + h) * TT + t] + g_ls1[(b * HH + h) * TT + t];
    float inv = 1.f / lt;
    float4 o0 = *(const float4*)(g_po0 + (size_t)idx * 4);
    float4 o1 = *(const float4*)(g_po1 + (size_t)idx * 4);
    *(float4*)(g_ao + (size_t)idx * 4) =
        make_float4((o0.x + o1.x) * inv, (o0.y + o1.y) * inv,
                    (o0.z + o1.z) * inv, (o0.w + o1.w) * inv);
}

// ---------------------------------------------------------------------------
extern "C" void kernel_launch(void* const* d_in, const int* in_sizes, int n_in,
                              void* d_out, int out_size)
{
    const float* x    = (const float*)d_in[0];
    const float* pe   = (const float*)d_in[1];
    const float* Wq   = (const float*)d_in[2];
    const float* bq   = (const float*)d_in[3];
    const float* Wk   = (const float*)d_in[4];
    const float* bk   = (const float*)d_in[5];
    const float* Wv   = (const float*)d_in[6];
    const float* bv   = (const float*)d_in[7];
    const float* Wpos = (const float*)d_in[8];
    const float* Wout = (const float*)d_in[9];
    const float* bout = (const float*)d_in[10];
    const float* pbu  = (const float*)d_in[11];
    const float* pbv  = (const float*)d_in[12];
    float* out = (float*)d_out;

    cudaFuncSetAttribute(flash_kernel, cudaFuncAttributeMaxDynamicSharedMemorySize, FLASH_SMEM);

    dim3 blk(256);
    gemm_kernel<<<dim3(8, 128), blk>>>(x,  Wq, bq, 0, pbu, pbv, nullptr);
    gemm_kernel<<<dim3(8, 128), blk>>>(x,  Wk, bk, 1, nullptr, nullptr, nullptr);
    gemm_kernel<<<dim3(8, 128), blk>>>(x,  Wv, bv, 2, nullptr, nullptr, nullptr);
    gemm_kernel<<<dim3(8, 32),  blk>>>(pe, Wpos, nullptr, 3, nullptr, nullptr, nullptr);
    flash_kernel<<<dim3(TT / 128, BB * HH, 2), blk, FLASH_SMEM>>>();
    combine_kernel<<<dim3((MM * FF) / 1024), blk>>>();
    gemm_kernel<<<dim3(8, 128), blk>>>(nullptr, Wout, bout, 4, nullptr, nullptr, out);
}

// round 6
// speedup vs baseline: 2.2134x; 1.0312x over previous
#include <cuda_runtime.h>
#include <cuda_bf16.h>
#include <cuda_fp16.h>
#include <cstdint>

#define BB 4
#define TT 2048
#define HH 8
#define FF 512
#define MM (BB*TT)   // 8192

// ---------------------------------------------------------------------------
// Global scratch (device globals; uint4 for 16B alignment)
// ---------------------------------------------------------------------------
__device__ uint4 g_qh_[1048576];   // q_cat fp16 (single): [bh=32][t=2048][128] (scaled 0.125, biases fused)
__device__ uint4 g_kh_[1048576];   // k_cat hi fp16: [bh][t][0:64]=k, [64:128]=p
__device__ uint4 g_kl_[1048576];   // k_cat lo fp16
__device__ uint4 g_vh_[524288];    // V hi fp16: [bh][t][64]
__device__ uint4 g_vl_[524288];    // V lo fp16
__device__ float g_po0[(size_t)MM*FF];  // partial O (keys 0:1024), unnormalized
__device__ float g_po1[(size_t)MM*FF];  // partial O (keys 1024:2048)
__device__ float g_ls0[32*TT];          // partial row sums
__device__ float g_ls1[32*TT];
__device__ float g_lm0[32*TT];          // partial row maxes
__device__ float g_lm1[32*TT];
__device__ float g_ao[(size_t)MM*FF];   // combined attention out

#define G_QH ((__half*)g_qh_)
#define G_KH ((__half*)g_kh_)
#define G_KL ((__half*)g_kl_)
#define G_VH ((__half*)g_vh_)
#define G_VL ((__half*)g_vl_)

// ---------------------------------------------------------------------------
__device__ __forceinline__ uint32_t cvta_s(const void* p) {
    return (uint32_t)__cvta_generic_to_shared(p);
}
__device__ __forceinline__ float ex2f(float x) {
    float r; asm("ex2.approx.ftz.f32 %0, %1;" : "=f"(r) : "f"(x)); return r;
}
// pack two f32 -> f16x2 word: first arg -> low half, second -> high half
__device__ __forceinline__ uint32_t pack2h(float lo, float hi) {
    uint32_t r; asm("cvt.rn.f16x2.f32 %0, %1, %2;" : "=r"(r) : "f"(hi), "f"(lo)); return r;
}

__device__ __forceinline__ void ldsm4(uint32_t r[4], uint32_t a) {
    asm volatile("ldmatrix.sync.aligned.m8n8.x4.shared.b16 {%0,%1,%2,%3}, [%4];"
                 : "=r"(r[0]), "=r"(r[1]), "=r"(r[2]), "=r"(r[3]) : "r"(a));
}
__device__ __forceinline__ void ldsm4t(uint32_t r[4], uint32_t a) {
    asm volatile("ldmatrix.sync.aligned.m8n8.x4.trans.shared.b16 {%0,%1,%2,%3}, [%4];"
                 : "=r"(r[0]), "=r"(r[1]), "=r"(r[2]), "=r"(r[3]) : "r"(a));
}
// fp16 mma, f32 accumulate. Non-volatile: pure register op.
__device__ __forceinline__ void mma16(float c[4], const uint32_t a[4], uint32_t b0, uint32_t b1) {
    asm("mma.sync.aligned.m16n8k16.row.col.f32.f16.f16.f32 "
        "{%0,%1,%2,%3}, {%4,%5,%6,%7}, {%8,%9}, {%0,%1,%2,%3};"
        : "+f"(c[0]), "+f"(c[1]), "+f"(c[2]), "+f"(c[3])
        : "r"(a[0]), "r"(a[1]), "r"(a[2]), "r"(a[3]), "r"(b0), "r"(b1));
}

__device__ __forceinline__ void cpa16(uint32_t d, const void* s) {
    asm volatile("cp.async.cg.shared.global [%0], [%1], 16;" :: "r"(d), "l"(s) : "memory");
}
#define CPA_COMMIT() asm volatile("cp.async.commit_group;" ::: "memory")
#define CPA_WAIT1()  asm volatile("cp.async.wait_group 1;" ::: "memory")
#define CPA_WAIT0()  asm volatile("cp.async.wait_group 0;" ::: "memory")

#define LOG2E_F 1.4426950408889634f

// ---------------------------------------------------------------------------
// SIMT projection GEMM (near FFMA roofline) with fp16 scatter epilogues.
// mode 0: Q -> g_qh single fp16 (both halves, +pos_bias_u/v, *0.125)
// mode 1: K -> g_k{h,l}[.. 0:64] fp16 hi/lo
// mode 2: V -> g_v{h,l} fp16 hi/lo
// mode 3: P -> g_k{h,l}[.. 64:128] for all 4 batches (M=2048, no bias)
// mode 4: OUT: A = g_ao, C = d_out (fp32)
// ---------------------------------------------------------------------------
__device__ __forceinline__ void fma16(float acc[4][4], float4 a, float4 b) {
    acc[0][0] += a.x*b.x; acc[0][1] += a.x*b.y; acc[0][2] += a.x*b.z; acc[0][3] += a.x*b.w;
    acc[1][0] += a.y*b.x; acc[1][1] += a.y*b.y; acc[1][2] += a.y*b.z; acc[1][3] += a.y*b.w;
    acc[2][0] += a.z*b.x; acc[2][1] += a.z*b.y; acc[2][2] += a.z*b.z; acc[2][3] += a.z*b.w;
    acc[3][0] += a.w*b.x; acc[3][1] += a.w*b.y; acc[3][2] += a.w*b.z; acc[3][3] += a.w*b.w;
}

__device__ __forceinline__ void split4h(const float v[4], uint2& hi, uint2& lo) {
    uint32_t h0 = pack2h(v[0], v[1]);
    uint32_t h1 = pack2h(v[2], v[3]);
    float2 f0 = __half22float2(*reinterpret_cast<__half2*>(&h0));
    float2 f1 = __half22float2(*reinterpret_cast<__half2*>(&h1));
    hi = make_uint2(h0, h1);
    lo = make_uint2(pack2h(v[0] - f0.x, v[1] - f0.y), pack2h(v[2] - f1.x, v[3] - f1.y));
}

__global__ __launch_bounds__(256) void gemm_kernel(
    const float* __restrict__ A, const float* __restrict__ W,
    const float* __restrict__ bias, int mode,
    const float* __restrict__ pbu, const float* __restrict__ pbv,
    float* __restrict__ C)
{
    __shared__ float As[16][64];
    __shared__ float Ws[16][64];
    int tid = threadIdx.x;
    int ty = tid >> 4, tx = tid & 15;
    int m0 = blockIdx.y << 6, n0 = blockIdx.x << 6;
    int lr = tid >> 2, lc = (tid & 3) << 2;

    const float* Abase = (mode == 4) ? g_ao : A;
    const float* Ap = Abase + (size_t)(m0 + lr) * FF + lc;
    const float* Wp = W     + (size_t)(n0 + lr) * FF + lc;

    float acc[4][4] = {};

    for (int k0 = 0; k0 < FF; k0 += 16) {
        float4 av = *(const float4*)(Ap + k0);
        float4 wv = *(const float4*)(Wp + k0);
        __syncthreads();
        As[lc+0][lr] = av.x; As[lc+1][lr] = av.y; As[lc+2][lr] = av.z; As[lc+3][lr] = av.w;
        Ws[lc+0][lr] = wv.x; Ws[lc+1][lr] = wv.y; Ws[lc+2][lr] = wv.z; Ws[lc+3][lr] = wv.w;
        __syncthreads();
#pragma unroll
        for (int k = 0; k < 16; k++) {
            float4 a = *(const float4*)&As[k][ty << 2];
            float4 b = *(const float4*)&Ws[k][tx << 2];
            fma16(acc, a, b);
        }
    }

    int ncol = n0 + (tx << 2);
    int h = ncol >> 6, dd = ncol & 63;

    if (mode == 0) {
#pragma unroll
        for (int i = 0; i < 4; i++) {
            int m = m0 + (ty << 2) + i;
            int b = m >> 11, t = m & (TT - 1);
            float vu[4], vv[4];
#pragma unroll
            for (int j = 0; j < 4; j++) {
                float v = acc[i][j] + bias[ncol + j];
                vu[j] = (v + pbu[ncol + j]) * 0.125f;
                vv[j] = (v + pbv[ncol + j]) * 0.125f;
            }
            size_t base = ((size_t)(b * HH + h) * TT + t) * 128 + dd;
            *(uint2*)(G_QH + base)      = make_uint2(pack2h(vu[0], vu[1]), pack2h(vu[2], vu[3]));
            *(uint2*)(G_QH + base + 64) = make_uint2(pack2h(vv[0], vv[1]), pack2h(vv[2], vv[3]));
        }
    } else if (mode == 1) {
#pragma unroll
        for (int i = 0; i < 4; i++) {
            int m = m0 + (ty << 2) + i;
            int b = m >> 11, t = m & (TT - 1);
            float vk[4];
#pragma unroll
            for (int j = 0; j < 4; j++) vk[j] = acc[i][j] + bias[ncol + j];
            size_t base = ((size_t)(b * HH + h) * TT + t) * 128 + dd;
            uint2 hi, lo;
            split4h(vk, hi, lo);
            *(uint2*)(G_KH + base) = hi; *(uint2*)(G_KL + base) = lo;
        }
    } else if (mode == 2) {
#pragma unroll
        for (int i = 0; i < 4; i++) {
            int m = m0 + (ty << 2) + i;
            int b = m >> 11, t = m & (TT - 1);
            float vk[4];
#pragma unroll
            for (int j = 0; j < 4; j++) vk[j] = acc[i][j] + bias[ncol + j];
            size_t base = ((size_t)(b * HH + h) * TT + t) * 64 + dd;
            uint2 hi, lo;
            split4h(vk, hi, lo);
            *(uint2*)(G_VH + base) = hi; *(uint2*)(G_VL + base) = lo;
        }
    } else if (mode == 3) {
#pragma unroll
        for (int i = 0; i < 4; i++) {
            int t = m0 + (ty << 2) + i;   // m is t (0..2047)
            float vp[4];
#pragma unroll
            for (int j = 0; j < 4; j++) vp[j] = acc[i][j];
            uint2 hi, lo;
            split4h(vp, hi, lo);
#pragma unroll
            for (int bb = 0; bb < BB; bb++) {
                size_t base = ((size_t)(bb * HH + h) * TT + t) * 128 + 64 + dd;
                *(uint2*)(G_KH + base) = hi; *(uint2*)(G_KL + base) = lo;
            }
        }
    } else {
#pragma unroll
        for (int i = 0; i < 4; i++) {
            int m = m0 + (ty << 2) + i;
#pragma unroll
            for (int j = 0; j < 4; j++) {
                int n = ncol + j;
                C[(size_t)m * FF + n] = acc[i][j] + bias[n];
            }
        }
    }
}

// ---------------------------------------------------------------------------
// fp16 mma.sync flash attention with ONLINE softmax.
// Q single fp16; K = Kh+Kl (2-term); P single fp16; V = Vh+Vl (2-term).
// Key-split via blockIdx.z; partials (O, l, m) merged by combine_kernel.
// ---------------------------------------------------------------------------
#define KSTR 272     // K/Q smem row stride bytes (128 f16 + 16B pad)
#define VSTR 144     // V smem row stride bytes (64 f16 + 16B pad)
#define SM_KH 0
#define SM_KL 34816
#define SM_VH 69632
#define SM_VL 88064
#define STAGE 106496
#define FLASH_SMEM (2*STAGE)   // 212992

__device__ __forceinline__ void copy_tile_async(uint32_t stb, int bh, int s0, int tid) {
    const uint4* kh = g_kh_ + ((size_t)bh * TT + s0) * 16;
    const uint4* kl = g_kl_ + ((size_t)bh * TT + s0) * 16;
#pragma unroll
    for (int i = 0; i < 8; i++) {
        int idx = tid + i * 256;
        int r = idx >> 4, c = idx & 15;
        cpa16(stb + SM_KH + r * KSTR + c * 16, kh + r * 16 + c);
        cpa16(stb + SM_KL + r * KSTR + c * 16, kl + r * 16 + c);
    }
    const uint4* vh = g_vh_ + ((size_t)bh * TT + s0) * 8;
    const uint4* vl = g_vl_ + ((size_t)bh * TT + s0) * 8;
#pragma unroll
    for (int i = 0; i < 4; i++) {
        int idx = tid + i * 256;
        int r = idx >> 3, c = idx & 7;
        cpa16(stb + SM_VH + r * VSTR + c * 16, vh + r * 8 + c);
        cpa16(stb + SM_VL + r * VSTR + c * 16, vl + r * 8 + c);
    }
}

__global__ __launch_bounds__(256) void flash_kernel()
{
    extern __shared__ char sm[];
    uint32_t sb = cvta_s(sm);

    int tid = threadIdx.x;
    int w = tid >> 5, l = tid & 31;
    int bh = blockIdx.y;
    int b = bh >> 3, h = bh & 7;
    int t0 = blockIdx.x << 7;
    int z  = blockIdx.z;
    int kbase = z << 10;          // key range [kbase, kbase+1024)

    // ---- prologue: Q (single fp16, 32KB) -> stage1, tile0 -> stage0 ----
    {
        uint32_t qb = sb + STAGE;
        const uint4* qh = g_qh_ + ((size_t)bh * TT + t0) * 16;
#pragma unroll
        for (int i = 0; i < 8; i++) {
            int idx = tid + i * 256;
            int r = idx >> 4, c = idx & 15;
            cpa16(qb + SM_KH + r * KSTR + c * 16, qh + r * 16 + c);
        }
        CPA_COMMIT();
        copy_tile_async(sb, bh, kbase, tid);
        CPA_COMMIT();
    }
    CPA_WAIT1();           // Q landed
    __syncthreads();

    // ---- frag Q (16 rows per warp, full d=128) ----
    uint32_t Qf[8][4];
    {
        uint32_t rowa = sb + STAGE + (16 * w + (l & 15)) * KSTR + (l >> 4) * 16;
#pragma unroll
        for (int ks = 0; ks < 8; ks++) ldsm4(Qf[ks], rowa + SM_KH + ks * 32);
    }

    float O[8][4];
#pragma unroll
    for (int i = 0; i < 8; i++)
#pragma unroll
        for (int j = 0; j < 4; j++) O[i][j] = 0.f;
    float l_0 = 0.f, l_1 = 0.f;
    float m_0 = -1e30f, m_1 = -1e30f;

    uint32_t kB_rel = (l & 7) * KSTR + (l >> 3) * 16;
    uint32_t vB_rel = ((l & 7) + ((l >> 3) & 1) * 8) * VSTR + (l >> 4) * 16;

    for (int it = 0; it < 8; ++it) {
        __syncthreads();
        if (it < 7) {
            copy_tile_async(sb + ((it + 1) & 1) * STAGE, bh, kbase + ((it + 1) << 7), tid);
            CPA_COMMIT();
            CPA_WAIT1();
        } else {
            CPA_WAIT0();
        }
        __syncthreads();

        uint32_t stb = sb + (it & 1) * STAGE;
        uint32_t kB_lane = stb + kB_rel;
        uint32_t vB_lane = stb + vB_rel;

#pragma unroll
        for (int kb = 0; kb < 8; kb++) {
            // ---- S for 16 keys, d=128: Q*(Kh+Kl), B frags double-buffered ----
            float S0A[4] = {0.f,0.f,0.f,0.f}, S0B[4] = {0.f,0.f,0.f,0.f};
            float S1A[4] = {0.f,0.f,0.f,0.f}, S1B[4] = {0.f,0.f,0.f,0.f};
            uint32_t r0a = kB_lane + (16 * kb) * KSTR;
            uint32_t r1a = r0a + 8 * KSTR;

            uint32_t Bh0[2][4], Bl0[2][4], Bh1[2][4], Bl1[2][4];
            ldsm4(Bh0[0], r0a + SM_KH); ldsm4(Bl0[0], r0a + SM_KL);
            ldsm4(Bh1[0], r1a + SM_KH); ldsm4(Bl1[0], r1a + SM_KL);
#pragma unroll
            for (int j = 0; j < 4; j++) {
                int cur = j & 1, nxt = cur ^ 1;
                if (j < 3) {
                    ldsm4(Bh0[nxt], r0a + SM_KH + (j + 1) * 64);
                    ldsm4(Bl0[nxt], r0a + SM_KL + (j + 1) * 64);
                    ldsm4(Bh1[nxt], r1a + SM_KH + (j + 1) * 64);
                    ldsm4(Bl1[nxt], r1a + SM_KL + (j + 1) * 64);
                }
                mma16(S0A, Qf[2*j],   Bh0[cur][0], Bh0[cur][1]);
                mma16(S1A, Qf[2*j],   Bh1[cur][0], Bh1[cur][1]);
                mma16(S0B, Qf[2*j+1], Bh0[cur][2], Bh0[cur][3]);
                mma16(S1B, Qf[2*j+1], Bh1[cur][2], Bh1[cur][3]);
                mma16(S0A, Qf[2*j],   Bl0[cur][0], Bl0[cur][1]);
                mma16(S1A, Qf[2*j],   Bl1[cur][0], Bl1[cur][1]);
                mma16(S0B, Qf[2*j+1], Bl0[cur][2], Bl0[cur][3]);
                mma16(S1B, Qf[2*j+1], Bl1[cur][2], Bl1[cur][3]);
            }

            // ---- start V frag loads (latency hidden under softmax) ----
            uint32_t va = vB_lane + (16 * kb) * VSTR;
            uint32_t Vh[2][4], Vl[2][4];
            ldsm4t(Vh[0], va + SM_VH); ldsm4t(Vl[0], va + SM_VL);

            // ---- online softmax (rows r and r+8) ----
            float s00 = S0A[0]+S0B[0], s01 = S0A[1]+S0B[1];
            float s02 = S0A[2]+S0B[2], s03 = S0A[3]+S0B[3];
            float s10 = S1A[0]+S1B[0], s11 = S1A[1]+S1B[1];
            float s12 = S1A[2]+S1B[2], s13 = S1A[3]+S1B[3];

            float mx0 = fmaxf(fmaxf(s00, s01), fmaxf(s10, s11));
            float mx1 = fmaxf(fmaxf(s02, s03), fmaxf(s12, s13));
            mx0 = fmaxf(mx0, __shfl_xor_sync(0xffffffffu, mx0, 1));
            mx0 = fmaxf(mx0, __shfl_xor_sync(0xffffffffu, mx0, 2));
            mx1 = fmaxf(mx1, __shfl_xor_sync(0xffffffffu, mx1, 1));
            mx1 = fmaxf(mx1, __shfl_xor_sync(0xffffffffu, mx1, 2));
            float mn0 = fmaxf(m_0, mx0), mn1 = fmaxf(m_1, mx1);
            float c0 = ex2f((m_0 - mn0) * LOG2E_F);
            float c1 = ex2f((m_1 - mn1) * LOG2E_F);
            m_0 = mn0; m_1 = mn1;

            float p00 = ex2f((s00 - mn0) * LOG2E_F);
            float p01 = ex2f((s01 - mn0) * LOG2E_F);
            float p10 = ex2f((s10 - mn0) * LOG2E_F);
            float p11 = ex2f((s11 - mn0) * LOG2E_F);
            float p02 = ex2f((s02 - mn1) * LOG2E_F);
            float p03 = ex2f((s03 - mn1) * LOG2E_F);
            float p12 = ex2f((s12 - mn1) * LOG2E_F);
            float p13 = ex2f((s13 - mn1) * LOG2E_F);
            l_0 = l_0 * c0 + ((p00 + p01) + (p10 + p11));
            l_1 = l_1 * c1 + ((p02 + p03) + (p12 + p13));
#pragma unroll
            for (int nd = 0; nd < 8; nd++) {
                O[nd][0] *= c0; O[nd][1] *= c0;
                O[nd][2] *= c1; O[nd][3] *= c1;
            }

            uint32_t P[4];
            P[0] = pack2h(p00, p01);
            P[1] = pack2h(p02, p03);
            P[2] = pack2h(p10, p11);
            P[3] = pack2h(p12, p13);

            // ---- O += P*(Vh+Vl), V frags double-buffered ----
#pragma unroll
            for (int nd = 0; nd < 4; nd++) {
                int cur = nd & 1, nxt = cur ^ 1;
                if (nd < 3) {
                    ldsm4t(Vh[nxt], va + SM_VH + (nd + 1) * 32);
                    ldsm4t(Vl[nxt], va + SM_VL + (nd + 1) * 32);
                }
                mma16(O[2*nd],   P, Vh[cur][0], Vh[cur][1]);
                mma16(O[2*nd+1], P, Vh[cur][2], Vh[cur][3]);
                mma16(O[2*nd],   P, Vl[cur][0], Vl[cur][1]);
                mma16(O[2*nd+1], P, Vl[cur][2], Vl[cur][3]);
            }
        }
    }

    // ---- reduce row sums across quads, write partials (O, l, m) ----
    l_0 += __shfl_xor_sync(0xffffffffu, l_0, 1);
    l_0 += __shfl_xor_sync(0xffffffffu, l_0, 2);
    l_1 += __shfl_xor_sync(0xffffffffu, l_1, 1);
    l_1 += __shfl_xor_sync(0xffffffffu, l_1, 2);

    float* po = z ? g_po1 : g_po0;
    float* ls = z ? g_ls1 : g_ls0;
    float* lm = z ? g_lm1 : g_lm0;

    int row0 = t0 + 16 * w + (l >> 2);
    if ((l & 3) == 0) {
        ls[bh * TT + row0] = l_0;      lm[bh * TT + row0] = m_0;
        ls[bh * TT + row0 + 8] = l_1;  lm[bh * TT + row0 + 8] = m_1;
    }
    float* d0 = po + ((size_t)(b * TT + row0)) * FF + (h << 6) + ((l & 3) << 1);
    float* d1 = d0 + (size_t)8 * FF;
#pragma unroll
    for (int nd = 0; nd < 8; nd++) {
        *(float2*)(d0 + nd * 8) = make_float2(O[nd][0], O[nd][1]);
        *(float2*)(d1 + nd * 8) = make_float2(O[nd][2], O[nd][3]);
    }
}

// ---------------------------------------------------------------------------
// combine partial halves with (m,l) merge -> normalized g_ao
// ---------------------------------------------------------------------------
__global__ __launch_bounds__(256) void combine_kernel()
{
    int idx = blockIdx.x * 256 + threadIdx.x;   // float4 units over MM*FF
    int m = idx >> 7;
    int c = (idx & 127) << 2;
    int h = c >> 6;
    int b = m >> 11, t = m & (TT - 1);
    int r = (b * HH + h) * TT + t;
    float m0 = g_lm0[r], m1 = g_lm1[r];
    float M = fmaxf(m0, m1);
    float w0 = ex2f((m0 - M) * LOG2E_F);
    float w1 = ex2f((m1 - M) * LOG2E_F);
    float inv = 1.f / (g_ls0[r] * w0 + g_ls1[r] * w1);
    float4 o0 = *(const float4*)(g_po0 + (size_t)idx * 4);
    float4 o1 = *(const float4*)(g_po1 + (size_t)idx * 4);
    *(float4*)(g_ao + (size_t)idx * 4) =
        make_float4((o0.x * w0 + o1.x * w1) * inv, (o0.y * w0 + o1.y * w1) * inv,
                    (o0.z * w0 + o1.z * w1) * inv, (o0.w * w0 + o1.w * w1) * inv);
}

// ---------------------------------------------------------------------------
extern "C" void kernel_launch(void* const* d_in, const int* in_sizes, int n_in,
                              void* d_out, int out_size)
{
    const float* x    = (const float*)d_in[0];
    const float* pe   = (const float*)d_in[1];
    const float* Wq   = (const float*)d_in[2];
    const float* bq   = (const float*)d_in[3];
    const float* Wk   = (const float*)d_in[4];
    const float* bk   = (const float*)d_in[5];
    const float* Wv   = (const float*)d_in[6];
    const float* bv   = (const float*)d_in[7];
    const float* Wpos = (const float*)d_in[8];
    const float* Wout = (const float*)d_in[9];
    const float* bout = (const float*)d_in[10];
    const float* pbu  = (const float*)d_in[11];
    const float* pbv  = (const float*)d_in[12];
    float* out = (float*)d_out;

    cudaFuncSetAttribute(flash_kernel, cudaFuncAttributeMaxDynamicSharedMemorySize, FLASH_SMEM);

    dim3 blk(256);
    gemm_kernel<<<dim3(8, 128), blk>>>(x,  Wq, bq, 0, pbu, pbv, nullptr);
    gemm_kernel<<<dim3(8, 128), blk>>>(x,  Wk, bk, 1, nullptr, nullptr, nullptr);
    gemm_kernel<<<dim3(8, 128), blk>>>(x,  Wv, bv, 2, nullptr, nullptr, nullptr);
    gemm_kernel<<<dim3(8, 32),  blk>>>(pe, Wpos, nullptr, 3, nullptr, nullptr, nullptr);
    flash_kernel<<<dim3(TT / 128, BB * HH, 2), blk, FLASH_SMEM>>>();
    combine_kernel<<<dim3((MM * FF) / 1024), blk>>>();
    gemm_kernel<<<dim3(8, 128), blk>>>(nullptr, Wout, bout, 4, nullptr, nullptr, out);
}

// round 7
// speedup vs baseline: 2.4032x; 1.0857x over previous
#include <cuda_runtime.h>
#include <cuda_bf16.h>
#include <cuda_fp16.h>
#include <cstdint>

#define BB 4
#define TT 2048
#define HH 8
#define FF 512
#define MM (BB*TT)   // 8192
#define NZ 4         // key-split factor

// ---------------------------------------------------------------------------
// Global scratch (device globals; uint4 for 16B alignment)
// ---------------------------------------------------------------------------
__device__ uint4 g_qh_[1048576];   // q_cat fp16 (single): [bh=32][t=2048][128] (scaled 0.125, biases fused)
__device__ uint4 g_kh_[1048576];   // k_cat hi fp16: [bh][t][0:64]=k, [64:128]=p
__device__ uint4 g_kl_[1048576];   // k_cat lo fp16
__device__ uint4 g_vh_[524288];    // V hi fp16: [bh][t][64]
__device__ uint4 g_vl_[524288];    // V lo fp16
__device__ float g_po[(size_t)NZ*MM*FF];  // partial O per z, unnormalized
__device__ float g_ls[NZ*32*TT];          // partial row sums
__device__ float g_lm[NZ*32*TT];          // partial row maxes
__device__ float g_ao[(size_t)MM*FF];     // combined attention out

#define G_QH ((__half*)g_qh_)
#define G_KH ((__half*)g_kh_)
#define G_KL ((__half*)g_kl_)
#define G_VH ((__half*)g_vh_)
#define G_VL ((__half*)g_vl_)

// ---------------------------------------------------------------------------
__device__ __forceinline__ uint32_t cvta_s(const void* p) {
    return (uint32_t)__cvta_generic_to_shared(p);
}
__device__ __forceinline__ float ex2f(float x) {
    float r; asm("ex2.approx.ftz.f32 %0, %1;" : "=f"(r) : "f"(x)); return r;
}
// pack two f32 -> f16x2 word: first arg -> low half, second -> high half
__device__ __forceinline__ uint32_t pack2h(float lo, float hi) {
    uint32_t r; asm("cvt.rn.f16x2.f32 %0, %1, %2;" : "=r"(r) : "f"(hi), "f"(lo)); return r;
}

__device__ __forceinline__ void ldsm4(uint32_t r[4], uint32_t a) {
    asm volatile("ldmatrix.sync.aligned.m8n8.x4.shared.b16 {%0,%1,%2,%3}, [%4];"
                 : "=r"(r[0]), "=r"(r[1]), "=r"(r[2]), "=r"(r[3]) : "r"(a));
}
__device__ __forceinline__ void ldsm4t(uint32_t r[4], uint32_t a) {
    asm volatile("ldmatrix.sync.aligned.m8n8.x4.trans.shared.b16 {%0,%1,%2,%3}, [%4];"
                 : "=r"(r[0]), "=r"(r[1]), "=r"(r[2]), "=r"(r[3]) : "r"(a));
}
// fp16 mma, f32 accumulate. Non-volatile: pure register op.
__device__ __forceinline__ void mma16(float c[4], const uint32_t a[4], uint32_t b0, uint32_t b1) {
    asm("mma.sync.aligned.m16n8k16.row.col.f32.f16.f16.f32 "
        "{%0,%1,%2,%3}, {%4,%5,%6,%7}, {%8,%9}, {%0,%1,%2,%3};"
        : "+f"(c[0]), "+f"(c[1]), "+f"(c[2]), "+f"(c[3])
        : "r"(a[0]), "r"(a[1]), "r"(a[2]), "r"(a[3]), "r"(b0), "r"(b1));
}

__device__ __forceinline__ void cpa16(uint32_t d, const void* s) {
    asm volatile("cp.async.cg.shared.global [%0], [%1], 16;" :: "r"(d), "l"(s) : "memory");
}
#define CPA_COMMIT() asm volatile("cp.async.commit_group;" ::: "memory")
#define CPA_WAIT1()  asm volatile("cp.async.wait_group 1;" ::: "memory")
#define CPA_WAIT0()  asm volatile("cp.async.wait_group 0;" ::: "memory")

#define LOG2E_F 1.4426950408889634f

// ---------------------------------------------------------------------------
// SIMT projection GEMM (near FFMA roofline) with fp16 scatter epilogues.
// mode 0: Q -> g_qh single fp16 (both halves, +pos_bias_u/v, *0.125)
// mode 1: K -> g_k{h,l}[.. 0:64] fp16 hi/lo
// mode 2: V -> g_v{h,l} fp16 hi/lo
// mode 3: P -> g_k{h,l}[.. 64:128] for all 4 batches (M=2048, no bias)
// mode 4: OUT: A = g_ao, C = d_out (fp32)
// ---------------------------------------------------------------------------
__device__ __forceinline__ void fma16(float acc[4][4], float4 a, float4 b) {
    acc[0][0] += a.x*b.x; acc[0][1] += a.x*b.y; acc[0][2] += a.x*b.z; acc[0][3] += a.x*b.w;
    acc[1][0] += a.y*b.x; acc[1][1] += a.y*b.y; acc[1][2] += a.y*b.z; acc[1][3] += a.y*b.w;
    acc[2][0] += a.z*b.x; acc[2][1] += a.z*b.y; acc[2][2] += a.z*b.z; acc[2][3] += a.z*b.w;
    acc[3][0] += a.w*b.x; acc[3][1] += a.w*b.y; acc[3][2] += a.w*b.z; acc[3][3] += a.w*b.w;
}

__device__ __forceinline__ void split4h(const float v[4], uint2& hi, uint2& lo) {
    uint32_t h0 = pack2h(v[0], v[1]);
    uint32_t h1 = pack2h(v[2], v[3]);
    float2 f0 = __half22float2(*reinterpret_cast<__half2*>(&h0));
    float2 f1 = __half22float2(*reinterpret_cast<__half2*>(&h1));
    hi = make_uint2(h0, h1);
    lo = make_uint2(pack2h(v[0] - f0.x, v[1] - f0.y), pack2h(v[2] - f1.x, v[3] - f1.y));
}

__global__ __launch_bounds__(256) void gemm_kernel(
    const float* __restrict__ A, const float* __restrict__ W,
    const float* __restrict__ bias, int mode,
    const float* __restrict__ pbu, const float* __restrict__ pbv,
    float* __restrict__ C)
{
    __shared__ float As[16][64];
    __shared__ float Ws[16][64];
    int tid = threadIdx.x;
    int ty = tid >> 4, tx = tid & 15;
    int m0 = blockIdx.y << 6, n0 = blockIdx.x << 6;
    int lr = tid >> 2, lc = (tid & 3) << 2;

    const float* Abase = (mode == 4) ? g_ao : A;
    const float* Ap = Abase + (size_t)(m0 + lr) * FF + lc;
    const float* Wp = W     + (size_t)(n0 + lr) * FF + lc;

    float acc[4][4] = {};

    for (int k0 = 0; k0 < FF; k0 += 16) {
        float4 av = *(const float4*)(Ap + k0);
        float4 wv = *(const float4*)(Wp + k0);
        __syncthreads();
        As[lc+0][lr] = av.x; As[lc+1][lr] = av.y; As[lc+2][lr] = av.z; As[lc+3][lr] = av.w;
        Ws[lc+0][lr] = wv.x; Ws[lc+1][lr] = wv.y; Ws[lc+2][lr] = wv.z; Ws[lc+3][lr] = wv.w;
        __syncthreads();
#pragma unroll
        for (int k = 0; k < 16; k++) {
            float4 a = *(const float4*)&As[k][ty << 2];
            float4 b = *(const float4*)&Ws[k][tx << 2];
            fma16(acc, a, b);
        }
    }

    int ncol = n0 + (tx << 2);
    int h = ncol >> 6, dd = ncol & 63;

    if (mode == 0) {
#pragma unroll
        for (int i = 0; i < 4; i++) {
            int m = m0 + (ty << 2) + i;
            int b = m >> 11, t = m & (TT - 1);
            float vu[4], vv[4];
#pragma unroll
            for (int j = 0; j < 4; j++) {
                float v = acc[i][j] + bias[ncol + j];
                vu[j] = (v + pbu[ncol + j]) * 0.125f;
                vv[j] = (v + pbv[ncol + j]) * 0.125f;
            }
            size_t base = ((size_t)(b * HH + h) * TT + t) * 128 + dd;
            *(uint2*)(G_QH + base)      = make_uint2(pack2h(vu[0], vu[1]), pack2h(vu[2], vu[3]));
            *(uint2*)(G_QH + base + 64) = make_uint2(pack2h(vv[0], vv[1]), pack2h(vv[2], vv[3]));
        }
    } else if (mode == 1) {
#pragma unroll
        for (int i = 0; i < 4; i++) {
            int m = m0 + (ty << 2) + i;
            int b = m >> 11, t = m & (TT - 1);
            float vk[4];
#pragma unroll
            for (int j = 0; j < 4; j++) vk[j] = acc[i][j] + bias[ncol + j];
            size_t base = ((size_t)(b * HH + h) * TT + t) * 128 + dd;
            uint2 hi, lo;
            split4h(vk, hi, lo);
            *(uint2*)(G_KH + base) = hi; *(uint2*)(G_KL + base) = lo;
        }
    } else if (mode == 2) {
#pragma unroll
        for (int i = 0; i < 4; i++) {
            int m = m0 + (ty << 2) + i;
            int b = m >> 11, t = m & (TT - 1);
            float vk[4];
#pragma unroll
            for (int j = 0; j < 4; j++) vk[j] = acc[i][j] + bias[ncol + j];
            size_t base = ((size_t)(b * HH + h) * TT + t) * 64 + dd;
            uint2 hi, lo;
            split4h(vk, hi, lo);
            *(uint2*)(G_VH + base) = hi; *(uint2*)(G_VL + base) = lo;
        }
    } else if (mode == 3) {
#pragma unroll
        for (int i = 0; i < 4; i++) {
            int t = m0 + (ty << 2) + i;   // m is t (0..2047)
            float vp[4];
#pragma unroll
            for (int j = 0; j < 4; j++) vp[j] = acc[i][j];
            uint2 hi, lo;
            split4h(vp, hi, lo);
#pragma unroll
            for (int bb = 0; bb < BB; bb++) {
                size_t base = ((size_t)(bb * HH + h) * TT + t) * 128 + 64 + dd;
                *(uint2*)(G_KH + base) = hi; *(uint2*)(G_KL + base) = lo;
            }
        }
    } else {
#pragma unroll
        for (int i = 0; i < 4; i++) {
            int m = m0 + (ty << 2) + i;
#pragma unroll
            for (int j = 0; j < 4; j++) {
                int n = ncol + j;
                C[(size_t)m * FF + n] = acc[i][j] + bias[n];
            }
        }
    }
}

// ---------------------------------------------------------------------------
// fp16 mma.sync flash attention, ONLINE softmax, 2 CTAs/SM (4 warps/SMSP).
// 64-key tiles, double-buffered cp.async. Q single fp16; K/V 2-term fp16.
// Key-split z in [0,4); partials merged by combine_kernel.
// ---------------------------------------------------------------------------
#define KSTR 272     // K/Q smem row stride bytes (128 f16 + 16B pad)
#define VSTR 144     // V smem row stride bytes (64 f16 + 16B pad)
#define SM_KH 0
#define SM_KL 17408
#define SM_VH 34816
#define SM_VL 44032
#define STAGE 53248
#define FLASH_SMEM (2*STAGE)   // 106496 -> 2 CTAs/SM

// 64-key tile copy: K hi/lo 64x128 f16, V hi/lo 64x64 f16
__device__ __forceinline__ void copy_tile_async(uint32_t stb, int bh, int s0, int tid) {
    const uint4* kh = g_kh_ + ((size_t)bh * TT + s0) * 16;
    const uint4* kl = g_kl_ + ((size_t)bh * TT + s0) * 16;
#pragma unroll
    for (int i = 0; i < 4; i++) {
        int idx = tid + i * 256;          // 1024 uint4 per buffer
        int r = idx >> 4, c = idx & 15;
        cpa16(stb + SM_KH + r * KSTR + c * 16, kh + r * 16 + c);
        cpa16(stb + SM_KL + r * KSTR + c * 16, kl + r * 16 + c);
    }
    const uint4* vh = g_vh_ + ((size_t)bh * TT + s0) * 8;
    const uint4* vl = g_vl_ + ((size_t)bh * TT + s0) * 8;
#pragma unroll
    for (int i = 0; i < 2; i++) {
        int idx = tid + i * 256;          // 512 uint4 per buffer
        int r = idx >> 3, c = idx & 7;
        cpa16(stb + SM_VH + r * VSTR + c * 16, vh + r * 8 + c);
        cpa16(stb + SM_VL + r * VSTR + c * 16, vl + r * 8 + c);
    }
}

__global__ __launch_bounds__(256, 2) void flash_kernel()
{
    extern __shared__ char sm[];
    uint32_t sb = cvta_s(sm);

    int tid = threadIdx.x;
    int w = tid >> 5, l = tid & 31;
    int bh = blockIdx.y;
    int b = bh >> 3, h = bh & 7;
    int t0 = blockIdx.x << 7;
    int z  = blockIdx.z;
    int kbase = z << 9;           // key range [kbase, kbase+512)

    // ---- prologue: Q (128 rows, 34.8KB) -> stage1; tile0 -> stage0 ----
    {
        uint32_t qb = sb + STAGE;
        const uint4* qh = g_qh_ + ((size_t)bh * TT + t0) * 16;
#pragma unroll
        for (int i = 0; i < 8; i++) {
            int idx = tid + i * 256;
            int r = idx >> 4, c = idx & 15;
            cpa16(qb + r * KSTR + c * 16, qh + r * 16 + c);
        }
        CPA_COMMIT();
        copy_tile_async(sb, bh, kbase, tid);
        CPA_COMMIT();
    }
    CPA_WAIT1();           // Q landed (tile0 may be in flight)
    __syncthreads();

    // ---- frag Q from stage1 (16 rows per warp, full d=128) ----
    uint32_t Qf[8][4];
    {
        uint32_t rowa = sb + STAGE + (16 * w + (l & 15)) * KSTR + (l >> 4) * 16;
#pragma unroll
        for (int ks = 0; ks < 8; ks++) ldsm4(Qf[ks], rowa + ks * 32);
    }

    float O[8][4];
#pragma unroll
    for (int i = 0; i < 8; i++)
#pragma unroll
        for (int j = 0; j < 4; j++) O[i][j] = 0.f;
    float l_0 = 0.f, l_1 = 0.f;
    float m_0 = -1e30f, m_1 = -1e30f;

    uint32_t kB_rel = (l & 7) * KSTR + (l >> 3) * 16;
    uint32_t vB_rel = ((l & 7) + ((l >> 3) & 1) * 8) * VSTR + (l >> 4) * 16;

    for (int it = 0; it < 8; ++it) {
        __syncthreads();   // all warps done with the stage the prefetch will overwrite
        if (it < 7) {
            copy_tile_async(sb + ((it + 1) & 1) * STAGE, bh, kbase + ((it + 1) << 6), tid);
            CPA_COMMIT();
            CPA_WAIT1();   // tile `it` complete
        } else {
            CPA_WAIT0();
        }
        __syncthreads();   // tile `it` visible

        uint32_t stb = sb + (it & 1) * STAGE;
        uint32_t kB_lane = stb + kB_rel;
        uint32_t vB_lane = stb + vB_rel;

#pragma unroll
        for (int kb = 0; kb < 4; kb++) {
            // ---- S for 16 keys, d=128: Q*(Kh+Kl) ----
            float S0A[4] = {0.f,0.f,0.f,0.f}, S0B[4] = {0.f,0.f,0.f,0.f};
            float S1A[4] = {0.f,0.f,0.f,0.f}, S1B[4] = {0.f,0.f,0.f,0.f};
            uint32_t r0a = kB_lane + (16 * kb) * KSTR;
            uint32_t r1a = r0a + 8 * KSTR;
#pragma unroll
            for (int j = 0; j < 4; j++) {
                uint32_t Bh0[4], Bl0[4], Bh1[4], Bl1[4];
                ldsm4(Bh0, r0a + SM_KH + j * 64);
                ldsm4(Bl0, r0a + SM_KL + j * 64);
                ldsm4(Bh1, r1a + SM_KH + j * 64);
                ldsm4(Bl1, r1a + SM_KL + j * 64);
                mma16(S0A, Qf[2*j],   Bh0[0], Bh0[1]);
                mma16(S1A, Qf[2*j],   Bh1[0], Bh1[1]);
                mma16(S0B, Qf[2*j+1], Bh0[2], Bh0[3]);
                mma16(S1B, Qf[2*j+1], Bh1[2], Bh1[3]);
                mma16(S0A, Qf[2*j],   Bl0[0], Bl0[1]);
                mma16(S1A, Qf[2*j],   Bl1[0], Bl1[1]);
                mma16(S0B, Qf[2*j+1], Bl0[2], Bl0[3]);
                mma16(S1B, Qf[2*j+1], Bl1[2], Bl1[3]);
            }

            // ---- online softmax (rows r and r+8) ----
            float s00 = S0A[0]+S0B[0], s01 = S0A[1]+S0B[1];
            float s02 = S0A[2]+S0B[2], s03 = S0A[3]+S0B[3];
            float s10 = S1A[0]+S1B[0], s11 = S1A[1]+S1B[1];
            float s12 = S1A[2]+S1B[2], s13 = S1A[3]+S1B[3];

            float mx0 = fmaxf(fmaxf(s00, s01), fmaxf(s10, s11));
            float mx1 = fmaxf(fmaxf(s02, s03), fmaxf(s12, s13));
            mx0 = fmaxf(mx0, __shfl_xor_sync(0xffffffffu, mx0, 1));
            mx0 = fmaxf(mx0, __shfl_xor_sync(0xffffffffu, mx0, 2));
            mx1 = fmaxf(mx1, __shfl_xor_sync(0xffffffffu, mx1, 1));
            mx1 = fmaxf(mx1, __shfl_xor_sync(0xffffffffu, mx1, 2));
            float mn0 = fmaxf(m_0, mx0), mn1 = fmaxf(m_1, mx1);
            float c0 = ex2f((m_0 - mn0) * LOG2E_F);
            float c1 = ex2f((m_1 - mn1) * LOG2E_F);
            m_0 = mn0; m_1 = mn1;

            float p00 = ex2f((s00 - mn0) * LOG2E_F);
            float p01 = ex2f((s01 - mn0) * LOG2E_F);
            float p10 = ex2f((s10 - mn0) * LOG2E_F);
            float p11 = ex2f((s11 - mn0) * LOG2E_F);
            float p02 = ex2f((s02 - mn1) * LOG2E_F);
            float p03 = ex2f((s03 - mn1) * LOG2E_F);
            float p12 = ex2f((s12 - mn1) * LOG2E_F);
            float p13 = ex2f((s13 - mn1) * LOG2E_F);
            l_0 = l_0 * c0 + ((p00 + p01) + (p10 + p11));
            l_1 = l_1 * c1 + ((p02 + p03) + (p12 + p13));
#pragma unroll
            for (int nd = 0; nd < 8; nd++) {
                O[nd][0] *= c0; O[nd][1] *= c0;
                O[nd][2] *= c1; O[nd][3] *= c1;
            }

            uint32_t P[4];
            P[0] = pack2h(p00, p01);
            P[1] = pack2h(p02, p03);
            P[2] = pack2h(p10, p11);
            P[3] = pack2h(p12, p13);

            // ---- O += P*(Vh+Vl) ----
            uint32_t va = vB_lane + (16 * kb) * VSTR;
#pragma unroll
            for (int nd = 0; nd < 4; nd++) {
                uint32_t Vh[4], Vl[4];
                ldsm4t(Vh, va + SM_VH + nd * 32);
                ldsm4t(Vl, va + SM_VL + nd * 32);
                mma16(O[2*nd],   P, Vh[0], Vh[1]);
                mma16(O[2*nd+1], P, Vh[2], Vh[3]);
                mma16(O[2*nd],   P, Vl[0], Vl[1]);
                mma16(O[2*nd+1], P, Vl[2], Vl[3]);
            }
        }
    }

    // ---- reduce row sums across quads, write partials (O, l, m) ----
    l_0 += __shfl_xor_sync(0xffffffffu, l_0, 1);
    l_0 += __shfl_xor_sync(0xffffffffu, l_0, 2);
    l_1 += __shfl_xor_sync(0xffffffffu, l_1, 1);
    l_1 += __shfl_xor_sync(0xffffffffu, l_1, 2);

    float* po = g_po + (size_t)z * MM * FF;
    float* ls = g_ls + z * 32 * TT;
    float* lm = g_lm + z * 32 * TT;

    int row0 = t0 + 16 * w + (l >> 2);
    if ((l & 3) == 0) {
        ls[bh * TT + row0] = l_0;      lm[bh * TT + row0] = m_0;
        ls[bh * TT + row0 + 8] = l_1;  lm[bh * TT + row0 + 8] = m_1;
    }
    float* d0 = po + ((size_t)(b * TT + row0)) * FF + (h << 6) + ((l & 3) << 1);
    float* d1 = d0 + (size_t)8 * FF;
#pragma unroll
    for (int nd = 0; nd < 8; nd++) {
        *(float2*)(d0 + nd * 8) = make_float2(O[nd][0], O[nd][1]);
        *(float2*)(d1 + nd * 8) = make_float2(O[nd][2], O[nd][3]);
    }
}

// ---------------------------------------------------------------------------
// combine NZ partials with (m,l) merge -> normalized g_ao
// ---------------------------------------------------------------------------
__global__ __launch_bounds__(256) void combine_kernel()
{
    int idx = blockIdx.x * 256 + threadIdx.x;   // float4 units over MM*FF
    int m = idx >> 7;
    int c = (idx & 127) << 2;
    int h = c >> 6;
    int b = m >> 11, t = m & (TT - 1);
    int r = (b * HH + h) * TT + t;

    float mz[NZ];
    float M = -1e30f;
#pragma unroll
    for (int zz = 0; zz < NZ; zz++) { mz[zz] = g_lm[zz * 32 * TT + r]; M = fmaxf(M, mz[zz]); }
    float L = 0.f;
    float wz[NZ];
#pragma unroll
    for (int zz = 0; zz < NZ; zz++) {
        wz[zz] = ex2f((mz[zz] - M) * LOG2E_F);
        L += g_ls[zz * 32 * TT + r] * wz[zz];
    }
    float inv = 1.f / L;

    float4 acc = make_float4(0.f, 0.f, 0.f, 0.f);
#pragma unroll
    for (int zz = 0; zz < NZ; zz++) {
        float4 o = *(const float4*)(g_po + (size_t)zz * MM * FF + (size_t)idx * 4);
        acc.x += o.x * wz[zz]; acc.y += o.y * wz[zz];
        acc.z += o.z * wz[zz]; acc.w += o.w * wz[zz];
    }
    *(float4*)(g_ao + (size_t)idx * 4) =
        make_float4(acc.x * inv, acc.y * inv, acc.z * inv, acc.w * inv);
}

// ---------------------------------------------------------------------------
extern "C" void kernel_launch(void* const* d_in, const int* in_sizes, int n_in,
                              void* d_out, int out_size)
{
    const float* x    = (const float*)d_in[0];
    const float* pe   = (const float*)d_in[1];
    const float* Wq   = (const float*)d_in[2];
    const float* bq   = (const float*)d_in[3];
    const float* Wk   = (const float*)d_in[4];
    const float* bk   = (const float*)d_in[5];
    const float* Wv   = (const float*)d_in[6];
    const float* bv   = (const float*)d_in[7];
    const float* Wpos = (const float*)d_in[8];
    const float* Wout = (const float*)d_in[9];
    const float* bout = (const float*)d_in[10];
    const float* pbu  = (const float*)d_in[11];
    const float* pbv  = (const float*)d_in[12];
    float* out = (float*)d_out;

    cudaFuncSetAttribute(flash_kernel, cudaFuncAttributeMaxDynamicSharedMemorySize, FLASH_SMEM);

    dim3 blk(256);
    gemm_kernel<<<dim3(8, 128), blk>>>(x,  Wq, bq, 0, pbu, pbv, nullptr);
    gemm_kernel<<<dim3(8, 128), blk>>>(x,  Wk, bk, 1, nullptr, nullptr, nullptr);
    gemm_kernel<<<dim3(8, 128), blk>>>(x,  Wv, bv, 2, nullptr, nullptr, nullptr);
    gemm_kernel<<<dim3(8, 32),  blk>>>(pe, Wpos, nullptr, 3, nullptr, nullptr, nullptr);
    flash_kernel<<<dim3(TT / 128, BB * HH, NZ), blk, FLASH_SMEM>>>();
    combine_kernel<<<dim3((MM * FF) / 1024), blk>>>();
    gemm_kernel<<<dim3(8, 128), blk>>>(nullptr, Wout, bout, 4, nullptr, nullptr, out);
}

// round 8
// speedup vs baseline: 2.7568x; 1.1471x over previous
#include <cuda_runtime.h>
#include <cuda_bf16.h>
#include <cuda_fp16.h>
#include <cstdint>

#define BB 4
#define TT 2048
#define HH 8
#define FF 512
#define MM (BB*TT)   // 8192
#define NZ 4         // key-split factor

// ---------------------------------------------------------------------------
// Global scratch (device globals; uint4 for 16B alignment)
// ---------------------------------------------------------------------------
__device__ uint4 g_qh_[1048576];   // q_cat fp16: [bh=32][t=2048][128] (scaled 0.125, biases fused)
__device__ uint4 g_kh_[1048576];   // k_cat fp16: [bh][t][0:64]=k, [64:128]=p
__device__ uint4 g_vh_[524288];    // V fp16: [bh][t][64]
__device__ float g_po[(size_t)NZ*MM*FF];  // partial O per z, unnormalized
__device__ float g_ls[NZ*32*TT];          // partial row sums
__device__ float g_lm[NZ*32*TT];          // partial row maxes
__device__ float g_ao[(size_t)MM*FF];     // combined attention out

#define G_QH ((__half*)g_qh_)
#define G_KH ((__half*)g_kh_)
#define G_VH ((__half*)g_vh_)

// ---------------------------------------------------------------------------
__device__ __forceinline__ uint32_t cvta_s(const void* p) {
    return (uint32_t)__cvta_generic_to_shared(p);
}
__device__ __forceinline__ float ex2f(float x) {
    float r; asm("ex2.approx.ftz.f32 %0, %1;" : "=f"(r) : "f"(x)); return r;
}
// pack two f32 -> f16x2 word: first arg -> low half, second -> high half
__device__ __forceinline__ uint32_t pack2h(float lo, float hi) {
    uint32_t r; asm("cvt.rn.f16x2.f32 %0, %1, %2;" : "=r"(r) : "f"(hi), "f"(lo)); return r;
}

__device__ __forceinline__ void ldsm4(uint32_t r[4], uint32_t a) {
    asm volatile("ldmatrix.sync.aligned.m8n8.x4.shared.b16 {%0,%1,%2,%3}, [%4];"
                 : "=r"(r[0]), "=r"(r[1]), "=r"(r[2]), "=r"(r[3]) : "r"(a));
}
__device__ __forceinline__ void ldsm4t(uint32_t r[4], uint32_t a) {
    asm volatile("ldmatrix.sync.aligned.m8n8.x4.trans.shared.b16 {%0,%1,%2,%3}, [%4];"
                 : "=r"(r[0]), "=r"(r[1]), "=r"(r[2]), "=r"(r[3]) : "r"(a));
}
// fp16 mma, f32 accumulate. Non-volatile: pure register op.
__device__ __forceinline__ void mma16(float c[4], const uint32_t a[4], uint32_t b0, uint32_t b1) {
    asm("mma.sync.aligned.m16n8k16.row.col.f32.f16.f16.f32 "
        "{%0,%1,%2,%3}, {%4,%5,%6,%7}, {%8,%9}, {%0,%1,%2,%3};"
        : "+f"(c[0]), "+f"(c[1]), "+f"(c[2]), "+f"(c[3])
        : "r"(a[0]), "r"(a[1]), "r"(a[2]), "r"(a[3]), "r"(b0), "r"(b1));
}

__device__ __forceinline__ void cpa16(uint32_t d, const void* s) {
    asm volatile("cp.async.cg.shared.global [%0], [%1], 16;" :: "r"(d), "l"(s) : "memory");
}
#define CPA_COMMIT() asm volatile("cp.async.commit_group;" ::: "memory")
#define CPA_WAIT1()  asm volatile("cp.async.wait_group 1;" ::: "memory")
#define CPA_WAIT0()  asm volatile("cp.async.wait_group 0;" ::: "memory")

#define LOG2E_F 1.4426950408889634f

// ---------------------------------------------------------------------------
// SIMT projection GEMM (near FFMA roofline) with fp16 scatter epilogues.
// mode 0: Q -> g_qh fp16 (both halves, +pos_bias_u/v, *0.125)
// mode 1: K -> g_kh[.. 0:64] fp16
// mode 2: V -> g_vh fp16
// mode 3: P -> g_kh[.. 64:128] for all 4 batches (M=2048, no bias)
// mode 4: OUT: A = g_ao, C = d_out (fp32)
// ---------------------------------------------------------------------------
__device__ __forceinline__ void fma16(float acc[4][4], float4 a, float4 b) {
    acc[0][0] += a.x*b.x; acc[0][1] += a.x*b.y; acc[0][2] += a.x*b.z; acc[0][3] += a.x*b.w;
    acc[1][0] += a.y*b.x; acc[1][1] += a.y*b.y; acc[1][2] += a.y*b.z; acc[1][3] += a.y*b.w;
    acc[2][0] += a.z*b.x; acc[2][1] += a.z*b.y; acc[2][2] += a.z*b.z; acc[2][3] += a.z*b.w;
    acc[3][0] += a.w*b.x; acc[3][1] += a.w*b.y; acc[3][2] += a.w*b.z; acc[3][3] += a.w*b.w;
}

__global__ __launch_bounds__(256) void gemm_kernel(
    const float* __restrict__ A, const float* __restrict__ W,
    const float* __restrict__ bias, int mode,
    const float* __restrict__ pbu, const float* __restrict__ pbv,
    float* __restrict__ C)
{
    __shared__ float As[16][64];
    __shared__ float Ws[16][64];
    int tid = threadIdx.x;
    int ty = tid >> 4, tx = tid & 15;
    int m0 = blockIdx.y << 6, n0 = blockIdx.x << 6;
    int lr = tid >> 2, lc = (tid & 3) << 2;

    const float* Abase = (mode == 4) ? g_ao : A;
    const float* Ap = Abase + (size_t)(m0 + lr) * FF + lc;
    const float* Wp = W     + (size_t)(n0 + lr) * FF + lc;

    float acc[4][4] = {};

    for (int k0 = 0; k0 < FF; k0 += 16) {
        float4 av = *(const float4*)(Ap + k0);
        float4 wv = *(const float4*)(Wp + k0);
        __syncthreads();
        As[lc+0][lr] = av.x; As[lc+1][lr] = av.y; As[lc+2][lr] = av.z; As[lc+3][lr] = av.w;
        Ws[lc+0][lr] = wv.x; Ws[lc+1][lr] = wv.y; Ws[lc+2][lr] = wv.z; Ws[lc+3][lr] = wv.w;
        __syncthreads();
#pragma unroll
        for (int k = 0; k < 16; k++) {
            float4 a = *(const float4*)&As[k][ty << 2];
            float4 b = *(const float4*)&Ws[k][tx << 2];
            fma16(acc, a, b);
        }
    }

    int ncol = n0 + (tx << 2);
    int h = ncol >> 6, dd = ncol & 63;

    if (mode == 0) {
#pragma unroll
        for (int i = 0; i < 4; i++) {
            int m = m0 + (ty << 2) + i;
            int b = m >> 11, t = m & (TT - 1);
            float vu[4], vv[4];
#pragma unroll
            for (int j = 0; j < 4; j++) {
                float v = acc[i][j] + bias[ncol + j];
                vu[j] = (v + pbu[ncol + j]) * 0.125f;
                vv[j] = (v + pbv[ncol + j]) * 0.125f;
            }
            size_t base = ((size_t)(b * HH + h) * TT + t) * 128 + dd;
            *(uint2*)(G_QH + base)      = make_uint2(pack2h(vu[0], vu[1]), pack2h(vu[2], vu[3]));
            *(uint2*)(G_QH + base + 64) = make_uint2(pack2h(vv[0], vv[1]), pack2h(vv[2], vv[3]));
        }
    } else if (mode == 1) {
#pragma unroll
        for (int i = 0; i < 4; i++) {
            int m = m0 + (ty << 2) + i;
            int b = m >> 11, t = m & (TT - 1);
            float vk[4];
#pragma unroll
            for (int j = 0; j < 4; j++) vk[j] = acc[i][j] + bias[ncol + j];
            size_t base = ((size_t)(b * HH + h) * TT + t) * 128 + dd;
            *(uint2*)(G_KH + base) = make_uint2(pack2h(vk[0], vk[1]), pack2h(vk[2], vk[3]));
        }
    } else if (mode == 2) {
#pragma unroll
        for (int i = 0; i < 4; i++) {
            int m = m0 + (ty << 2) + i;
            int b = m >> 11, t = m & (TT - 1);
            float vk[4];
#pragma unroll
            for (int j = 0; j < 4; j++) vk[j] = acc[i][j] + bias[ncol + j];
            size_t base = ((size_t)(b * HH + h) * TT + t) * 64 + dd;
            *(uint2*)(G_VH + base) = make_uint2(pack2h(vk[0], vk[1]), pack2h(vk[2], vk[3]));
        }
    } else if (mode == 3) {
#pragma unroll
        for (int i = 0; i < 4; i++) {
            int t = m0 + (ty << 2) + i;   // m is t (0..2047)
            uint2 pv = make_uint2(pack2h(acc[i][0], acc[i][1]), pack2h(acc[i][2], acc[i][3]));
#pragma unroll
            for (int bb = 0; bb < BB; bb++) {
                size_t base = ((size_t)(bb * HH + h) * TT + t) * 128 + 64 + dd;
                *(uint2*)(G_KH + base) = pv;
            }
        }
    } else {
#pragma unroll
        for (int i = 0; i < 4; i++) {
            int m = m0 + (ty << 2) + i;
#pragma unroll
            for (int j = 0; j < 4; j++) {
                int n = ncol + j;
                C[(size_t)m * FF + n] = acc[i][j] + bias[n];
            }
        }
    }
}

// ---------------------------------------------------------------------------
// Single-fp16 mma.sync flash attention, ONLINE softmax, 2 CTAs/SM.
// 128-key tiles, double-buffered cp.async. Key-split z in [0,4).
// ---------------------------------------------------------------------------
#define KSTR 272     // K/Q smem row stride bytes (128 f16 + 16B pad)
#define VSTR 144     // V smem row stride bytes (64 f16 + 16B pad)
#define SM_K 0
#define SM_V 34816
#define STAGE 53248
#define FLASH_SMEM (2*STAGE)   // 106496 -> 2 CTAs/SM

// 128-key tile copy: K 128x128 f16, V 128x64 f16
__device__ __forceinline__ void copy_tile_async(uint32_t stb, int bh, int s0, int tid) {
    const uint4* kh = g_kh_ + ((size_t)bh * TT + s0) * 16;
#pragma unroll
    for (int i = 0; i < 8; i++) {
        int idx = tid + i * 256;          // 2048 uint4
        int r = idx >> 4, c = idx & 15;
        cpa16(stb + SM_K + r * KSTR + c * 16, kh + r * 16 + c);
    }
    const uint4* vh = g_vh_ + ((size_t)bh * TT + s0) * 8;
#pragma unroll
    for (int i = 0; i < 4; i++) {
        int idx = tid + i * 256;          // 1024 uint4
        int r = idx >> 3, c = idx & 7;
        cpa16(stb + SM_V + r * VSTR + c * 16, vh + r * 8 + c);
    }
}

__global__ __launch_bounds__(256, 2) void flash_kernel()
{
    extern __shared__ char sm[];
    uint32_t sb = cvta_s(sm);

    int tid = threadIdx.x;
    int w = tid >> 5, l = tid & 31;
    int bh = blockIdx.y;
    int b = bh >> 3, h = bh & 7;
    int t0 = blockIdx.x << 7;
    int z  = blockIdx.z;
    int kbase = z << 9;           // key range [kbase, kbase+512)

    // ---- prologue: Q (128 rows, 34.8KB) -> stage1 K region; tile0 -> stage0 ----
    {
        uint32_t qb = sb + STAGE;
        const uint4* qh = g_qh_ + ((size_t)bh * TT + t0) * 16;
#pragma unroll
        for (int i = 0; i < 8; i++) {
            int idx = tid + i * 256;
            int r = idx >> 4, c = idx & 15;
            cpa16(qb + r * KSTR + c * 16, qh + r * 16 + c);
        }
        CPA_COMMIT();
        copy_tile_async(sb, bh, kbase, tid);
        CPA_COMMIT();
    }
    CPA_WAIT1();           // Q landed (tile0 may be in flight)
    __syncthreads();

    // ---- frag Q from stage1 (16 rows per warp, full d=128) ----
    uint32_t Qf[8][4];
    {
        uint32_t rowa = sb + STAGE + (16 * w + (l & 15)) * KSTR + (l >> 4) * 16;
#pragma unroll
        for (int ks = 0; ks < 8; ks++) ldsm4(Qf[ks], rowa + ks * 32);
    }

    float O[8][4];
#pragma unroll
    for (int i = 0; i < 8; i++)
#pragma unroll
        for (int j = 0; j < 4; j++) O[i][j] = 0.f;
    float l_0 = 0.f, l_1 = 0.f;
    float m_0 = -1e30f, m_1 = -1e30f;

    uint32_t kB_rel = (l & 7) * KSTR + (l >> 3) * 16;
    uint32_t vB_rel = ((l & 7) + ((l >> 3) & 1) * 8) * VSTR + (l >> 4) * 16;

    for (int it = 0; it < 4; ++it) {
        __syncthreads();   // all warps done with the stage the prefetch will overwrite
        if (it < 3) {
            copy_tile_async(sb + ((it + 1) & 1) * STAGE, bh, kbase + ((it + 1) << 7), tid);
            CPA_COMMIT();
            CPA_WAIT1();   // tile `it` complete
        } else {
            CPA_WAIT0();
        }
        __syncthreads();   // tile `it` visible

        uint32_t stb = sb + (it & 1) * STAGE;
        uint32_t kB_lane = stb + kB_rel;
        uint32_t vB_lane = stb + vB_rel;

#pragma unroll
        for (int kb = 0; kb < 8; kb++) {
            // ---- S for 16 keys, d=128 (single fp16) ----
            float S0A[4] = {0.f,0.f,0.f,0.f}, S0B[4] = {0.f,0.f,0.f,0.f};
            float S1A[4] = {0.f,0.f,0.f,0.f}, S1B[4] = {0.f,0.f,0.f,0.f};
            uint32_t r0a = kB_lane + SM_K + (16 * kb) * KSTR;
            uint32_t r1a = r0a + 8 * KSTR;
#pragma unroll
            for (int j = 0; j < 4; j++) {
                uint32_t B0[4], B1[4];
                ldsm4(B0, r0a + j * 64);
                ldsm4(B1, r1a + j * 64);
                mma16(S0A, Qf[2*j],   B0[0], B0[1]);
                mma16(S1A, Qf[2*j],   B1[0], B1[1]);
                mma16(S0B, Qf[2*j+1], B0[2], B0[3]);
                mma16(S1B, Qf[2*j+1], B1[2], B1[3]);
            }

            // ---- online softmax (rows r and r+8) ----
            float s00 = S0A[0]+S0B[0], s01 = S0A[1]+S0B[1];
            float s02 = S0A[2]+S0B[2], s03 = S0A[3]+S0B[3];
            float s10 = S1A[0]+S1B[0], s11 = S1A[1]+S1B[1];
            float s12 = S1A[2]+S1B[2], s13 = S1A[3]+S1B[3];

            float mx0 = fmaxf(fmaxf(s00, s01), fmaxf(s10, s11));
            float mx1 = fmaxf(fmaxf(s02, s03), fmaxf(s12, s13));
            mx0 = fmaxf(mx0, __shfl_xor_sync(0xffffffffu, mx0, 1));
            mx0 = fmaxf(mx0, __shfl_xor_sync(0xffffffffu, mx0, 2));
            mx1 = fmaxf(mx1, __shfl_xor_sync(0xffffffffu, mx1, 1));
            mx1 = fmaxf(mx1, __shfl_xor_sync(0xffffffffu, mx1, 2));
            float mn0 = fmaxf(m_0, mx0), mn1 = fmaxf(m_1, mx1);
            float c0 = ex2f((m_0 - mn0) * LOG2E_F);
            float c1 = ex2f((m_1 - mn1) * LOG2E_F);
            m_0 = mn0; m_1 = mn1;

            float p00 = ex2f((s00 - mn0) * LOG2E_F);
            float p01 = ex2f((s01 - mn0) * LOG2E_F);
            float p10 = ex2f((s10 - mn0) * LOG2E_F);
            float p11 = ex2f((s11 - mn0) * LOG2E_F);
            float p02 = ex2f((s02 - mn1) * LOG2E_F);
            float p03 = ex2f((s03 - mn1) * LOG2E_F);
            float p12 = ex2f((s12 - mn1) * LOG2E_F);
            float p13 = ex2f((s13 - mn1) * LOG2E_F);
            l_0 = l_0 * c0 + ((p00 + p01) + (p10 + p11));
            l_1 = l_1 * c1 + ((p02 + p03) + (p12 + p13));
#pragma unroll
            for (int nd = 0; nd < 8; nd++) {
                O[nd][0] *= c0; O[nd][1] *= c0;
                O[nd][2] *= c1; O[nd][3] *= c1;
            }

            uint32_t P[4];
            P[0] = pack2h(p00, p01);
            P[1] = pack2h(p02, p03);
            P[2] = pack2h(p10, p11);
            P[3] = pack2h(p12, p13);

            // ---- O += P @ V (single fp16) ----
            uint32_t va = vB_lane + SM_V + (16 * kb) * VSTR;
#pragma unroll
            for (int nd = 0; nd < 4; nd++) {
                uint32_t V[4];
                ldsm4t(V, va + nd * 32);
                mma16(O[2*nd],   P, V[0], V[1]);
                mma16(O[2*nd+1], P, V[2], V[3]);
            }
        }
    }

    // ---- reduce row sums across quads, write partials (O, l, m) ----
    l_0 += __shfl_xor_sync(0xffffffffu, l_0, 1);
    l_0 += __shfl_xor_sync(0xffffffffu, l_0, 2);
    l_1 += __shfl_xor_sync(0xffffffffu, l_1, 1);
    l_1 += __shfl_xor_sync(0xffffffffu, l_1, 2);

    float* po = g_po + (size_t)z * MM * FF;
    float* ls = g_ls + z * 32 * TT;
    float* lm = g_lm + z * 32 * TT;

    int row0 = t0 + 16 * w + (l >> 2);
    if ((l & 3) == 0) {
        ls[bh * TT + row0] = l_0;      lm[bh * TT + row0] = m_0;
        ls[bh * TT + row0 + 8] = l_1;  lm[bh * TT + row0 + 8] = m_1;
    }
    float* d0 = po + ((size_t)(b * TT + row0)) * FF + (h << 6) + ((l & 3) << 1);
    float* d1 = d0 + (size_t)8 * FF;
#pragma unroll
    for (int nd = 0; nd < 8; nd++) {
        *(float2*)(d0 + nd * 8) = make_float2(O[nd][0], O[nd][1]);
        *(float2*)(d1 + nd * 8) = make_float2(O[nd][2], O[nd][3]);
    }
}

// ---------------------------------------------------------------------------
// combine NZ partials with (m,l) merge -> normalized g_ao
// ---------------------------------------------------------------------------
__global__ __launch_bounds__(256) void combine_kernel()
{
    int idx = blockIdx.x * 256 + threadIdx.x;   // float4 units over MM*FF
    int m = idx >> 7;
    int c = (idx & 127) << 2;
    int h = c >> 6;
    int b = m >> 11, t = m & (TT - 1);
    int r = (b * HH + h) * TT + t;

    float mz[NZ];
    float M = -1e30f;
#pragma unroll
    for (int zz = 0; zz < NZ; zz++) { mz[zz] = g_lm[zz * 32 * TT + r]; M = fmaxf(M, mz[zz]); }
    float L = 0.f;
    float wz[NZ];
#pragma unroll
    for (int zz = 0; zz < NZ; zz++) {
        wz[zz] = ex2f((mz[zz] - M) * LOG2E_F);
        L += g_ls[zz * 32 * TT + r] * wz[zz];
    }
    float inv = 1.f / L;

    float4 acc = make_float4(0.f, 0.f, 0.f, 0.f);
#pragma unroll
    for (int zz = 0; zz < NZ; zz++) {
        float4 o = *(const float4*)(g_po + (size_t)zz * MM * FF + (size_t)idx * 4);
        acc.x += o.x * wz[zz]; acc.y += o.y * wz[zz];
        acc.z += o.z * wz[zz]; acc.w += o.w * wz[zz];
    }
    *(float4*)(g_ao + (size_t)idx * 4) =
        make_float4(acc.x * inv, acc.y * inv, acc.z * inv, acc.w * inv);
}

// ---------------------------------------------------------------------------
extern "C" void kernel_launch(void* const* d_in, const int* in_sizes, int n_in,
                              void* d_out, int out_size)
{
    const float* x    = (const float*)d_in[0];
    const float* pe   = (const float*)d_in[1];
    const float* Wq   = (const float*)d_in[2];
    const float* bq   = (const float*)d_in[3];
    const float* Wk   = (const float*)d_in[4];
    const float* bk   = (const float*)d_in[5];
    const float* Wv   = (const float*)d_in[6];
    const float* bv   = (const float*)d_in[7];
    const float* Wpos = (const float*)d_in[8];
    const float* Wout = (const float*)d_in[9];
    const float* bout = (const float*)d_in[10];
    const float* pbu  = (const float*)d_in[11];
    const float* pbv  = (const float*)d_in[12];
    float* out = (float*)d_out;

    cudaFuncSetAttribute(flash_kernel, cudaFuncAttributeMaxDynamicSharedMemorySize, FLASH_SMEM);

    dim3 blk(256);
    gemm_kernel<<<dim3(8, 128), blk>>>(x,  Wq, bq, 0, pbu, pbv, nullptr);
    gemm_kernel<<<dim3(8, 128), blk>>>(x,  Wk, bk, 1, nullptr, nullptr, nullptr);
    gemm_kernel<<<dim3(8, 128), blk>>>(x,  Wv, bv, 2, nullptr, nullptr, nullptr);
    gemm_kernel<<<dim3(8, 32),  blk>>>(pe, Wpos, nullptr, 3, nullptr, nullptr, nullptr);
    flash_kernel<<<dim3(TT / 128, BB * HH, NZ), blk, FLASH_SMEM>>>();
    combine_kernel<<<dim3((MM * FF) / 1024), blk>>>();
    gemm_kernel<<<dim3(8, 128), blk>>>(nullptr, Wout, bout, 4, nullptr, nullptr, out);
}

// round 9
// speedup vs baseline: 2.8366x; 1.0289x over previous
#include <cuda_runtime.h>
#include <cuda_bf16.h>
#include <cuda_fp16.h>
#include <cstdint>

#define BB 4
#define TT 2048
#define HH 8
#define FF 512
#define MM (BB*TT)   // 8192
#define NZ 4         // key-split factor

// ---------------------------------------------------------------------------
// Global scratch (device globals; uint4 for 16B alignment)
// ---------------------------------------------------------------------------
__device__ uint4 g_qh_[1048576];   // q_cat fp16: [bh=32][t=2048][128] (scaled 0.125, biases fused)
__device__ uint4 g_kh_[1048576];   // k_cat fp16: [bh][t][0:64]=k, [64:128]=p
__device__ uint4 g_vh_[524288];    // V fp16: [bh][t][64]
__device__ float g_po[(size_t)NZ*MM*FF];  // partial O per z, unnormalized
__device__ float g_ls[NZ*32*TT];          // partial row sums
__device__ float g_lm[NZ*32*TT];          // partial row maxes
__device__ float g_ao[(size_t)MM*FF];     // combined attention out

#define G_QH ((__half*)g_qh_)
#define G_KH ((__half*)g_kh_)
#define G_VH ((__half*)g_vh_)

// ---------------------------------------------------------------------------
__device__ __forceinline__ uint32_t cvta_s(const void* p) {
    return (uint32_t)__cvta_generic_to_shared(p);
}
__device__ __forceinline__ float ex2f(float x) {
    float r; asm("ex2.approx.ftz.f32 %0, %1;" : "=f"(r) : "f"(x)); return r;
}
// pack two f32 -> f16x2 word: first arg -> low half, second -> high half
__device__ __forceinline__ uint32_t pack2h(float lo, float hi) {
    uint32_t r; asm("cvt.rn.f16x2.f32 %0, %1, %2;" : "=r"(r) : "f"(hi), "f"(lo)); return r;
}

__device__ __forceinline__ void ldsm4(uint32_t r[4], uint32_t a) {
    asm volatile("ldmatrix.sync.aligned.m8n8.x4.shared.b16 {%0,%1,%2,%3}, [%4];"
                 : "=r"(r[0]), "=r"(r[1]), "=r"(r[2]), "=r"(r[3]) : "r"(a));
}
__device__ __forceinline__ void ldsm4t(uint32_t r[4], uint32_t a) {
    asm volatile("ldmatrix.sync.aligned.m8n8.x4.trans.shared.b16 {%0,%1,%2,%3}, [%4];"
                 : "=r"(r[0]), "=r"(r[1]), "=r"(r[2]), "=r"(r[3]) : "r"(a));
}
// fp16 mma, f32 accumulate. Non-volatile: pure register op.
__device__ __forceinline__ void mma16(float c[4], const uint32_t a[4], uint32_t b0, uint32_t b1) {
    asm("mma.sync.aligned.m16n8k16.row.col.f32.f16.f16.f32 "
        "{%0,%1,%2,%3}, {%4,%5,%6,%7}, {%8,%9}, {%0,%1,%2,%3};"
        : "+f"(c[0]), "+f"(c[1]), "+f"(c[2]), "+f"(c[3])
        : "r"(a[0]), "r"(a[1]), "r"(a[2]), "r"(a[3]), "r"(b0), "r"(b1));
}

__device__ __forceinline__ void cpa16(uint32_t d, const void* s) {
    asm volatile("cp.async.cg.shared.global [%0], [%1], 16;" :: "r"(d), "l"(s) : "memory");
}
#define CPA_COMMIT() asm volatile("cp.async.commit_group;" ::: "memory")
#define CPA_WAIT1()  asm volatile("cp.async.wait_group 1;" ::: "memory")
#define CPA_WAIT0()  asm volatile("cp.async.wait_group 0;" ::: "memory")

#define LOG2E_F 1.4426950408889634f

// ---------------------------------------------------------------------------
// SIMT GEMM body (near FFMA roofline): acc[i][j] = sum_k A[m,k]*W[n,k]
// ---------------------------------------------------------------------------
__device__ __forceinline__ void fma16(float acc[4][4], float4 a, float4 b) {
    acc[0][0] += a.x*b.x; acc[0][1] += a.x*b.y; acc[0][2] += a.x*b.z; acc[0][3] += a.x*b.w;
    acc[1][0] += a.y*b.x; acc[1][1] += a.y*b.y; acc[1][2] += a.y*b.z; acc[1][3] += a.y*b.w;
    acc[2][0] += a.z*b.x; acc[2][1] += a.z*b.y; acc[2][2] += a.z*b.z; acc[2][3] += a.z*b.w;
    acc[3][0] += a.w*b.x; acc[3][1] += a.w*b.y; acc[3][2] += a.w*b.z; acc[3][3] += a.w*b.w;
}

__device__ __forceinline__ void gemm_body(
    const float* __restrict__ Abase, const float* __restrict__ W,
    int m0, int n0, int tid, float acc[4][4],
    float As[16][64], float Ws[16][64])
{
    int ty = tid >> 4, tx = tid & 15;
    int lr = tid >> 2, lc = (tid & 3) << 2;
    const float* Ap = Abase + (size_t)(m0 + lr) * FF + lc;
    const float* Wp = W     + (size_t)(n0 + lr) * FF + lc;

    for (int k0 = 0; k0 < FF; k0 += 16) {
        float4 av = *(const float4*)(Ap + k0);
        float4 wv = *(const float4*)(Wp + k0);
        __syncthreads();
        As[lc+0][lr] = av.x; As[lc+1][lr] = av.y; As[lc+2][lr] = av.z; As[lc+3][lr] = av.w;
        Ws[lc+0][lr] = wv.x; Ws[lc+1][lr] = wv.y; Ws[lc+2][lr] = wv.z; Ws[lc+3][lr] = wv.w;
        __syncthreads();
#pragma unroll
        for (int k = 0; k < 16; k++) {
            float4 a = *(const float4*)&As[k][ty << 2];
            float4 b = *(const float4*)&Ws[k][tx << 2];
            fma16(acc, a, b);
        }
    }
}

// ---------------------------------------------------------------------------
// Fused QKV projections: blockIdx.z selects {Q,K,V}, fp16 scatter epilogues.
// ---------------------------------------------------------------------------
__global__ __launch_bounds__(256) void qkv_kernel(
    const float* __restrict__ x,
    const float* __restrict__ Wq, const float* __restrict__ bq,
    const float* __restrict__ Wk, const float* __restrict__ bk,
    const float* __restrict__ Wv, const float* __restrict__ bv,
    const float* __restrict__ pbu, const float* __restrict__ pbv)
{
    __shared__ float As[16][64];
    __shared__ float Ws[16][64];
    int tid = threadIdx.x;
    int ty = tid >> 4, tx = tid & 15;
    int m0 = blockIdx.y << 6, n0 = blockIdx.x << 6;
    int z = blockIdx.z;

    const float* W    = (z == 0) ? Wq : (z == 1) ? Wk : Wv;
    const float* bias = (z == 0) ? bq : (z == 1) ? bk : bv;

    float acc[4][4] = {};
    gemm_body(x, W, m0, n0, tid, acc, As, Ws);

    int ncol = n0 + (tx << 2);
    int h = ncol >> 6, dd = ncol & 63;

    if (z == 0) {
#pragma unroll
        for (int i = 0; i < 4; i++) {
            int m = m0 + (ty << 2) + i;
            int b = m >> 11, t = m & (TT - 1);
            float vu[4], vv[4];
#pragma unroll
            for (int j = 0; j < 4; j++) {
                float v = acc[i][j] + bias[ncol + j];
                vu[j] = (v + pbu[ncol + j]) * 0.125f;
                vv[j] = (v + pbv[ncol + j]) * 0.125f;
            }
            size_t base = ((size_t)(b * HH + h) * TT + t) * 128 + dd;
            *(uint2*)(G_QH + base)      = make_uint2(pack2h(vu[0], vu[1]), pack2h(vu[2], vu[3]));
            *(uint2*)(G_QH + base + 64) = make_uint2(pack2h(vv[0], vv[1]), pack2h(vv[2], vv[3]));
        }
    } else if (z == 1) {
#pragma unroll
        for (int i = 0; i < 4; i++) {
            int m = m0 + (ty << 2) + i;
            int b = m >> 11, t = m & (TT - 1);
            float vk[4];
#pragma unroll
            for (int j = 0; j < 4; j++) vk[j] = acc[i][j] + bias[ncol + j];
            size_t base = ((size_t)(b * HH + h) * TT + t) * 128 + dd;
            *(uint2*)(G_KH + base) = make_uint2(pack2h(vk[0], vk[1]), pack2h(vk[2], vk[3]));
        }
    } else {
#pragma unroll
        for (int i = 0; i < 4; i++) {
            int m = m0 + (ty << 2) + i;
            int b = m >> 11, t = m & (TT - 1);
            float vk[4];
#pragma unroll
            for (int j = 0; j < 4; j++) vk[j] = acc[i][j] + bias[ncol + j];
            size_t base = ((size_t)(b * HH + h) * TT + t) * 64 + dd;
            *(uint2*)(G_VH + base) = make_uint2(pack2h(vk[0], vk[1]), pack2h(vk[2], vk[3]));
        }
    }
}

// ---------------------------------------------------------------------------
// P projection (mode 3) and output projection (mode 4)
// ---------------------------------------------------------------------------
__global__ __launch_bounds__(256) void gemm_kernel(
    const float* __restrict__ A, const float* __restrict__ W,
    const float* __restrict__ bias, int mode,
    float* __restrict__ C)
{
    __shared__ float As[16][64];
    __shared__ float Ws[16][64];
    int tid = threadIdx.x;
    int ty = tid >> 4, tx = tid & 15;
    int m0 = blockIdx.y << 6, n0 = blockIdx.x << 6;

    const float* Abase = (mode == 4) ? g_ao : A;
    float acc[4][4] = {};
    gemm_body(Abase, W, m0, n0, tid, acc, As, Ws);

    int ncol = n0 + (tx << 2);
    int h = ncol >> 6, dd = ncol & 63;

    if (mode == 3) {
#pragma unroll
        for (int i = 0; i < 4; i++) {
            int t = m0 + (ty << 2) + i;   // m is t (0..2047)
            uint2 pv = make_uint2(pack2h(acc[i][0], acc[i][1]), pack2h(acc[i][2], acc[i][3]));
#pragma unroll
            for (int bb = 0; bb < BB; bb++) {
                size_t base = ((size_t)(bb * HH + h) * TT + t) * 128 + 64 + dd;
                *(uint2*)(G_KH + base) = pv;
            }
        }
    } else {
#pragma unroll
        for (int i = 0; i < 4; i++) {
            int m = m0 + (ty << 2) + i;
#pragma unroll
            for (int j = 0; j < 4; j++) {
                int n = ncol + j;
                C[(size_t)m * FF + n] = acc[i][j] + bias[n];
            }
        }
    }
}

// tiny spacer so flash_kernel lands in the profiler's capture slot (launch #3)
__global__ void dummy_kernel() {}

// ---------------------------------------------------------------------------
// Single-fp16 mma.sync flash attention, ONLINE softmax, 2 CTAs/SM.
// 128-key tiles, double-buffered cp.async. Key-split z in [0,4).
// R9: V-ldsm hoisted before softmax (unpins volatile ldsm chain so ptxas can
// overlap next kb's S-mmas with this kb's softmax); half2-packed max shuffle;
// __all_sync fast path skipping O-rescale when running max unchanged.
// ---------------------------------------------------------------------------
#define KSTR 272     // K/Q smem row stride bytes (128 f16 + 16B pad)
#define VSTR 144     // V smem row stride bytes (64 f16 + 16B pad)
#define SM_K 0
#define SM_V 34816
#define STAGE 53248
#define FLASH_SMEM (2*STAGE)   // 106496 -> 2 CTAs/SM

// 128-key tile copy: K 128x128 f16, V 128x64 f16
__device__ __forceinline__ void copy_tile_async(uint32_t stb, int bh, int s0, int tid) {
    const uint4* kh = g_kh_ + ((size_t)bh * TT + s0) * 16;
#pragma unroll
    for (int i = 0; i < 8; i++) {
        int idx = tid + i * 256;          // 2048 uint4
        int r = idx >> 4, c = idx & 15;
        cpa16(stb + SM_K + r * KSTR + c * 16, kh + r * 16 + c);
    }
    const uint4* vh = g_vh_ + ((size_t)bh * TT + s0) * 8;
#pragma unroll
    for (int i = 0; i < 4; i++) {
        int idx = tid + i * 256;          // 1024 uint4
        int r = idx >> 3, c = idx & 7;
        cpa16(stb + SM_V + r * VSTR + c * 16, vh + r * 8 + c);
    }
}

__global__ __launch_bounds__(256, 2) void flash_kernel()
{
    extern __shared__ char sm[];
    uint32_t sb = cvta_s(sm);

    int tid = threadIdx.x;
    int w = tid >> 5, l = tid & 31;
    int bh = blockIdx.y;
    int b = bh >> 3, h = bh & 7;
    int t0 = blockIdx.x << 7;
    int z  = blockIdx.z;
    int kbase = z << 9;           // key range [kbase, kbase+512)

    // ---- prologue: Q (128 rows, 34.8KB) -> stage1 K region; tile0 -> stage0 ----
    {
        uint32_t qb = sb + STAGE;
        const uint4* qh = g_qh_ + ((size_t)bh * TT + t0) * 16;
#pragma unroll
        for (int i = 0; i < 8; i++) {
            int idx = tid + i * 256;
            int r = idx >> 4, c = idx & 15;
            cpa16(qb + r * KSTR + c * 16, qh + r * 16 + c);
        }
        CPA_COMMIT();
        copy_tile_async(sb, bh, kbase, tid);
        CPA_COMMIT();
    }
    CPA_WAIT1();           // Q landed (tile0 may be in flight)
    __syncthreads();

    // ---- frag Q from stage1 (16 rows per warp, full d=128) ----
    uint32_t Qf[8][4];
    {
        uint32_t rowa = sb + STAGE + (16 * w + (l & 15)) * KSTR + (l >> 4) * 16;
#pragma unroll
        for (int ks = 0; ks < 8; ks++) ldsm4(Qf[ks], rowa + ks * 32);
    }

    float O[8][4];
#pragma unroll
    for (int i = 0; i < 8; i++)
#pragma unroll
        for (int j = 0; j < 4; j++) O[i][j] = 0.f;
    float l_0 = 0.f, l_1 = 0.f;
    float m_0 = -1e30f, m_1 = -1e30f;

    uint32_t kB_rel = (l & 7) * KSTR + (l >> 3) * 16;
    uint32_t vB_rel = ((l & 7) + ((l >> 3) & 1) * 8) * VSTR + (l >> 4) * 16;

    for (int it = 0; it < 4; ++it) {
        __syncthreads();   // all warps done with the stage the prefetch will overwrite
        if (it < 3) {
            copy_tile_async(sb + ((it + 1) & 1) * STAGE, bh, kbase + ((it + 1) << 7), tid);
            CPA_COMMIT();
            CPA_WAIT1();   // tile `it` complete
        } else {
            CPA_WAIT0();
        }
        __syncthreads();   // tile `it` visible

        uint32_t stb = sb + (it & 1) * STAGE;
        uint32_t kB_lane = stb + kB_rel;
        uint32_t vB_lane = stb + vB_rel;

#pragma unroll
        for (int kb = 0; kb < 8; kb++) {
            // ---- S for 16 keys, d=128 (single fp16) ----
            float S0A[4] = {0.f,0.f,0.f,0.f}, S0B[4] = {0.f,0.f,0.f,0.f};
            float S1A[4] = {0.f,0.f,0.f,0.f}, S1B[4] = {0.f,0.f,0.f,0.f};
            uint32_t r0a = kB_lane + SM_K + (16 * kb) * KSTR;
            uint32_t r1a = r0a + 8 * KSTR;
#pragma unroll
            for (int j = 0; j < 4; j++) {
                uint32_t B0[4], B1[4];
                ldsm4(B0, r0a + j * 64);
                ldsm4(B1, r1a + j * 64);
                mma16(S0A, Qf[2*j],   B0[0], B0[1]);
                mma16(S1A, Qf[2*j],   B1[0], B1[1]);
                mma16(S0B, Qf[2*j+1], B0[2], B0[3]);
                mma16(S1B, Qf[2*j+1], B1[2], B1[3]);
            }

            // ---- V fragments for this kb, loaded BEFORE softmax ----
            uint32_t va = vB_lane + SM_V + (16 * kb) * VSTR;
            uint32_t V0[4], V1[4], V2[4], V3[4];
            ldsm4t(V0, va);
            ldsm4t(V1, va + 32);
            ldsm4t(V2, va + 64);
            ldsm4t(V3, va + 96);

            // ---- online softmax (rows r and r+8), packed-half2 max reduce ----
            float s00 = S0A[0]+S0B[0], s01 = S0A[1]+S0B[1];
            float s02 = S0A[2]+S0B[2], s03 = S0A[3]+S0B[3];
            float s10 = S1A[0]+S1B[0], s11 = S1A[1]+S1B[1];
            float s12 = S1A[2]+S1B[2], s13 = S1A[3]+S1B[3];

            float mx0f = fmaxf(fmaxf(s00, s01), fmaxf(s10, s11));
            float mx1f = fmaxf(fmaxf(s02, s03), fmaxf(s12, s13));
            uint32_t pk = pack2h(mx0f, mx1f);
            {
                uint32_t o1 = __shfl_xor_sync(0xffffffffu, pk, 1);
                __half2 a = *reinterpret_cast<__half2*>(&pk);
                __half2 c = __hmax2(a, *reinterpret_cast<__half2*>(&o1));
                pk = *reinterpret_cast<uint32_t*>(&c);
                uint32_t o2 = __shfl_xor_sync(0xffffffffu, pk, 2);
                __half2 d = __hmax2(*reinterpret_cast<__half2*>(&pk),
                                    *reinterpret_cast<__half2*>(&o2));
                pk = *reinterpret_cast<uint32_t*>(&d);
            }
            float2 mxf = __half22float2(*reinterpret_cast<__half2*>(&pk));
            float mn0 = fmaxf(m_0, mxf.x), mn1 = fmaxf(m_1, mxf.y);
            bool nochg = __all_sync(0xffffffffu, (mn0 == m_0) && (mn1 == m_1));

            float p00 = ex2f((s00 - mn0) * LOG2E_F);
            float p01 = ex2f((s01 - mn0) * LOG2E_F);
            float p10 = ex2f((s10 - mn0) * LOG2E_F);
            float p11 = ex2f((s11 - mn0) * LOG2E_F);
            float p02 = ex2f((s02 - mn1) * LOG2E_F);
            float p03 = ex2f((s03 - mn1) * LOG2E_F);
            float p12 = ex2f((s12 - mn1) * LOG2E_F);
            float p13 = ex2f((s13 - mn1) * LOG2E_F);
            float sum0 = (p00 + p01) + (p10 + p11);
            float sum1 = (p02 + p03) + (p12 + p13);

            if (nochg) {
                l_0 += sum0;
                l_1 += sum1;
            } else {
                float c0 = ex2f((m_0 - mn0) * LOG2E_F);
                float c1 = ex2f((m_1 - mn1) * LOG2E_F);
                l_0 = l_0 * c0 + sum0;
                l_1 = l_1 * c1 + sum1;
                m_0 = mn0; m_1 = mn1;
#pragma unroll
                for (int nd = 0; nd < 8; nd++) {
                    O[nd][0] *= c0; O[nd][1] *= c0;
                    O[nd][2] *= c1; O[nd][3] *= c1;
                }
            }

            uint32_t P[4];
            P[0] = pack2h(p00, p01);
            P[1] = pack2h(p02, p03);
            P[2] = pack2h(p10, p11);
            P[3] = pack2h(p12, p13);

            // ---- O += P @ V (single fp16) ----
            mma16(O[0], P, V0[0], V0[1]);
            mma16(O[1], P, V0[2], V0[3]);
            mma16(O[2], P, V1[0], V1[1]);
            mma16(O[3], P, V1[2], V1[3]);
            mma16(O[4], P, V2[0], V2[1]);
            mma16(O[5], P, V2[2], V2[3]);
            mma16(O[6], P, V3[0], V3[1]);
            mma16(O[7], P, V3[2], V3[3]);
        }
    }

    // ---- reduce row sums across quads, write partials (O, l, m) ----
    l_0 += __shfl_xor_sync(0xffffffffu, l_0, 1);
    l_0 += __shfl_xor_sync(0xffffffffu, l_0, 2);
    l_1 += __shfl_xor_sync(0xffffffffu, l_1, 1);
    l_1 += __shfl_xor_sync(0xffffffffu, l_1, 2);

    float* po = g_po + (size_t)z * MM * FF;
    float* ls = g_ls + z * 32 * TT;
    float* lm = g_lm + z * 32 * TT;

    int row0 = t0 + 16 * w + (l >> 2);
    if ((l & 3) == 0) {
        ls[bh * TT + row0] = l_0;      lm[bh * TT + row0] = m_0;
        ls[bh * TT + row0 + 8] = l_1;  lm[bh * TT + row0 + 8] = m_1;
    }
    float* d0 = po + ((size_t)(b * TT + row0)) * FF + (h << 6) + ((l & 3) << 1);
    float* d1 = d0 + (size_t)8 * FF;
#pragma unroll
    for (int nd = 0; nd < 8; nd++) {
        *(float2*)(d0 + nd * 8) = make_float2(O[nd][0], O[nd][1]);
        *(float2*)(d1 + nd * 8) = make_float2(O[nd][2], O[nd][3]);
    }
}

// ---------------------------------------------------------------------------
// combine NZ partials with (m,l) merge -> normalized g_ao
// ---------------------------------------------------------------------------
__global__ __launch_bounds__(256) void combine_kernel()
{
    int idx = blockIdx.x * 256 + threadIdx.x;   // float4 units over MM*FF
    int m = idx >> 7;
    int c = (idx & 127) << 2;
    int h = c >> 6;
    int b = m >> 11, t = m & (TT - 1);
    int r = (b * HH + h) * TT + t;

    float mz[NZ];
    float M = -1e30f;
#pragma unroll
    for (int zz = 0; zz < NZ; zz++) { mz[zz] = g_lm[zz * 32 * TT + r]; M = fmaxf(M, mz[zz]); }
    float L = 0.f;
    float wz[NZ];
#pragma unroll
    for (int zz = 0; zz < NZ; zz++) {
        wz[zz] = ex2f((mz[zz] - M) * LOG2E_F);
        L += g_ls[zz * 32 * TT + r] * wz[zz];
    }
    float inv = 1.f / L;

    float4 acc = make_float4(0.f, 0.f, 0.f, 0.f);
#pragma unroll
    for (int zz = 0; zz < NZ; zz++) {
        float4 o = *(const float4*)(g_po + (size_t)zz * MM * FF + (size_t)idx * 4);
        acc.x += o.x * wz[zz]; acc.y += o.y * wz[zz];
        acc.z += o.z * wz[zz]; acc.w += o.w * wz[zz];
    }
    *(float4*)(g_ao + (size_t)idx * 4) =
        make_float4(acc.x * inv, acc.y * inv, acc.z * inv, acc.w * inv);
}

// ---------------------------------------------------------------------------
extern "C" void kernel_launch(void* const* d_in, const int* in_sizes, int n_in,
                              void* d_out, int out_size)
{
    const float* x    = (const float*)d_in[0];
    const float* pe   = (const float*)d_in[1];
    const float* Wq   = (const float*)d_in[2];
    const float* bq   = (const float*)d_in[3];
    const float* Wk   = (const float*)d_in[4];
    const float* bk   = (const float*)d_in[5];
    const float* Wv   = (const float*)d_in[6];
    const float* bv   = (const float*)d_in[7];
    const float* Wpos = (const float*)d_in[8];
    const float* Wout = (const float*)d_in[9];
    const float* bout = (const float*)d_in[10];
    const float* pbu  = (const float*)d_in[11];
    const float* pbv  = (const float*)d_in[12];
    float* out = (float*)d_out;

    cudaFuncSetAttribute(flash_kernel, cudaFuncAttributeMaxDynamicSharedMemorySize, FLASH_SMEM);

    dim3 blk(256);
    // #0: fused QKV projections
    qkv_kernel<<<dim3(8, 128, 3), blk>>>(x, Wq, bq, Wk, bk, Wv, bv, pbu, pbv);
    // #1: positional projection
    gemm_kernel<<<dim3(8, 32), blk>>>(pe, Wpos, nullptr, 3, nullptr);
    // #2: spacer so flash is launch #3 (the profiler's capture slot)
    dummy_kernel<<<1, 1>>>();
    // #3: flash attention
    flash_kernel<<<dim3(TT / 128, BB * HH, NZ), blk, FLASH_SMEM>>>();
    // #4: combine split-K partials
    combine_kernel<<<dim3((MM * FF) / 1024), blk>>>();
    // #5: output projection
    gemm_kernel<<<dim3(8, 128), blk>>>(nullptr, Wout, bout, 4, out);
}

// round 10
// speedup vs baseline: 6.3727x; 2.2466x over previous
#include <cuda_runtime.h>
#include <cuda_bf16.h>
#include <cuda_fp16.h>
#include <cstdint>

#define BB 4
#define TT 2048
#define HH 8
#define FF 512
#define MM (BB*TT)   // 8192
#define NZ 4         // key-split factor

// ---------------------------------------------------------------------------
// Global scratch (device globals; uint4 for 16B alignment)
// ---------------------------------------------------------------------------
__device__ uint4 g_qh_[1048576];   // q_cat fp16: [bh=32][t=2048][128] (scaled 0.125, biases fused)
__device__ uint4 g_kh_[1048576];   // k_cat fp16: [bh][t][0:64]=k, [64:128]=p
__device__ uint4 g_vh_[524288];    // V fp16: [bh][t][64]
__device__ uint4 g_xh_[524288];    // x hi fp16 [8192][512]
__device__ uint4 g_xl_[524288];    // x lo fp16
__device__ uint4 g_peh_[131072];   // pos_emb hi fp16 [2048][512]
__device__ uint4 g_pel_[131072];   // pos_emb lo fp16
__device__ uint4 g_wh_[163840];    // 5 weights fp16 [5][512][512] (Wq,Wk,Wv,Wpos,Wout)
__device__ uint4 g_aoh_[524288];   // attention-out hi fp16 [8192][512]
__device__ uint4 g_aol_[524288];   // attention-out lo fp16
__device__ float g_po[(size_t)NZ*MM*FF];  // partial O per z, unnormalized
__device__ float g_ls[NZ*32*TT];          // partial row sums
__device__ float g_lm[NZ*32*TT];          // partial row maxes

#define G_QH ((__half*)g_qh_)
#define G_KH ((__half*)g_kh_)
#define G_VH ((__half*)g_vh_)

// ---------------------------------------------------------------------------
__device__ __forceinline__ uint32_t cvta_s(const void* p) {
    return (uint32_t)__cvta_generic_to_shared(p);
}
__device__ __forceinline__ float ex2f(float x) {
    float r; asm("ex2.approx.ftz.f32 %0, %1;" : "=f"(r) : "f"(x)); return r;
}
// pack two f32 -> f16x2 word: first arg -> low half, second -> high half
__device__ __forceinline__ uint32_t pack2h(float lo, float hi) {
    uint32_t r; asm("cvt.rn.f16x2.f32 %0, %1, %2;" : "=r"(r) : "f"(hi), "f"(lo)); return r;
}

__device__ __forceinline__ void ldsm4(uint32_t r[4], uint32_t a) {
    asm volatile("ldmatrix.sync.aligned.m8n8.x4.shared.b16 {%0,%1,%2,%3}, [%4];"
                 : "=r"(r[0]), "=r"(r[1]), "=r"(r[2]), "=r"(r[3]) : "r"(a));
}
__device__ __forceinline__ void ldsm4t(uint32_t r[4], uint32_t a) {
    asm volatile("ldmatrix.sync.aligned.m8n8.x4.trans.shared.b16 {%0,%1,%2,%3}, [%4];"
                 : "=r"(r[0]), "=r"(r[1]), "=r"(r[2]), "=r"(r[3]) : "r"(a));
}
// fp16 mma, f32 accumulate. Non-volatile: pure register op.
__device__ __forceinline__ void mma16(float c[4], const uint32_t a[4], uint32_t b0, uint32_t b1) {
    asm("mma.sync.aligned.m16n8k16.row.col.f32.f16.f16.f32 "
        "{%0,%1,%2,%3}, {%4,%5,%6,%7}, {%8,%9}, {%0,%1,%2,%3};"
        : "+f"(c[0]), "+f"(c[1]), "+f"(c[2]), "+f"(c[3])
        : "r"(a[0]), "r"(a[1]), "r"(a[2]), "r"(a[3]), "r"(b0), "r"(b1));
}

__device__ __forceinline__ void cpa16(uint32_t d, const void* s) {
    asm volatile("cp.async.cg.shared.global [%0], [%1], 16;" :: "r"(d), "l"(s) : "memory");
}
#define CPA_COMMIT() asm volatile("cp.async.commit_group;" ::: "memory")
#define CPA_WAIT1()  asm volatile("cp.async.wait_group 1;" ::: "memory")
#define CPA_WAIT0()  asm volatile("cp.async.wait_group 0;" ::: "memory")

#define LOG2E_F 1.4426950408889634f

// ---------------------------------------------------------------------------
// conv_kernel: fp32 -> fp16 conversions.
// z=0: x -> g_xh/g_xl (hi/lo). z=1: pos_emb -> g_peh/g_pel.
// z=2..6: Wq,Wk,Wv,Wpos,Wout -> g_wh (single fp16).
// ---------------------------------------------------------------------------
__global__ __launch_bounds__(256) void conv_kernel(
    const float* __restrict__ x, const float* __restrict__ pe,
    const float* __restrict__ Wq, const float* __restrict__ Wk,
    const float* __restrict__ Wv, const float* __restrict__ Wpos,
    const float* __restrict__ Wout)
{
    int z = blockIdx.y;
    int stride = gridDim.x * 256;
    if (z == 0 || z == 1) {
        int n = (z == 0) ? 1048576 : 262144;
        const float4* src = (const float4*)((z == 0) ? x : pe);
        uint2* dh = (uint2*)((z == 0) ? g_xh_ : g_peh_);
        uint2* dl = (uint2*)((z == 0) ? g_xl_ : g_pel_);
        for (int i = blockIdx.x * 256 + threadIdx.x; i < n; i += stride) {
            float4 v = src[i];
            uint32_t h0 = pack2h(v.x, v.y);
            uint32_t h1 = pack2h(v.z, v.w);
            float2 f0 = __half22float2(*reinterpret_cast<__half2*>(&h0));
            float2 f1 = __half22float2(*reinterpret_cast<__half2*>(&h1));
            dh[i] = make_uint2(h0, h1);
            dl[i] = make_uint2(pack2h(v.x - f0.x, v.y - f0.y), pack2h(v.z - f1.x, v.w - f1.y));
        }
    } else {
        int widx = z - 2;
        const float* Wsel = (widx == 0) ? Wq : (widx == 1) ? Wk : (widx == 2) ? Wv
                          : (widx == 3) ? Wpos : Wout;
        const float4* src = (const float4*)Wsel;
        uint2* dh = (uint2*)g_wh_ + (size_t)widx * 65536;
        for (int i = blockIdx.x * 256 + threadIdx.x; i < 65536; i += stride) {
            float4 v = src[i];
            dh[i] = make_uint2(pack2h(v.x, v.y), pack2h(v.z, v.w));
        }
    }
}

// ---------------------------------------------------------------------------
// fp16 tensor-core projection GEMM: C[m,n] = (Ah+Al)[m,:] . W[n,:]
// CTA: 128 rows x 64 cols, 8 warps (warp w: rows 16w..16w+15).
// K=512 in 8 chunks of 64, double-buffered cp.async.
// mode (blockIdx.z if arg<0): 0=Q, 1=K, 2=V, 3=P, 4=OUT — scatter epilogues.
// ---------------------------------------------------------------------------
#define KSTR2 144         // 64 f16 + 16B pad
#define SM_AH 0
#define SM_AL 18432
#define SM_B  36864
#define GSTAGE 46080
#define GEMM_SMEM (2*GSTAGE)   // 92160 -> 2 CTAs/SM

__device__ __forceinline__ void copy_gtile(
    uint32_t stb, const uint4* Ah, const uint4* Al, const uint4* Wb,
    int m0, int n0, int k08, int tid)
{
#pragma unroll
    for (int i = 0; i < 4; i++) {
        int idx = tid + i * 256;          // 1024: 128 rows x 8 uint4
        int r = idx >> 3, c = idx & 7;
        size_t so = (size_t)(m0 + r) * 64 + k08 + c;
        cpa16(stb + SM_AH + r * KSTR2 + c * 16, Ah + so);
        cpa16(stb + SM_AL + r * KSTR2 + c * 16, Al + so);
    }
#pragma unroll
    for (int i = 0; i < 2; i++) {
        int idx = tid + i * 256;          // 512: 64 rows x 8 uint4
        int r = idx >> 3, c = idx & 7;
        cpa16(stb + SM_B + r * KSTR2 + c * 16, Wb + (size_t)(n0 + r) * 64 + k08 + c);
    }
}

__global__ __launch_bounds__(256, 2) void proj_kernel(
    int mode_arg, float* __restrict__ out,
    const float* __restrict__ bq, const float* __restrict__ bk,
    const float* __restrict__ bv, const float* __restrict__ bout,
    const float* __restrict__ pbu, const float* __restrict__ pbv)
{
    extern __shared__ char sm[];
    uint32_t sb = cvta_s(sm);

    int tid = threadIdx.x;
    int w = tid >> 5, l = tid & 31;
    int mode = (mode_arg < 0) ? (int)blockIdx.z : mode_arg;
    int m0 = blockIdx.y << 7, n0 = blockIdx.x << 6;

    const uint4* Ah = (mode <= 2) ? g_xh_ : (mode == 3) ? g_peh_ : g_aoh_;
    const uint4* Al = (mode <= 2) ? g_xl_ : (mode == 3) ? g_pel_ : g_aol_;
    int widx = (mode <= 2) ? mode : ((mode == 3) ? 3 : 4);
    const uint4* Wb = g_wh_ + (size_t)widx * 32768;

    // prologue: chunks 0,1
    copy_gtile(sb, Ah, Al, Wb, m0, n0, 0, tid);  CPA_COMMIT();
    copy_gtile(sb + GSTAGE, Ah, Al, Wb, m0, n0, 8, tid);  CPA_COMMIT();

    float acc[4][2][4];
#pragma unroll
    for (int a = 0; a < 4; a++)
#pragma unroll
        for (int bq2 = 0; bq2 < 2; bq2++)
#pragma unroll
            for (int c = 0; c < 4; c++) acc[a][bq2][c] = 0.f;

    uint32_t rowa_rel = (16 * w + (l & 15)) * KSTR2 + (l >> 4) * 16;
    uint32_t kB_rel   = (l & 7) * KSTR2 + (l >> 3) * 16;

    for (int ch = 0; ch < 8; ch++) {
        if (ch < 6) { CPA_WAIT1(); } else { CPA_WAIT0(); }
        __syncthreads();

        uint32_t stb = sb + (ch & 1) * GSTAGE;

        uint32_t Afh[4][4], Afl[4][4];
#pragma unroll
        for (int ks = 0; ks < 4; ks++) {
            ldsm4(Afh[ks], stb + SM_AH + rowa_rel + ks * 32);
            ldsm4(Afl[ks], stb + SM_AL + rowa_rel + ks * 32);
        }
#pragma unroll
        for (int nb = 0; nb < 4; nb++) {
            uint32_t r0 = stb + SM_B + (16 * nb) * KSTR2 + kB_rel;
            uint32_t r1 = r0 + 8 * KSTR2;
#pragma unroll
            for (int j = 0; j < 2; j++) {
                uint32_t B0[4], B1[4];
                ldsm4(B0, r0 + j * 64);
                ldsm4(B1, r1 + j * 64);
                mma16(acc[nb][0], Afh[2*j],   B0[0], B0[1]);
                mma16(acc[nb][1], Afh[2*j],   B1[0], B1[1]);
                mma16(acc[nb][0], Afh[2*j+1], B0[2], B0[3]);
                mma16(acc[nb][1], Afh[2*j+1], B1[2], B1[3]);
                mma16(acc[nb][0], Afl[2*j],   B0[0], B0[1]);
                mma16(acc[nb][1], Afl[2*j],   B1[0], B1[1]);
                mma16(acc[nb][0], Afl[2*j+1], B0[2], B0[3]);
                mma16(acc[nb][1], Afl[2*j+1], B1[2], B1[3]);
            }
        }
        __syncthreads();
        if (ch + 2 < 8) {
            copy_gtile(sb + (ch & 1) * GSTAGE, Ah, Al, Wb, m0, n0, (ch + 2) * 8, tid);
            CPA_COMMIT();
        }
    }

    // ---- epilogue: scatter per mode ----
    int row0 = 16 * w + (l >> 2);
    int m = m0 + row0;          // rows m and m+8
    int colb = (l & 3) << 1;

#pragma unroll
    for (int nb = 0; nb < 4; nb++) {
#pragma unroll
        for (int half = 0; half < 2; half++) {
            int n = n0 + nb * 16 + half * 8 + colb;   // n, n+1
            float c0 = acc[nb][half][0], c1 = acc[nb][half][1];
            float c2 = acc[nb][half][2], c3 = acc[nb][half][3];
            int h = n >> 6, dd = n & 63;

            if (mode == 0) {
                float b0 = bq[n], b1 = bq[n + 1];
                float u0 = pbu[n], u1 = pbu[n + 1];
                float v0 = pbv[n], v1 = pbv[n + 1];
                int bb = m >> 11, t = m & (TT - 1);
                size_t base = ((size_t)(bb * HH + h) * TT + t) * 128 + dd;
                *(uint32_t*)(G_QH + base)      = pack2h((c0+b0+u0)*0.125f, (c1+b1+u1)*0.125f);
                *(uint32_t*)(G_QH + base + 64) = pack2h((c0+b0+v0)*0.125f, (c1+b1+v1)*0.125f);
                size_t base2 = base + (size_t)8 * 128;
                *(uint32_t*)(G_QH + base2)      = pack2h((c2+b0+u0)*0.125f, (c3+b1+u1)*0.125f);
                *(uint32_t*)(G_QH + base2 + 64) = pack2h((c2+b0+v0)*0.125f, (c3+b1+v1)*0.125f);
            } else if (mode == 1) {
                float b0 = bk[n], b1 = bk[n + 1];
                int bb = m >> 11, t = m & (TT - 1);
                size_t base = ((size_t)(bb * HH + h) * TT + t) * 128 + dd;
                *(uint32_t*)(G_KH + base) = pack2h(c0 + b0, c1 + b1);
                *(uint32_t*)(G_KH + base + (size_t)8 * 128) = pack2h(c2 + b0, c3 + b1);
            } else if (mode == 2) {
                float b0 = bv[n], b1 = bv[n + 1];
                int bb = m >> 11, t = m & (TT - 1);
                size_t base = ((size_t)(bb * HH + h) * TT + t) * 64 + dd;
                *(uint32_t*)(G_VH + base) = pack2h(c0 + b0, c1 + b1);
                *(uint32_t*)(G_VH + base + (size_t)8 * 64) = pack2h(c2 + b0, c3 + b1);
            } else if (mode == 3) {
                int t = m;   // 0..2047
                uint32_t p0 = pack2h(c0, c1);
                uint32_t p1 = pack2h(c2, c3);
#pragma unroll
                for (int bb = 0; bb < BB; bb++) {
                    size_t base = ((size_t)(bb * HH + h) * TT + t) * 128 + 64 + dd;
                    *(uint32_t*)(G_KH + base) = p0;
                    *(uint32_t*)(G_KH + base + (size_t)8 * 128) = p1;
                }
            } else {
                float b0 = bout[n], b1 = bout[n + 1];
                *(float2*)(out + (size_t)m * FF + n) = make_float2(c0 + b0, c1 + b1);
                *(float2*)(out + (size_t)(m + 8) * FF + n) = make_float2(c2 + b0, c3 + b1);
            }
        }
    }
}

// ---------------------------------------------------------------------------
// Single-fp16 mma.sync flash attention, ONLINE softmax, 2 CTAs/SM.
// 128-key tiles, double-buffered cp.async. Key-split z in [0,4). (R9-proven)
// ---------------------------------------------------------------------------
#define KSTR 272     // K/Q smem row stride bytes (128 f16 + 16B pad)
#define VSTR 144     // V smem row stride bytes (64 f16 + 16B pad)
#define SM_K 0
#define SM_V 34816
#define STAGE 53248
#define FLASH_SMEM (2*STAGE)   // 106496 -> 2 CTAs/SM

__device__ __forceinline__ void copy_tile_async(uint32_t stb, int bh, int s0, int tid) {
    const uint4* kh = g_kh_ + ((size_t)bh * TT + s0) * 16;
#pragma unroll
    for (int i = 0; i < 8; i++) {
        int idx = tid + i * 256;
        int r = idx >> 4, c = idx & 15;
        cpa16(stb + SM_K + r * KSTR + c * 16, kh + r * 16 + c);
    }
    const uint4* vh = g_vh_ + ((size_t)bh * TT + s0) * 8;
#pragma unroll
    for (int i = 0; i < 4; i++) {
        int idx = tid + i * 256;
        int r = idx >> 3, c = idx & 7;
        cpa16(stb + SM_V + r * VSTR + c * 16, vh + r * 8 + c);
    }
}

__global__ __launch_bounds__(256, 2) void flash_kernel()
{
    extern __shared__ char sm[];
    uint32_t sb = cvta_s(sm);

    int tid = threadIdx.x;
    int w = tid >> 5, l = tid & 31;
    int bh = blockIdx.y;
    int b = bh >> 3, h = bh & 7;
    int t0 = blockIdx.x << 7;
    int z  = blockIdx.z;
    int kbase = z << 9;

    {
        uint32_t qb = sb + STAGE;
        const uint4* qh = g_qh_ + ((size_t)bh * TT + t0) * 16;
#pragma unroll
        for (int i = 0; i < 8; i++) {
            int idx = tid + i * 256;
            int r = idx >> 4, c = idx & 15;
            cpa16(qb + r * KSTR + c * 16, qh + r * 16 + c);
        }
        CPA_COMMIT();
        copy_tile_async(sb, bh, kbase, tid);
        CPA_COMMIT();
    }
    CPA_WAIT1();
    __syncthreads();

    uint32_t Qf[8][4];
    {
        uint32_t rowa = sb + STAGE + (16 * w + (l & 15)) * KSTR + (l >> 4) * 16;
#pragma unroll
        for (int ks = 0; ks < 8; ks++) ldsm4(Qf[ks], rowa + ks * 32);
    }

    float O[8][4];
#pragma unroll
    for (int i = 0; i < 8; i++)
#pragma unroll
        for (int j = 0; j < 4; j++) O[i][j] = 0.f;
    float l_0 = 0.f, l_1 = 0.f;
    float m_0 = -1e30f, m_1 = -1e30f;

    uint32_t kB_rel = (l & 7) * KSTR + (l >> 3) * 16;
    uint32_t vB_rel = ((l & 7) + ((l >> 3) & 1) * 8) * VSTR + (l >> 4) * 16;

    for (int it = 0; it < 4; ++it) {
        __syncthreads();
        if (it < 3) {
            copy_tile_async(sb + ((it + 1) & 1) * STAGE, bh, kbase + ((it + 1) << 7), tid);
            CPA_COMMIT();
            CPA_WAIT1();
        } else {
            CPA_WAIT0();
        }
        __syncthreads();

        uint32_t stb = sb + (it & 1) * STAGE;
        uint32_t kB_lane = stb + kB_rel;
        uint32_t vB_lane = stb + vB_rel;

#pragma unroll
        for (int kb = 0; kb < 8; kb++) {
            float S0A[4] = {0.f,0.f,0.f,0.f}, S0B[4] = {0.f,0.f,0.f,0.f};
            float S1A[4] = {0.f,0.f,0.f,0.f}, S1B[4] = {0.f,0.f,0.f,0.f};
            uint32_t r0a = kB_lane + SM_K + (16 * kb) * KSTR;
            uint32_t r1a = r0a + 8 * KSTR;
#pragma unroll
            for (int j = 0; j < 4; j++) {
                uint32_t B0[4], B1[4];
                ldsm4(B0, r0a + j * 64);
                ldsm4(B1, r1a + j * 64);
                mma16(S0A, Qf[2*j],   B0[0], B0[1]);
                mma16(S1A, Qf[2*j],   B1[0], B1[1]);
                mma16(S0B, Qf[2*j+1], B0[2], B0[3]);
                mma16(S1B, Qf[2*j+1], B1[2], B1[3]);
            }

            uint32_t va = vB_lane + SM_V + (16 * kb) * VSTR;
            uint32_t V0[4], V1[4], V2[4], V3[4];
            ldsm4t(V0, va);
            ldsm4t(V1, va + 32);
            ldsm4t(V2, va + 64);
            ldsm4t(V3, va + 96);

            float s00 = S0A[0]+S0B[0], s01 = S0A[1]+S0B[1];
            float s02 = S0A[2]+S0B[2], s03 = S0A[3]+S0B[3];
            float s10 = S1A[0]+S1B[0], s11 = S1A[1]+S1B[1];
            float s12 = S1A[2]+S1B[2], s13 = S1A[3]+S1B[3];

            float mx0f = fmaxf(fmaxf(s00, s01), fmaxf(s10, s11));
            float mx1f = fmaxf(fmaxf(s02, s03), fmaxf(s12, s13));
            uint32_t pk = pack2h(mx0f, mx1f);
            {
                uint32_t o1 = __shfl_xor_sync(0xffffffffu, pk, 1);
                __half2 a = *reinterpret_cast<__half2*>(&pk);
                __half2 c = __hmax2(a, *reinterpret_cast<__half2*>(&o1));
                pk = *reinterpret_cast<uint32_t*>(&c);
                uint32_t o2 = __shfl_xor_sync(0xffffffffu, pk, 2);
                __half2 d = __hmax2(*reinterpret_cast<__half2*>(&pk),
                                    *reinterpret_cast<__half2*>(&o2));
                pk = *reinterpret_cast<uint32_t*>(&d);
            }
            float2 mxf = __half22float2(*reinterpret_cast<__half2*>(&pk));
            float mn0 = fmaxf(m_0, mxf.x), mn1 = fmaxf(m_1, mxf.y);
            bool nochg = __all_sync(0xffffffffu, (mn0 == m_0) && (mn1 == m_1));

            float p00 = ex2f((s00 - mn0) * LOG2E_F);
            float p01 = ex2f((s01 - mn0) * LOG2E_F);
            float p10 = ex2f((s10 - mn0) * LOG2E_F);
            float p11 = ex2f((s11 - mn0) * LOG2E_F);
            float p02 = ex2f((s02 - mn1) * LOG2E_F);
            float p03 = ex2f((s03 - mn1) * LOG2E_F);
            float p12 = ex2f((s12 - mn1) * LOG2E_F);
            float p13 = ex2f((s13 - mn1) * LOG2E_F);
            float sum0 = (p00 + p01) + (p10 + p11);
            float sum1 = (p02 + p03) + (p12 + p13);

            if (nochg) {
                l_0 += sum0;
                l_1 += sum1;
            } else {
                float c0 = ex2f((m_0 - mn0) * LOG2E_F);
                float c1 = ex2f((m_1 - mn1) * LOG2E_F);
                l_0 = l_0 * c0 + sum0;
                l_1 = l_1 * c1 + sum1;
                m_0 = mn0; m_1 = mn1;
#pragma unroll
                for (int nd = 0; nd < 8; nd++) {
                    O[nd][0] *= c0; O[nd][1] *= c0;
                    O[nd][2] *= c1; O[nd][3] *= c1;
                }
            }

            uint32_t P[4];
            P[0] = pack2h(p00, p01);
            P[1] = pack2h(p02, p03);
            P[2] = pack2h(p10, p11);
            P[3] = pack2h(p12, p13);

            mma16(O[0], P, V0[0], V0[1]);
            mma16(O[1], P, V0[2], V0[3]);
            mma16(O[2], P, V1[0], V1[1]);
            mma16(O[3], P, V1[2], V1[3]);
            mma16(O[4], P, V2[0], V2[1]);
            mma16(O[5], P, V2[2], V2[3]);
            mma16(O[6], P, V3[0], V3[1]);
            mma16(O[7], P, V3[2], V3[3]);
        }
    }

    l_0 += __shfl_xor_sync(0xffffffffu, l_0, 1);
    l_0 += __shfl_xor_sync(0xffffffffu, l_0, 2);
    l_1 += __shfl_xor_sync(0xffffffffu, l_1, 1);
    l_1 += __shfl_xor_sync(0xffffffffu, l_1, 2);

    float* po = g_po + (size_t)z * MM * FF;
    float* ls = g_ls + z * 32 * TT;
    float* lm = g_lm + z * 32 * TT;

    int row0 = t0 + 16 * w + (l >> 2);
    if ((l & 3) == 0) {
        ls[bh * TT + row0] = l_0;      lm[bh * TT + row0] = m_0;
        ls[bh * TT + row0 + 8] = l_1;  lm[bh * TT + row0 + 8] = m_1;
    }
    float* d0 = po + ((size_t)(b * TT + row0)) * FF + (h << 6) + ((l & 3) << 1);
    float* d1 = d0 + (size_t)8 * FF;
#pragma unroll
    for (int nd = 0; nd < 8; nd++) {
        *(float2*)(d0 + nd * 8) = make_float2(O[nd][0], O[nd][1]);
        *(float2*)(d1 + nd * 8) = make_float2(O[nd][2], O[nd][3]);
    }
}

// ---------------------------------------------------------------------------
// combine NZ partials with (m,l) merge -> hi/lo fp16 ao (feeds OUT gemm)
// ---------------------------------------------------------------------------
__global__ __launch_bounds__(256) void combine_kernel()
{
    int idx = blockIdx.x * 256 + threadIdx.x;   // float4 units over MM*FF
    int m = idx >> 7;
    int c = (idx & 127) << 2;
    int h = c >> 6;
    int b = m >> 11, t = m & (TT - 1);
    int r = (b * HH + h) * TT + t;

    float mz[NZ];
    float M = -1e30f;
#pragma unroll
    for (int zz = 0; zz < NZ; zz++) { mz[zz] = g_lm[zz * 32 * TT + r]; M = fmaxf(M, mz[zz]); }
    float L = 0.f;
    float wz[NZ];
#pragma unroll
    for (int zz = 0; zz < NZ; zz++) {
        wz[zz] = ex2f((mz[zz] - M) * LOG2E_F);
        L += g_ls[zz * 32 * TT + r] * wz[zz];
    }
    float inv = 1.f / L;

    float4 acc = make_float4(0.f, 0.f, 0.f, 0.f);
#pragma unroll
    for (int zz = 0; zz < NZ; zz++) {
        float4 o = *(const float4*)(g_po + (size_t)zz * MM * FF + (size_t)idx * 4);
        acc.x += o.x * wz[zz]; acc.y += o.y * wz[zz];
        acc.z += o.z * wz[zz]; acc.w += o.w * wz[zz];
    }
    acc.x *= inv; acc.y *= inv; acc.z *= inv; acc.w *= inv;

    uint32_t h0 = pack2h(acc.x, acc.y);
    uint32_t h1 = pack2h(acc.z, acc.w);
    float2 f0 = __half22float2(*reinterpret_cast<__half2*>(&h0));
    float2 f1 = __half22float2(*reinterpret_cast<__half2*>(&h1));
    ((uint2*)g_aoh_)[idx] = make_uint2(h0, h1);
    ((uint2*)g_aol_)[idx] =
        make_uint2(pack2h(acc.x - f0.x, acc.y - f0.y), pack2h(acc.z - f1.x, acc.w - f1.y));
}

// ---------------------------------------------------------------------------
extern "C" void kernel_launch(void* const* d_in, const int* in_sizes, int n_in,
                              void* d_out, int out_size)
{
    const float* x    = (const float*)d_in[0];
    const float* pe   = (const float*)d_in[1];
    const float* Wq   = (const float*)d_in[2];
    const float* bq   = (const float*)d_in[3];
    const float* Wk   = (const float*)d_in[4];
    const float* bk   = (const float*)d_in[5];
    const float* Wv   = (const float*)d_in[6];
    const float* bv   = (const float*)d_in[7];
    const float* Wpos = (const float*)d_in[8];
    const float* Wout = (const float*)d_in[9];
    const float* bout = (const float*)d_in[10];
    const float* pbu  = (const float*)d_in[11];
    const float* pbv  = (const float*)d_in[12];
    float* out = (float*)d_out;

    cudaFuncSetAttribute(flash_kernel, cudaFuncAttributeMaxDynamicSharedMemorySize, FLASH_SMEM);
    cudaFuncSetAttribute(proj_kernel, cudaFuncAttributeMaxDynamicSharedMemorySize, GEMM_SMEM);

    dim3 blk(256);
    // #0: fp32 -> fp16 conversions (x hi/lo, pe hi/lo, 5 weights)
    conv_kernel<<<dim3(512, 7), blk>>>(x, pe, Wq, Wk, Wv, Wpos, Wout);
    // #1: fused QKV projections (tensor cores)
    proj_kernel<<<dim3(8, 64, 3), blk, GEMM_SMEM>>>(-1, nullptr, bq, bk, bv, bout, pbu, pbv);
    // #2: positional projection
    proj_kernel<<<dim3(8, 16, 1), blk, GEMM_SMEM>>>(3, nullptr, bq, bk, bv, bout, pbu, pbv);
    // #3: flash attention
    flash_kernel<<<dim3(TT / 128, BB * HH, NZ), blk, FLASH_SMEM>>>();
    // #4: combine split-K partials -> fp16 hi/lo ao
    combine_kernel<<<dim3((MM * FF) / 1024), blk>>>();
    // #5: output projection (tensor cores) -> d_out
    proj_kernel<<<dim3(8, 64, 1), blk, GEMM_SMEM>>>(4, out, bq, bk, bv, bout, pbu, pbv);
}

// round 11
// speedup vs baseline: 6.8143x; 1.0693x over previous
#include <cuda_runtime.h>
#include <cuda_bf16.h>
#include <cuda_fp16.h>
#include <cstdint>

#define BB 4
#define TT 2048
#define HH 8
#define FF 512
#define MM (BB*TT)   // 8192
#define NZ 4         // key-split factor

// ---------------------------------------------------------------------------
// Global scratch (device globals; uint4 for 16B alignment)
// ---------------------------------------------------------------------------
__device__ uint4 g_qh_[1048576];   // q_cat fp16: [bh=32][t=2048][128] (scaled 0.125, biases fused)
__device__ uint4 g_kh_[1048576];   // k_cat fp16: [bh][t][0:64]=k, [64:128]=p
__device__ uint4 g_vh_[524288];    // V fp16: [bh][t][64]
__device__ uint4 g_xh_[524288];    // x hi fp16 [8192][512]
__device__ uint4 g_xl_[524288];    // x lo fp16
__device__ uint4 g_peh_[131072];   // pos_emb hi fp16 [2048][512]
__device__ uint4 g_pel_[131072];   // pos_emb lo fp16
__device__ uint4 g_wh_[163840];    // 5 weights fp16 [5][512][512] (Wq,Wk,Wv,Wpos,Wout)
__device__ uint4 g_aoh_[524288];   // attention-out fp16 [8192][512] (single precision term)
__device__ float g_po[(size_t)NZ*MM*FF];  // partial O per z, unnormalized
__device__ float g_ls[NZ*32*TT];          // partial row sums
__device__ float g_lm[NZ*32*TT];          // partial row maxes

#define G_QH ((__half*)g_qh_)
#define G_KH ((__half*)g_kh_)
#define G_VH ((__half*)g_vh_)

// ---------------------------------------------------------------------------
__device__ __forceinline__ uint32_t cvta_s(const void* p) {
    return (uint32_t)__cvta_generic_to_shared(p);
}
__device__ __forceinline__ float ex2f(float x) {
    float r; asm("ex2.approx.ftz.f32 %0, %1;" : "=f"(r) : "f"(x)); return r;
}
// pack two f32 -> f16x2 word: first arg -> low half, second -> high half
__device__ __forceinline__ uint32_t pack2h(float lo, float hi) {
    uint32_t r; asm("cvt.rn.f16x2.f32 %0, %1, %2;" : "=r"(r) : "f"(hi), "f"(lo)); return r;
}

__device__ __forceinline__ void ldsm4(uint32_t r[4], uint32_t a) {
    asm volatile("ldmatrix.sync.aligned.m8n8.x4.shared.b16 {%0,%1,%2,%3}, [%4];"
                 : "=r"(r[0]), "=r"(r[1]), "=r"(r[2]), "=r"(r[3]) : "r"(a));
}
__device__ __forceinline__ void ldsm4t(uint32_t r[4], uint32_t a) {
    asm volatile("ldmatrix.sync.aligned.m8n8.x4.trans.shared.b16 {%0,%1,%2,%3}, [%4];"
                 : "=r"(r[0]), "=r"(r[1]), "=r"(r[2]), "=r"(r[3]) : "r"(a));
}
// fp16 mma, f32 accumulate. Non-volatile: pure register op.
__device__ __forceinline__ void mma16(float c[4], const uint32_t a[4], uint32_t b0, uint32_t b1) {
    asm("mma.sync.aligned.m16n8k16.row.col.f32.f16.f16.f32 "
        "{%0,%1,%2,%3}, {%4,%5,%6,%7}, {%8,%9}, {%0,%1,%2,%3};"
        : "+f"(c[0]), "+f"(c[1]), "+f"(c[2]), "+f"(c[3])
        : "r"(a[0]), "r"(a[1]), "r"(a[2]), "r"(a[3]), "r"(b0), "r"(b1));
}

__device__ __forceinline__ void cpa16(uint32_t d, const void* s) {
    asm volatile("cp.async.cg.shared.global [%0], [%1], 16;" :: "r"(d), "l"(s) : "memory");
}
#define CPA_COMMIT() asm volatile("cp.async.commit_group;" ::: "memory")
#define CPA_WAIT1()  asm volatile("cp.async.wait_group 1;" ::: "memory")
#define CPA_WAIT0()  asm volatile("cp.async.wait_group 0;" ::: "memory")

#define LOG2E_F 1.4426950408889634f

// ---------------------------------------------------------------------------
// conv_kernel: fp32 -> fp16 conversions.
// z=0: x -> g_xh/g_xl (hi/lo). z=1: pos_emb -> g_peh/g_pel.
// z=2..6: Wq,Wk,Wv,Wpos,Wout -> g_wh (single fp16).
// ---------------------------------------------------------------------------
__global__ __launch_bounds__(256) void conv_kernel(
    const float* __restrict__ x, const float* __restrict__ pe,
    const float* __restrict__ Wq, const float* __restrict__ Wk,
    const float* __restrict__ Wv, const float* __restrict__ Wpos,
    const float* __restrict__ Wout)
{
    int z = blockIdx.y;
    int stride = gridDim.x * 256;
    if (z == 0 || z == 1) {
        int n = (z == 0) ? 1048576 : 262144;
        const float4* src = (const float4*)((z == 0) ? x : pe);
        uint2* dh = (uint2*)((z == 0) ? g_xh_ : g_peh_);
        uint2* dl = (uint2*)((z == 0) ? g_xl_ : g_pel_);
        for (int i = blockIdx.x * 256 + threadIdx.x; i < n; i += stride) {
            float4 v = src[i];
            uint32_t h0 = pack2h(v.x, v.y);
            uint32_t h1 = pack2h(v.z, v.w);
            float2 f0 = __half22float2(*reinterpret_cast<__half2*>(&h0));
            float2 f1 = __half22float2(*reinterpret_cast<__half2*>(&h1));
            dh[i] = make_uint2(h0, h1);
            dl[i] = make_uint2(pack2h(v.x - f0.x, v.y - f0.y), pack2h(v.z - f1.x, v.w - f1.y));
        }
    } else {
        int widx = z - 2;
        const float* Wsel = (widx == 0) ? Wq : (widx == 1) ? Wk : (widx == 2) ? Wv
                          : (widx == 3) ? Wpos : Wout;
        const float4* src = (const float4*)Wsel;
        uint2* dh = (uint2*)g_wh_ + (size_t)widx * 65536;
        for (int i = blockIdx.x * 256 + threadIdx.x; i < 65536; i += stride) {
            float4 v = src[i];
            dh[i] = make_uint2(pack2h(v.x, v.y), pack2h(v.z, v.w));
        }
    }
}

// ---------------------------------------------------------------------------
// fp16 tensor-core projection GEMM: C[m,n] = (Ah[+Al])[m,:] . W[n,:]
// CTA: 128 rows x 64 cols, 8 warps (warp w: rows 16w..16w+15).
// K=512 in 8 chunks of 64, double-buffered cp.async.
// mode (blockIdx.z if arg<0): 0=Q, 1=K, 2=V, 3=P, 4=OUT — scatter epilogues.
// mode 4 is single-term (A = g_aoh only).
// ---------------------------------------------------------------------------
#define KSTR2 144         // 64 f16 + 16B pad
#define SM_AH 0
#define SM_AL 18432
#define SM_B  36864
#define GSTAGE 46080
#define GEMM_SMEM (2*GSTAGE)   // 92160 -> 2 CTAs/SM

__device__ __forceinline__ void copy_gtile(
    uint32_t stb, const uint4* Ah, const uint4* Al, const uint4* Wb,
    int m0, int n0, int k08, int tid, bool two_term)
{
#pragma unroll
    for (int i = 0; i < 4; i++) {
        int idx = tid + i * 256;          // 1024: 128 rows x 8 uint4
        int r = idx >> 3, c = idx & 7;
        size_t so = (size_t)(m0 + r) * 64 + k08 + c;
        cpa16(stb + SM_AH + r * KSTR2 + c * 16, Ah + so);
        if (two_term) cpa16(stb + SM_AL + r * KSTR2 + c * 16, Al + so);
    }
#pragma unroll
    for (int i = 0; i < 2; i++) {
        int idx = tid + i * 256;          // 512: 64 rows x 8 uint4
        int r = idx >> 3, c = idx & 7;
        cpa16(stb + SM_B + r * KSTR2 + c * 16, Wb + (size_t)(n0 + r) * 64 + k08 + c);
    }
}

__global__ __launch_bounds__(256, 2) void proj_kernel(
    int mode_arg, float* __restrict__ out,
    const float* __restrict__ bq, const float* __restrict__ bk,
    const float* __restrict__ bv, const float* __restrict__ bout,
    const float* __restrict__ pbu, const float* __restrict__ pbv)
{
    extern __shared__ char sm[];
    uint32_t sb = cvta_s(sm);

    int tid = threadIdx.x;
    int w = tid >> 5, l = tid & 31;
    int mode = (mode_arg < 0) ? (int)blockIdx.z : mode_arg;
    int m0 = blockIdx.y << 7, n0 = blockIdx.x << 6;
    if (mode == 3 && m0 >= 2048) return;   // P has only 2048 rows

    bool two_term = (mode != 4);
    const uint4* Ah = (mode <= 2) ? g_xh_ : (mode == 3) ? g_peh_ : g_aoh_;
    const uint4* Al = (mode <= 2) ? g_xl_ : g_pel_;   // unused for mode 4
    int widx = (mode <= 2) ? mode : ((mode == 3) ? 3 : 4);
    const uint4* Wb = g_wh_ + (size_t)widx * 32768;

    // prologue: chunks 0,1
    copy_gtile(sb, Ah, Al, Wb, m0, n0, 0, tid, two_term);  CPA_COMMIT();
    copy_gtile(sb + GSTAGE, Ah, Al, Wb, m0, n0, 8, tid, two_term);  CPA_COMMIT();

    float acc[4][2][4];
#pragma unroll
    for (int a = 0; a < 4; a++)
#pragma unroll
        for (int bq2 = 0; bq2 < 2; bq2++)
#pragma unroll
            for (int c = 0; c < 4; c++) acc[a][bq2][c] = 0.f;

    uint32_t rowa_rel = (16 * w + (l & 15)) * KSTR2 + (l >> 4) * 16;
    uint32_t kB_rel   = (l & 7) * KSTR2 + (l >> 3) * 16;

    for (int ch = 0; ch < 8; ch++) {
        if (ch < 6) { CPA_WAIT1(); } else { CPA_WAIT0(); }
        __syncthreads();

        uint32_t stb = sb + (ch & 1) * GSTAGE;

        uint32_t Afh[4][4], Afl[4][4];
#pragma unroll
        for (int ks = 0; ks < 4; ks++) {
            ldsm4(Afh[ks], stb + SM_AH + rowa_rel + ks * 32);
            if (two_term) ldsm4(Afl[ks], stb + SM_AL + rowa_rel + ks * 32);
        }
#pragma unroll
        for (int nb = 0; nb < 4; nb++) {
            uint32_t r0 = stb + SM_B + (16 * nb) * KSTR2 + kB_rel;
            uint32_t r1 = r0 + 8 * KSTR2;
#pragma unroll
            for (int j = 0; j < 2; j++) {
                uint32_t B0[4], B1[4];
                ldsm4(B0, r0 + j * 64);
                ldsm4(B1, r1 + j * 64);
                mma16(acc[nb][0], Afh[2*j],   B0[0], B0[1]);
                mma16(acc[nb][1], Afh[2*j],   B1[0], B1[1]);
                mma16(acc[nb][0], Afh[2*j+1], B0[2], B0[3]);
                mma16(acc[nb][1], Afh[2*j+1], B1[2], B1[3]);
                if (two_term) {
                    mma16(acc[nb][0], Afl[2*j],   B0[0], B0[1]);
                    mma16(acc[nb][1], Afl[2*j],   B1[0], B1[1]);
                    mma16(acc[nb][0], Afl[2*j+1], B0[2], B0[3]);
                    mma16(acc[nb][1], Afl[2*j+1], B1[2], B1[3]);
                }
            }
        }
        __syncthreads();
        if (ch + 2 < 8) {
            copy_gtile(sb + (ch & 1) * GSTAGE, Ah, Al, Wb, m0, n0, (ch + 2) * 8, tid, two_term);
            CPA_COMMIT();
        }
    }

    // ---- epilogue: scatter per mode ----
    int row0 = 16 * w + (l >> 2);
    int m = m0 + row0;          // rows m and m+8
    int colb = (l & 3) << 1;

#pragma unroll
    for (int nb = 0; nb < 4; nb++) {
#pragma unroll
        for (int half = 0; half < 2; half++) {
            int n = n0 + nb * 16 + half * 8 + colb;   // n, n+1
            float c0 = acc[nb][half][0], c1 = acc[nb][half][1];
            float c2 = acc[nb][half][2], c3 = acc[nb][half][3];
            int h = n >> 6, dd = n & 63;

            if (mode == 0) {
                float b0 = bq[n], b1 = bq[n + 1];
                float u0 = pbu[n], u1 = pbu[n + 1];
                float v0 = pbv[n], v1 = pbv[n + 1];
                int bb = m >> 11, t = m & (TT - 1);
                size_t base = ((size_t)(bb * HH + h) * TT + t) * 128 + dd;
                *(uint32_t*)(G_QH + base)      = pack2h((c0+b0+u0)*0.125f, (c1+b1+u1)*0.125f);
                *(uint32_t*)(G_QH + base + 64) = pack2h((c0+b0+v0)*0.125f, (c1+b1+v1)*0.125f);
                size_t base2 = base + (size_t)8 * 128;
                *(uint32_t*)(G_QH + base2)      = pack2h((c2+b0+u0)*0.125f, (c3+b1+u1)*0.125f);
                *(uint32_t*)(G_QH + base2 + 64) = pack2h((c2+b0+v0)*0.125f, (c3+b1+v1)*0.125f);
            } else if (mode == 1) {
                float b0 = bk[n], b1 = bk[n + 1];
                int bb = m >> 11, t = m & (TT - 1);
                size_t base = ((size_t)(bb * HH + h) * TT + t) * 128 + dd;
                *(uint32_t*)(G_KH + base) = pack2h(c0 + b0, c1 + b1);
                *(uint32_t*)(G_KH + base + (size_t)8 * 128) = pack2h(c2 + b0, c3 + b1);
            } else if (mode == 2) {
                float b0 = bv[n], b1 = bv[n + 1];
                int bb = m >> 11, t = m & (TT - 1);
                size_t base = ((size_t)(bb * HH + h) * TT + t) * 64 + dd;
                *(uint32_t*)(G_VH + base) = pack2h(c0 + b0, c1 + b1);
                *(uint32_t*)(G_VH + base + (size_t)8 * 64) = pack2h(c2 + b0, c3 + b1);
            } else if (mode == 3) {
                int t = m;   // 0..2047
                uint32_t p0 = pack2h(c0, c1);
                uint32_t p1 = pack2h(c2, c3);
#pragma unroll
                for (int bb = 0; bb < BB; bb++) {
                    size_t base = ((size_t)(bb * HH + h) * TT + t) * 128 + 64 + dd;
                    *(uint32_t*)(G_KH + base) = p0;
                    *(uint32_t*)(G_KH + base + (size_t)8 * 128) = p1;
                }
            } else {
                float b0 = bout[n], b1 = bout[n + 1];
                *(float2*)(out + (size_t)m * FF + n) = make_float2(c0 + b0, c1 + b1);
                *(float2*)(out + (size_t)(m + 8) * FF + n) = make_float2(c2 + b0, c3 + b1);
            }
        }
    }
}

// ---------------------------------------------------------------------------
// Single-fp16 mma.sync flash attention, ONLINE softmax, 2 CTAs/SM.
// 128-key tiles, double-buffered cp.async. Key-split z in [0,4). (R9-proven)
// ---------------------------------------------------------------------------
#define KSTR 272     // K/Q smem row stride bytes (128 f16 + 16B pad)
#define VSTR 144     // V smem row stride bytes (64 f16 + 16B pad)
#define SM_K 0
#define SM_V 34816
#define STAGE 53248
#define FLASH_SMEM (2*STAGE)   // 106496 -> 2 CTAs/SM

__device__ __forceinline__ void copy_tile_async(uint32_t stb, int bh, int s0, int tid) {
    const uint4* kh = g_kh_ + ((size_t)bh * TT + s0) * 16;
#pragma unroll
    for (int i = 0; i < 8; i++) {
        int idx = tid + i * 256;
        int r = idx >> 4, c = idx & 15;
        cpa16(stb + SM_K + r * KSTR + c * 16, kh + r * 16 + c);
    }
    const uint4* vh = g_vh_ + ((size_t)bh * TT + s0) * 8;
#pragma unroll
    for (int i = 0; i < 4; i++) {
        int idx = tid + i * 256;
        int r = idx >> 3, c = idx & 7;
        cpa16(stb + SM_V + r * VSTR + c * 16, vh + r * 8 + c);
    }
}

__global__ __launch_bounds__(256, 2) void flash_kernel()
{
    extern __shared__ char sm[];
    uint32_t sb = cvta_s(sm);

    int tid = threadIdx.x;
    int w = tid >> 5, l = tid & 31;
    int bh = blockIdx.y;
    int b = bh >> 3, h = bh & 7;
    int t0 = blockIdx.x << 7;
    int z  = blockIdx.z;
    int kbase = z << 9;

    {
        uint32_t qb = sb + STAGE;
        const uint4* qh = g_qh_ + ((size_t)bh * TT + t0) * 16;
#pragma unroll
        for (int i = 0; i < 8; i++) {
            int idx = tid + i * 256;
            int r = idx >> 4, c = idx & 15;
            cpa16(qb + r * KSTR + c * 16, qh + r * 16 + c);
        }
        CPA_COMMIT();
        copy_tile_async(sb, bh, kbase, tid);
        CPA_COMMIT();
    }
    CPA_WAIT1();
    __syncthreads();

    uint32_t Qf[8][4];
    {
        uint32_t rowa = sb + STAGE + (16 * w + (l & 15)) * KSTR + (l >> 4) * 16;
#pragma unroll
        for (int ks = 0; ks < 8; ks++) ldsm4(Qf[ks], rowa + ks * 32);
    }

    float O[8][4];
#pragma unroll
    for (int i = 0; i < 8; i++)
#pragma unroll
        for (int j = 0; j < 4; j++) O[i][j] = 0.f;
    float l_0 = 0.f, l_1 = 0.f;
    float m_0 = -1e30f, m_1 = -1e30f;

    uint32_t kB_rel = (l & 7) * KSTR + (l >> 3) * 16;
    uint32_t vB_rel = ((l & 7) + ((l >> 3) & 1) * 8) * VSTR + (l >> 4) * 16;

    for (int it = 0; it < 4; ++it) {
        __syncthreads();
        if (it < 3) {
            copy_tile_async(sb + ((it + 1) & 1) * STAGE, bh, kbase + ((it + 1) << 7), tid);
            CPA_COMMIT();
            CPA_WAIT1();
        } else {
            CPA_WAIT0();
        }
        __syncthreads();

        uint32_t stb = sb + (it & 1) * STAGE;
        uint32_t kB_lane = stb + kB_rel;
        uint32_t vB_lane = stb + vB_rel;

#pragma unroll
        for (int kb = 0; kb < 8; kb++) {
            float S0A[4] = {0.f,0.f,0.f,0.f}, S0B[4] = {0.f,0.f,0.f,0.f};
            float S1A[4] = {0.f,0.f,0.f,0.f}, S1B[4] = {0.f,0.f,0.f,0.f};
            uint32_t r0a = kB_lane + SM_K + (16 * kb) * KSTR;
            uint32_t r1a = r0a + 8 * KSTR;
#pragma unroll
            for (int j = 0; j < 4; j++) {
                uint32_t B0[4], B1[4];
                ldsm4(B0, r0a + j * 64);
                ldsm4(B1, r1a + j * 64);
                mma16(S0A, Qf[2*j],   B0[0], B0[1]);
                mma16(S1A, Qf[2*j],   B1[0], B1[1]);
                mma16(S0B, Qf[2*j+1], B0[2], B0[3]);
                mma16(S1B, Qf[2*j+1], B1[2], B1[3]);
            }

            uint32_t va = vB_lane + SM_V + (16 * kb) * VSTR;
            uint32_t V0[4], V1[4], V2[4], V3[4];
            ldsm4t(V0, va);
            ldsm4t(V1, va + 32);
            ldsm4t(V2, va + 64);
            ldsm4t(V3, va + 96);

            float s00 = S0A[0]+S0B[0], s01 = S0A[1]+S0B[1];
            float s02 = S0A[2]+S0B[2], s03 = S0A[3]+S0B[3];
            float s10 = S1A[0]+S1B[0], s11 = S1A[1]+S1B[1];
            float s12 = S1A[2]+S1B[2], s13 = S1A[3]+S1B[3];

            float mx0f = fmaxf(fmaxf(s00, s01), fmaxf(s10, s11));
            float mx1f = fmaxf(fmaxf(s02, s03), fmaxf(s12, s13));
            uint32_t pk = pack2h(mx0f, mx1f);
            {
                uint32_t o1 = __shfl_xor_sync(0xffffffffu, pk, 1);
                __half2 a = *reinterpret_cast<__half2*>(&pk);
                __half2 c = __hmax2(a, *reinterpret_cast<__half2*>(&o1));
                pk = *reinterpret_cast<uint32_t*>(&c);
                uint32_t o2 = __shfl_xor_sync(0xffffffffu, pk, 2);
                __half2 d = __hmax2(*reinterpret_cast<__half2*>(&pk),
                                    *reinterpret_cast<__half2*>(&o2));
                pk = *reinterpret_cast<uint32_t*>(&d);
            }
            float2 mxf = __half22float2(*reinterpret_cast<__half2*>(&pk));
            float mn0 = fmaxf(m_0, mxf.x), mn1 = fmaxf(m_1, mxf.y);
            bool nochg = __all_sync(0xffffffffu, (mn0 == m_0) && (mn1 == m_1));

            float p00 = ex2f((s00 - mn0) * LOG2E_F);
            float p01 = ex2f((s01 - mn0) * LOG2E_F);
            float p10 = ex2f((s10 - mn0) * LOG2E_F);
            float p11 = ex2f((s11 - mn0) * LOG2E_F);
            float p02 = ex2f((s02 - mn1) * LOG2E_F);
            float p03 = ex2f((s03 - mn1) * LOG2E_F);
            float p12 = ex2f((s12 - mn1) * LOG2E_F);
            float p13 = ex2f((s13 - mn1) * LOG2E_F);
            float sum0 = (p00 + p01) + (p10 + p11);
            float sum1 = (p02 + p03) + (p12 + p13);

            if (nochg) {
                l_0 += sum0;
                l_1 += sum1;
            } else {
                float c0 = ex2f((m_0 - mn0) * LOG2E_F);
                float c1 = ex2f((m_1 - mn1) * LOG2E_F);
                l_0 = l_0 * c0 + sum0;
                l_1 = l_1 * c1 + sum1;
                m_0 = mn0; m_1 = mn1;
#pragma unroll
                for (int nd = 0; nd < 8; nd++) {
                    O[nd][0] *= c0; O[nd][1] *= c0;
                    O[nd][2] *= c1; O[nd][3] *= c1;
                }
            }

            uint32_t P[4];
            P[0] = pack2h(p00, p01);
            P[1] = pack2h(p02, p03);
            P[2] = pack2h(p10, p11);
            P[3] = pack2h(p12, p13);

            mma16(O[0], P, V0[0], V0[1]);
            mma16(O[1], P, V0[2], V0[3]);
            mma16(O[2], P, V1[0], V1[1]);
            mma16(O[3], P, V1[2], V1[3]);
            mma16(O[4], P, V2[0], V2[1]);
            mma16(O[5], P, V2[2], V2[3]);
            mma16(O[6], P, V3[0], V3[1]);
            mma16(O[7], P, V3[2], V3[3]);
        }
    }

    l_0 += __shfl_xor_sync(0xffffffffu, l_0, 1);
    l_0 += __shfl_xor_sync(0xffffffffu, l_0, 2);
    l_1 += __shfl_xor_sync(0xffffffffu, l_1, 1);
    l_1 += __shfl_xor_sync(0xffffffffu, l_1, 2);

    float* po = g_po + (size_t)z * MM * FF;
    float* ls = g_ls + z * 32 * TT;
    float* lm = g_lm + z * 32 * TT;

    int row0 = t0 + 16 * w + (l >> 2);
    if ((l & 3) == 0) {
        ls[bh * TT + row0] = l_0;      lm[bh * TT + row0] = m_0;
        ls[bh * TT + row0 + 8] = l_1;  lm[bh * TT + row0 + 8] = m_1;
    }
    float* d0 = po + ((size_t)(b * TT + row0)) * FF + (h << 6) + ((l & 3) << 1);
    float* d1 = d0 + (size_t)8 * FF;
#pragma unroll
    for (int nd = 0; nd < 8; nd++) {
        *(float2*)(d0 + nd * 8) = make_float2(O[nd][0], O[nd][1]);
        *(float2*)(d1 + nd * 8) = make_float2(O[nd][2], O[nd][3]);
    }
}

// ---------------------------------------------------------------------------
// combine NZ partials with (m,l) merge -> single fp16 ao (feeds OUT gemm)
// ---------------------------------------------------------------------------
__global__ __launch_bounds__(256) void combine_kernel()
{
    int idx = blockIdx.x * 256 + threadIdx.x;   // float4 units over MM*FF
    int m = idx >> 7;
    int c = (idx & 127) << 2;
    int h = c >> 6;
    int b = m >> 11, t = m & (TT - 1);
    int r = (b * HH + h) * TT + t;

    float mz[NZ];
    float M = -1e30f;
#pragma unroll
    for (int zz = 0; zz < NZ; zz++) { mz[zz] = g_lm[zz * 32 * TT + r]; M = fmaxf(M, mz[zz]); }
    float L = 0.f;
    float wz[NZ];
#pragma unroll
    for (int zz = 0; zz < NZ; zz++) {
        wz[zz] = ex2f((mz[zz] - M) * LOG2E_F);
        L += g_ls[zz * 32 * TT + r] * wz[zz];
    }
    float inv = 1.f / L;

    float4 acc = make_float4(0.f, 0.f, 0.f, 0.f);
#pragma unroll
    for (int zz = 0; zz < NZ; zz++) {
        float4 o = *(const float4*)(g_po + (size_t)zz * MM * FF + (size_t)idx * 4);
        acc.x += o.x * wz[zz]; acc.y += o.y * wz[zz];
        acc.z += o.z * wz[zz]; acc.w += o.w * wz[zz];
    }
    ((uint2*)g_aoh_)[idx] = make_uint2(pack2h(acc.x * inv, acc.y * inv),
                                       pack2h(acc.z * inv, acc.w * inv));
}

// ---------------------------------------------------------------------------
extern "C" void kernel_launch(void* const* d_in, const int* in_sizes, int n_in,
                              void* d_out, int out_size)
{
    const float* x    = (const float*)d_in[0];
    const float* pe   = (const float*)d_in[1];
    const float* Wq   = (const float*)d_in[2];
    const float* bq   = (const float*)d_in[3];
    const float* Wk   = (const float*)d_in[4];
    const float* bk   = (const float*)d_in[5];
    const float* Wv   = (const float*)d_in[6];
    const float* bv   = (const float*)d_in[7];
    const float* Wpos = (const float*)d_in[8];
    const float* Wout = (const float*)d_in[9];
    const float* bout = (const float*)d_in[10];
    const float* pbu  = (const float*)d_in[11];
    const float* pbv  = (const float*)d_in[12];
    float* out = (float*)d_out;

    cudaFuncSetAttribute(flash_kernel, cudaFuncAttributeMaxDynamicSharedMemorySize, FLASH_SMEM);
    cudaFuncSetAttribute(proj_kernel, cudaFuncAttributeMaxDynamicSharedMemorySize, GEMM_SMEM);

    dim3 blk(256);
    // #0: fp32 -> fp16 conversions (x hi/lo, pe hi/lo, 5 weights)
    conv_kernel<<<dim3(512, 7), blk>>>(x, pe, Wq, Wk, Wv, Wpos, Wout);
    // #1: fused QKV + P projections (tensor cores; z=3 = P, masked to y<16)
    proj_kernel<<<dim3(8, 64, 4), blk, GEMM_SMEM>>>(-1, nullptr, bq, bk, bv, bout, pbu, pbv);
    // #2: spacer keeps flash at the profiler's capture slot
    // (removed; flash is launch #2 now — capture slot shift is acceptable)
    // #2: flash attention
    flash_kernel<<<dim3(TT / 128, BB * HH, NZ), blk, FLASH_SMEM>>>();
    // #3: combine split-K partials -> fp16 ao
    combine_kernel<<<dim3((MM * FF) / 1024), blk>>>();
    // #4: output projection (tensor cores, single-term A) -> d_out
    proj_kernel<<<dim3(8, 64, 1), blk, GEMM_SMEM>>>(4, out, bq, bk, bv, bout, pbu, pbv);
}

// round 12
// speedup vs baseline: 7.1190x; 1.0447x over previous
#include <cuda_runtime.h>
#include <cuda_bf16.h>
#include <cuda_fp16.h>
#include <cstdint>

#define BB 4
#define TT 2048
#define HH 8
#define FF 512
#define MM (BB*TT)   // 8192
#define NZ 4         // key-split factor

// ---------------------------------------------------------------------------
// Global scratch (device globals; uint4 for 16B alignment)
// ---------------------------------------------------------------------------
__device__ uint4 g_qh_[1048576];   // q_cat fp16: [bh=32][t=2048][128] (scaled 0.125, biases fused)
__device__ uint4 g_kh_[1048576];   // k_cat fp16: [bh][t][0:64]=k, [64:128]=p
__device__ uint4 g_vh_[524288];    // V fp16: [bh][t][64]
__device__ uint4 g_xh_[524288];    // x fp16 [8192][512] (single term)
__device__ uint4 g_peh_[131072];   // pos_emb hi fp16 [2048][512]
__device__ uint4 g_pel_[131072];   // pos_emb lo fp16
__device__ uint4 g_wh_[163840];    // 5 weights fp16 [5][512][512] (Wq,Wk,Wv,Wpos,Wout)
__device__ uint4 g_aoh_[524288];   // attention-out fp16 [8192][512] (single term)
__device__ float g_po[(size_t)NZ*MM*FF];  // partial O per z, unnormalized
__device__ float g_ls[NZ*32*TT];          // partial row sums
__device__ float g_lm[NZ*32*TT];          // partial row maxes

#define G_QH ((__half*)g_qh_)
#define G_KH ((__half*)g_kh_)
#define G_VH ((__half*)g_vh_)

// ---------------------------------------------------------------------------
__device__ __forceinline__ uint32_t cvta_s(const void* p) {
    return (uint32_t)__cvta_generic_to_shared(p);
}
__device__ __forceinline__ float ex2f(float x) {
    float r; asm("ex2.approx.ftz.f32 %0, %1;" : "=f"(r) : "f"(x)); return r;
}
// pack two f32 -> f16x2 word: first arg -> low half, second -> high half
__device__ __forceinline__ uint32_t pack2h(float lo, float hi) {
    uint32_t r; asm("cvt.rn.f16x2.f32 %0, %1, %2;" : "=r"(r) : "f"(hi), "f"(lo)); return r;
}

__device__ __forceinline__ void ldsm4(uint32_t r[4], uint32_t a) {
    asm volatile("ldmatrix.sync.aligned.m8n8.x4.shared.b16 {%0,%1,%2,%3}, [%4];"
                 : "=r"(r[0]), "=r"(r[1]), "=r"(r[2]), "=r"(r[3]) : "r"(a));
}
__device__ __forceinline__ void ldsm4t(uint32_t r[4], uint32_t a) {
    asm volatile("ldmatrix.sync.aligned.m8n8.x4.trans.shared.b16 {%0,%1,%2,%3}, [%4];"
                 : "=r"(r[0]), "=r"(r[1]), "=r"(r[2]), "=r"(r[3]) : "r"(a));
}
// fp16 mma, f32 accumulate. Non-volatile: pure register op.
__device__ __forceinline__ void mma16(float c[4], const uint32_t a[4], uint32_t b0, uint32_t b1) {
    asm("mma.sync.aligned.m16n8k16.row.col.f32.f16.f16.f32 "
        "{%0,%1,%2,%3}, {%4,%5,%6,%7}, {%8,%9}, {%0,%1,%2,%3};"
        : "+f"(c[0]), "+f"(c[1]), "+f"(c[2]), "+f"(c[3])
        : "r"(a[0]), "r"(a[1]), "r"(a[2]), "r"(a[3]), "r"(b0), "r"(b1));
}

__device__ __forceinline__ void cpa16(uint32_t d, const void* s) {
    asm volatile("cp.async.cg.shared.global [%0], [%1], 16;" :: "r"(d), "l"(s) : "memory");
}
#define CPA_COMMIT() asm volatile("cp.async.commit_group;" ::: "memory")
#define CPA_WAIT1()  asm volatile("cp.async.wait_group 1;" ::: "memory")
#define CPA_WAIT0()  asm volatile("cp.async.wait_group 0;" ::: "memory")

#define LOG2E_F 1.4426950408889634f

// ---------------------------------------------------------------------------
// conv_kernel: fp32 -> fp16 conversions.
// z=0: x -> g_xh (single term). z=1: pos_emb -> g_peh/g_pel (hi/lo).
// z=2..6: Wq,Wk,Wv,Wpos,Wout -> g_wh (single fp16).
// ---------------------------------------------------------------------------
__global__ __launch_bounds__(256) void conv_kernel(
    const float* __restrict__ x, const float* __restrict__ pe,
    const float* __restrict__ Wq, const float* __restrict__ Wk,
    const float* __restrict__ Wv, const float* __restrict__ Wpos,
    const float* __restrict__ Wout)
{
    int z = blockIdx.y;
    int stride = gridDim.x * 256;
    if (z == 0) {
        const float4* src = (const float4*)x;
        uint2* dh = (uint2*)g_xh_;
        for (int i = blockIdx.x * 256 + threadIdx.x; i < 1048576; i += stride) {
            float4 v = src[i];
            dh[i] = make_uint2(pack2h(v.x, v.y), pack2h(v.z, v.w));
        }
    } else if (z == 1) {
        const float4* src = (const float4*)pe;
        uint2* dh = (uint2*)g_peh_;
        uint2* dl = (uint2*)g_pel_;
        for (int i = blockIdx.x * 256 + threadIdx.x; i < 262144; i += stride) {
            float4 v = src[i];
            uint32_t h0 = pack2h(v.x, v.y);
            uint32_t h1 = pack2h(v.z, v.w);
            float2 f0 = __half22float2(*reinterpret_cast<__half2*>(&h0));
            float2 f1 = __half22float2(*reinterpret_cast<__half2*>(&h1));
            dh[i] = make_uint2(h0, h1);
            dl[i] = make_uint2(pack2h(v.x - f0.x, v.y - f0.y), pack2h(v.z - f1.x, v.w - f1.y));
        }
    } else {
        int widx = z - 2;
        const float* Wsel = (widx == 0) ? Wq : (widx == 1) ? Wk : (widx == 2) ? Wv
                          : (widx == 3) ? Wpos : Wout;
        const float4* src = (const float4*)Wsel;
        uint2* dh = (uint2*)g_wh_ + (size_t)widx * 65536;
        for (int i = blockIdx.x * 256 + threadIdx.x; i < 65536; i += stride) {
            float4 v = src[i];
            dh[i] = make_uint2(pack2h(v.x, v.y), pack2h(v.z, v.w));
        }
    }
}

// ---------------------------------------------------------------------------
// fp16 tensor-core projection GEMM: C[m,n] = (Ah[+Al])[m,:] . W[n,:]
// CTA: 128 rows x 64 cols, 8 warps (warp w: rows 16w..16w+15).
// K=512 in 8 chunks of 64, double-buffered cp.async.
// mode (blockIdx.z if arg<0): 0=Q, 1=K, 2=V, 3=P, 4=OUT — scatter epilogues.
// Only mode 3 (P) uses the 2-term A split; QKV/OUT are single-term.
// ---------------------------------------------------------------------------
#define KSTR2 144         // 64 f16 + 16B pad
#define SM_AH 0
#define SM_AL 18432
#define SM_B  36864
#define GSTAGE 46080
#define GEMM_SMEM (2*GSTAGE)   // 92160 -> 2 CTAs/SM

__device__ __forceinline__ void copy_gtile(
    uint32_t stb, const uint4* Ah, const uint4* Al, const uint4* Wb,
    int m0, int n0, int k08, int tid, bool two_term)
{
#pragma unroll
    for (int i = 0; i < 4; i++) {
        int idx = tid + i * 256;          // 1024: 128 rows x 8 uint4
        int r = idx >> 3, c = idx & 7;
        size_t so = (size_t)(m0 + r) * 64 + k08 + c;
        cpa16(stb + SM_AH + r * KSTR2 + c * 16, Ah + so);
        if (two_term) cpa16(stb + SM_AL + r * KSTR2 + c * 16, Al + so);
    }
#pragma unroll
    for (int i = 0; i < 2; i++) {
        int idx = tid + i * 256;          // 512: 64 rows x 8 uint4
        int r = idx >> 3, c = idx & 7;
        cpa16(stb + SM_B + r * KSTR2 + c * 16, Wb + (size_t)(n0 + r) * 64 + k08 + c);
    }
}

__global__ __launch_bounds__(256, 2) void proj_kernel(
    int mode_arg, float* __restrict__ out,
    const float* __restrict__ bq, const float* __restrict__ bk,
    const float* __restrict__ bv, const float* __restrict__ bout,
    const float* __restrict__ pbu, const float* __restrict__ pbv)
{
    extern __shared__ char sm[];
    uint32_t sb = cvta_s(sm);

    int tid = threadIdx.x;
    int w = tid >> 5, l = tid & 31;
    int mode = (mode_arg < 0) ? (int)blockIdx.z : mode_arg;
    int m0 = blockIdx.y << 7, n0 = blockIdx.x << 6;
    if (mode == 3 && m0 >= 2048) return;   // P has only 2048 rows

    bool two_term = (mode == 3);
    const uint4* Ah = (mode <= 2) ? g_xh_ : (mode == 3) ? g_peh_ : g_aoh_;
    const uint4* Al = g_pel_;              // only used when mode==3
    int widx = (mode <= 2) ? mode : ((mode == 3) ? 3 : 4);
    const uint4* Wb = g_wh_ + (size_t)widx * 32768;

    // prologue: chunks 0,1
    copy_gtile(sb, Ah, Al, Wb, m0, n0, 0, tid, two_term);  CPA_COMMIT();
    copy_gtile(sb + GSTAGE, Ah, Al, Wb, m0, n0, 8, tid, two_term);  CPA_COMMIT();

    float acc[4][2][4];
#pragma unroll
    for (int a = 0; a < 4; a++)
#pragma unroll
        for (int bq2 = 0; bq2 < 2; bq2++)
#pragma unroll
            for (int c = 0; c < 4; c++) acc[a][bq2][c] = 0.f;

    uint32_t rowa_rel = (16 * w + (l & 15)) * KSTR2 + (l >> 4) * 16;
    uint32_t kB_rel   = (l & 7) * KSTR2 + (l >> 3) * 16;

    for (int ch = 0; ch < 8; ch++) {
        if (ch < 6) { CPA_WAIT1(); } else { CPA_WAIT0(); }
        __syncthreads();

        uint32_t stb = sb + (ch & 1) * GSTAGE;

        uint32_t Afh[4][4], Afl[4][4];
#pragma unroll
        for (int ks = 0; ks < 4; ks++) {
            ldsm4(Afh[ks], stb + SM_AH + rowa_rel + ks * 32);
            if (two_term) ldsm4(Afl[ks], stb + SM_AL + rowa_rel + ks * 32);
        }
#pragma unroll
        for (int nb = 0; nb < 4; nb++) {
            uint32_t r0 = stb + SM_B + (16 * nb) * KSTR2 + kB_rel;
            uint32_t r1 = r0 + 8 * KSTR2;
#pragma unroll
            for (int j = 0; j < 2; j++) {
                uint32_t B0[4], B1[4];
                ldsm4(B0, r0 + j * 64);
                ldsm4(B1, r1 + j * 64);
                mma16(acc[nb][0], Afh[2*j],   B0[0], B0[1]);
                mma16(acc[nb][1], Afh[2*j],   B1[0], B1[1]);
                mma16(acc[nb][0], Afh[2*j+1], B0[2], B0[3]);
                mma16(acc[nb][1], Afh[2*j+1], B1[2], B1[3]);
                if (two_term) {
                    mma16(acc[nb][0], Afl[2*j],   B0[0], B0[1]);
                    mma16(acc[nb][1], Afl[2*j],   B1[0], B1[1]);
                    mma16(acc[nb][0], Afl[2*j+1], B0[2], B0[3]);
                    mma16(acc[nb][1], Afl[2*j+1], B1[2], B1[3]);
                }
            }
        }
        __syncthreads();
        if (ch + 2 < 8) {
            copy_gtile(sb + (ch & 1) * GSTAGE, Ah, Al, Wb, m0, n0, (ch + 2) * 8, tid, two_term);
            CPA_COMMIT();
        }
    }

    // ---- epilogue: scatter per mode ----
    int row0 = 16 * w + (l >> 2);
    int m = m0 + row0;          // rows m and m+8
    int colb = (l & 3) << 1;

#pragma unroll
    for (int nb = 0; nb < 4; nb++) {
#pragma unroll
        for (int half = 0; half < 2; half++) {
            int n = n0 + nb * 16 + half * 8 + colb;   // n, n+1
            float c0 = acc[nb][half][0], c1 = acc[nb][half][1];
            float c2 = acc[nb][half][2], c3 = acc[nb][half][3];
            int h = n >> 6, dd = n & 63;

            if (mode == 0) {
                float b0 = bq[n], b1 = bq[n + 1];
                float u0 = pbu[n], u1 = pbu[n + 1];
                float v0 = pbv[n], v1 = pbv[n + 1];
                int bb = m >> 11, t = m & (TT - 1);
                size_t base = ((size_t)(bb * HH + h) * TT + t) * 128 + dd;
                *(uint32_t*)(G_QH + base)      = pack2h((c0+b0+u0)*0.125f, (c1+b1+u1)*0.125f);
                *(uint32_t*)(G_QH + base + 64) = pack2h((c0+b0+v0)*0.125f, (c1+b1+v1)*0.125f);
                size_t base2 = base + (size_t)8 * 128;
                *(uint32_t*)(G_QH + base2)      = pack2h((c2+b0+u0)*0.125f, (c3+b1+u1)*0.125f);
                *(uint32_t*)(G_QH + base2 + 64) = pack2h((c2+b0+v0)*0.125f, (c3+b1+v1)*0.125f);
            } else if (mode == 1) {
                float b0 = bk[n], b1 = bk[n + 1];
                int bb = m >> 11, t = m & (TT - 1);
                size_t base = ((size_t)(bb * HH + h) * TT + t) * 128 + dd;
                *(uint32_t*)(G_KH + base) = pack2h(c0 + b0, c1 + b1);
                *(uint32_t*)(G_KH + base + (size_t)8 * 128) = pack2h(c2 + b0, c3 + b1);
            } else if (mode == 2) {
                float b0 = bv[n], b1 = bv[n + 1];
                int bb = m >> 11, t = m & (TT - 1);
                size_t base = ((size_t)(bb * HH + h) * TT + t) * 64 + dd;
                *(uint32_t*)(G_VH + base) = pack2h(c0 + b0, c1 + b1);
                *(uint32_t*)(G_VH + base + (size_t)8 * 64) = pack2h(c2 + b0, c3 + b1);
            } else if (mode == 3) {
                int t = m;   // 0..2047
                uint32_t p0 = pack2h(c0, c1);
                uint32_t p1 = pack2h(c2, c3);
#pragma unroll
                for (int bb = 0; bb < BB; bb++) {
                    size_t base = ((size_t)(bb * HH + h) * TT + t) * 128 + 64 + dd;
                    *(uint32_t*)(G_KH + base) = p0;
                    *(uint32_t*)(G_KH + base + (size_t)8 * 128) = p1;
                }
            } else {
                float b0 = bout[n], b1 = bout[n + 1];
                *(float2*)(out + (size_t)m * FF + n) = make_float2(c0 + b0, c1 + b1);
                *(float2*)(out + (size_t)(m + 8) * FF + n) = make_float2(c2 + b0, c3 + b1);
            }
        }
    }
}

// ---------------------------------------------------------------------------
// Single-fp16 mma.sync flash attention, ONLINE softmax, 2 CTAs/SM.
// 128-key tiles, double-buffered cp.async. Key-split z in [0,4). (R9-proven)
// ---------------------------------------------------------------------------
#define KSTR 272     // K/Q smem row stride bytes (128 f16 + 16B pad)
#define VSTR 144     // V smem row stride bytes (64 f16 + 16B pad)
#define SM_K 0
#define SM_V 34816
#define STAGE 53248
#define FLASH_SMEM (2*STAGE)   // 106496 -> 2 CTAs/SM

__device__ __forceinline__ void copy_tile_async(uint32_t stb, int bh, int s0, int tid) {
    const uint4* kh = g_kh_ + ((size_t)bh * TT + s0) * 16;
#pragma unroll
    for (int i = 0; i < 8; i++) {
        int idx = tid + i * 256;
        int r = idx >> 4, c = idx & 15;
        cpa16(stb + SM_K + r * KSTR + c * 16, kh + r * 16 + c);
    }
    const uint4* vh = g_vh_ + ((size_t)bh * TT + s0) * 8;
#pragma unroll
    for (int i = 0; i < 4; i++) {
        int idx = tid + i * 256;
        int r = idx >> 3, c = idx & 7;
        cpa16(stb + SM_V + r * VSTR + c * 16, vh + r * 8 + c);
    }
}

__global__ __launch_bounds__(256, 2) void flash_kernel()
{
    extern __shared__ char sm[];
    uint32_t sb = cvta_s(sm);

    int tid = threadIdx.x;
    int w = tid >> 5, l = tid & 31;
    int bh = blockIdx.y;
    int b = bh >> 3, h = bh & 7;
    int t0 = blockIdx.x << 7;
    int z  = blockIdx.z;
    int kbase = z << 9;

    {
        uint32_t qb = sb + STAGE;
        const uint4* qh = g_qh_ + ((size_t)bh * TT + t0) * 16;
#pragma unroll
        for (int i = 0; i < 8; i++) {
            int idx = tid + i * 256;
            int r = idx >> 4, c = idx & 15;
            cpa16(qb + r * KSTR + c * 16, qh + r * 16 + c);
        }
        CPA_COMMIT();
        copy_tile_async(sb, bh, kbase, tid);
        CPA_COMMIT();
    }
    CPA_WAIT1();
    __syncthreads();

    uint32_t Qf[8][4];
    {
        uint32_t rowa = sb + STAGE + (16 * w + (l & 15)) * KSTR + (l >> 4) * 16;
#pragma unroll
        for (int ks = 0; ks < 8; ks++) ldsm4(Qf[ks], rowa + ks * 32);
    }

    float O[8][4];
#pragma unroll
    for (int i = 0; i < 8; i++)
#pragma unroll
        for (int j = 0; j < 4; j++) O[i][j] = 0.f;
    float l_0 = 0.f, l_1 = 0.f;
    float m_0 = -1e30f, m_1 = -1e30f;

    uint32_t kB_rel = (l & 7) * KSTR + (l >> 3) * 16;
    uint32_t vB_rel = ((l & 7) + ((l >> 3) & 1) * 8) * VSTR + (l >> 4) * 16;

    for (int it = 0; it < 4; ++it) {
        __syncthreads();
        if (it < 3) {
            copy_tile_async(sb + ((it + 1) & 1) * STAGE, bh, kbase + ((it + 1) << 7), tid);
            CPA_COMMIT();
            CPA_WAIT1();
        } else {
            CPA_WAIT0();
        }
        __syncthreads();

        uint32_t stb = sb + (it & 1) * STAGE;
        uint32_t kB_lane = stb + kB_rel;
        uint32_t vB_lane = stb + vB_rel;

#pragma unroll
        for (int kb = 0; kb < 8; kb++) {
            float S0A[4] = {0.f,0.f,0.f,0.f}, S0B[4] = {0.f,0.f,0.f,0.f};
            float S1A[4] = {0.f,0.f,0.f,0.f}, S1B[4] = {0.f,0.f,0.f,0.f};
            uint32_t r0a = kB_lane + SM_K + (16 * kb) * KSTR;
            uint32_t r1a = r0a + 8 * KSTR;
#pragma unroll
            for (int j = 0; j < 4; j++) {
                uint32_t B0[4], B1[4];
                ldsm4(B0, r0a + j * 64);
                ldsm4(B1, r1a + j * 64);
                mma16(S0A, Qf[2*j],   B0[0], B0[1]);
                mma16(S1A, Qf[2*j],   B1[0], B1[1]);
                mma16(S0B, Qf[2*j+1], B0[2], B0[3]);
                mma16(S1B, Qf[2*j+1], B1[2], B1[3]);
            }

            uint32_t va = vB_lane + SM_V + (16 * kb) * VSTR;
            uint32_t V0[4], V1[4], V2[4], V3[4];
            ldsm4t(V0, va);
            ldsm4t(V1, va + 32);
            ldsm4t(V2, va + 64);
            ldsm4t(V3, va + 96);

            float s00 = S0A[0]+S0B[0], s01 = S0A[1]+S0B[1];
            float s02 = S0A[2]+S0B[2], s03 = S0A[3]+S0B[3];
            float s10 = S1A[0]+S1B[0], s11 = S1A[1]+S1B[1];
            float s12 = S1A[2]+S1B[2], s13 = S1A[3]+S1B[3];

            float mx0f = fmaxf(fmaxf(s00, s01), fmaxf(s10, s11));
            float mx1f = fmaxf(fmaxf(s02, s03), fmaxf(s12, s13));
            uint32_t pk = pack2h(mx0f, mx1f);
            {
                uint32_t o1 = __shfl_xor_sync(0xffffffffu, pk, 1);
                __half2 a = *reinterpret_cast<__half2*>(&pk);
                __half2 c = __hmax2(a, *reinterpret_cast<__half2*>(&o1));
                pk = *reinterpret_cast<uint32_t*>(&c);
                uint32_t o2 = __shfl_xor_sync(0xffffffffu, pk, 2);
                __half2 d = __hmax2(*reinterpret_cast<__half2*>(&pk),
                                    *reinterpret_cast<__half2*>(&o2));
                pk = *reinterpret_cast<uint32_t*>(&d);
            }
            float2 mxf = __half22float2(*reinterpret_cast<__half2*>(&pk));
            float mn0 = fmaxf(m_0, mxf.x), mn1 = fmaxf(m_1, mxf.y);
            bool nochg = __all_sync(0xffffffffu, (mn0 == m_0) && (mn1 == m_1));

            float p00 = ex2f((s00 - mn0) * LOG2E_F);
            float p01 = ex2f((s01 - mn0) * LOG2E_F);
            float p10 = ex2f((s10 - mn0) * LOG2E_F);
            float p11 = ex2f((s11 - mn0) * LOG2E_F);
            float p02 = ex2f((s02 - mn1) * LOG2E_F);
            float p03 = ex2f((s03 - mn1) * LOG2E_F);
            float p12 = ex2f((s12 - mn1) * LOG2E_F);
            float p13 = ex2f((s13 - mn1) * LOG2E_F);
            float sum0 = (p00 + p01) + (p10 + p11);
            float sum1 = (p02 + p03) + (p12 + p13);

            if (nochg) {
                l_0 += sum0;
                l_1 += sum1;
            } else {
                float c0 = ex2f((m_0 - mn0) * LOG2E_F);
                float c1 = ex2f((m_1 - mn1) * LOG2E_F);
                l_0 = l_0 * c0 + sum0;
                l_1 = l_1 * c1 + sum1;
                m_0 = mn0; m_1 = mn1;
#pragma unroll
                for (int nd = 0; nd < 8; nd++) {
                    O[nd][0] *= c0; O[nd][1] *= c0;
                    O[nd][2] *= c1; O[nd][3] *= c1;
                }
            }

            uint32_t P[4];
            P[0] = pack2h(p00, p01);
            P[1] = pack2h(p02, p03);
            P[2] = pack2h(p10, p11);
            P[3] = pack2h(p12, p13);

            mma16(O[0], P, V0[0], V0[1]);
            mma16(O[1], P, V0[2], V0[3]);
            mma16(O[2], P, V1[0], V1[1]);
            mma16(O[3], P, V1[2], V1[3]);
            mma16(O[4], P, V2[0], V2[1]);
            mma16(O[5], P, V2[2], V2[3]);
            mma16(O[6], P, V3[0], V3[1]);
            mma16(O[7], P, V3[2], V3[3]);
        }
    }

    l_0 += __shfl_xor_sync(0xffffffffu, l_0, 1);
    l_0 += __shfl_xor_sync(0xffffffffu, l_0, 2);
    l_1 += __shfl_xor_sync(0xffffffffu, l_1, 1);
    l_1 += __shfl_xor_sync(0xffffffffu, l_1, 2);

    float* po = g_po + (size_t)z * MM * FF;
    float* ls = g_ls + z * 32 * TT;
    float* lm = g_lm + z * 32 * TT;

    int row0 = t0 + 16 * w + (l >> 2);
    if ((l & 3) == 0) {
        ls[bh * TT + row0] = l_0;      lm[bh * TT + row0] = m_0;
        ls[bh * TT + row0 + 8] = l_1;  lm[bh * TT + row0 + 8] = m_1;
    }
    float* d0 = po + ((size_t)(b * TT + row0)) * FF + (h << 6) + ((l & 3) << 1);
    float* d1 = d0 + (size_t)8 * FF;
#pragma unroll
    for (int nd = 0; nd < 8; nd++) {
        *(float2*)(d0 + nd * 8) = make_float2(O[nd][0], O[nd][1]);
        *(float2*)(d1 + nd * 8) = make_float2(O[nd][2], O[nd][3]);
    }
}

// ---------------------------------------------------------------------------
// combine NZ partials with (m,l) merge -> single fp16 ao (feeds OUT gemm)
// ---------------------------------------------------------------------------
__global__ __launch_bounds__(256) void combine_kernel()
{
    int idx = blockIdx.x * 256 + threadIdx.x;   // float4 units over MM*FF
    int m = idx >> 7;
    int c = (idx & 127) << 2;
    int h = c >> 6;
    int b = m >> 11, t = m & (TT - 1);
    int r = (b * HH + h) * TT + t;

    float mz[NZ];
    float M = -1e30f;
#pragma unroll
    for (int zz = 0; zz < NZ; zz++) { mz[zz] = g_lm[zz * 32 * TT + r]; M = fmaxf(M, mz[zz]); }
    float L = 0.f;
    float wz[NZ];
#pragma unroll
    for (int zz = 0; zz < NZ; zz++) {
        wz[zz] = ex2f((mz[zz] - M) * LOG2E_F);
        L += g_ls[zz * 32 * TT + r] * wz[zz];
    }
    float inv = 1.f / L;

    float4 acc = make_float4(0.f, 0.f, 0.f, 0.f);
#pragma unroll
    for (int zz = 0; zz < NZ; zz++) {
        float4 o = *(const float4*)(g_po + (size_t)zz * MM * FF + (size_t)idx * 4);
        acc.x += o.x * wz[zz]; acc.y += o.y * wz[zz];
        acc.z += o.z * wz[zz]; acc.w += o.w * wz[zz];
    }
    ((uint2*)g_aoh_)[idx] = make_uint2(pack2h(acc.x * inv, acc.y * inv),
                                       pack2h(acc.z * inv, acc.w * inv));
}

// ---------------------------------------------------------------------------
extern "C" void kernel_launch(void* const* d_in, const int* in_sizes, int n_in,
                              void* d_out, int out_size)
{
    const float* x    = (const float*)d_in[0];
    const float* pe   = (const float*)d_in[1];
    const float* Wq   = (const float*)d_in[2];
    const float* bq   = (const float*)d_in[3];
    const float* Wk   = (const float*)d_in[4];
    const float* bk   = (const float*)d_in[5];
    const float* Wv   = (const float*)d_in[6];
    const float* bv   = (const float*)d_in[7];
    const float* Wpos = (const float*)d_in[8];
    const float* Wout = (const float*)d_in[9];
    const float* bout = (const float*)d_in[10];
    const float* pbu  = (const float*)d_in[11];
    const float* pbv  = (const float*)d_in[12];
    float* out = (float*)d_out;

    cudaFuncSetAttribute(flash_kernel, cudaFuncAttributeMaxDynamicSharedMemorySize, FLASH_SMEM);
    cudaFuncSetAttribute(proj_kernel, cudaFuncAttributeMaxDynamicSharedMemorySize, GEMM_SMEM);

    dim3 blk(256);
    // #0: fp32 -> fp16 conversions (x, pe hi/lo, 5 weights)
    conv_kernel<<<dim3(512, 7), blk>>>(x, pe, Wq, Wk, Wv, Wpos, Wout);
    // #1: fused QKV + P projections (tensor cores; z=3 = P, masked to y<16)
    proj_kernel<<<dim3(8, 64, 4), blk, GEMM_SMEM>>>(-1, nullptr, bq, bk, bv, bout, pbu, pbv);
    // #2: flash attention
    flash_kernel<<<dim3(TT / 128, BB * HH, NZ), blk, FLASH_SMEM>>>();
    // #3: combine split-K partials -> fp16 ao
    combine_kernel<<<dim3((MM * FF) / 1024), blk>>>();
    // #4: output projection (tensor cores, single-term A) -> d_out
    proj_kernel<<<dim3(8, 64, 1), blk, GEMM_SMEM>>>(4, out, bq, bk, bv, bout, pbu, pbv);
}